// round 1
// baseline (speedup 1.0000x reference)
#include <cuda_runtime.h>
#include <math.h>

#define B_  4
#define S_  2048
#define D_  1024
#define H_  16
#define DK_ 64
#define M_  (B_*S_)   // 8192 rows

// Scratch: device globals (no cudaMalloc allowed)
__device__ float g_q[M_*D_];
__device__ float g_k[M_*D_];
__device__ float g_v[M_*D_];
__device__ float g_ctx[M_*D_];

// ---------------------------------------------------------------------------
// SGEMM: C[M,N] = A[M,K] @ W[N,K]^T   (torch Linear convention, no bias)
// M=8192, N=K=1024. 128x128 tile, BK=8, 256 threads, 8x8 per thread.
// ---------------------------------------------------------------------------
__global__ __launch_bounds__(256, 2)
void sgemm_nt(const float* __restrict__ A, const float* __restrict__ W,
              float* __restrict__ C) {
    const int K = D_;
    const int N = D_;
    __shared__ float As[8][128];
    __shared__ float Ws[8][128];

    const int tid = threadIdx.x;
    const int bm = blockIdx.y * 128;
    const int bn = blockIdx.x * 128;
    const int tx = tid & 15;     // 0..15
    const int ty = tid >> 4;     // 0..15
    const int lr = tid >> 1;     // 0..127 (tile row for loads)
    const int lc = (tid & 1) * 4;

    const float* Ag = A + (size_t)(bm + lr) * K + lc;
    const float* Wg = W + (size_t)(bn + lr) * K + lc;

    float acc[8][8];
#pragma unroll
    for (int i = 0; i < 8; i++)
#pragma unroll
        for (int j = 0; j < 8; j++) acc[i][j] = 0.f;

    for (int k0 = 0; k0 < K; k0 += 8) {
        float4 a4 = *(const float4*)(Ag + k0);
        float4 w4 = *(const float4*)(Wg + k0);
        __syncthreads();
        As[lc+0][lr] = a4.x; As[lc+1][lr] = a4.y;
        As[lc+2][lr] = a4.z; As[lc+3][lr] = a4.w;
        Ws[lc+0][lr] = w4.x; Ws[lc+1][lr] = w4.y;
        Ws[lc+2][lr] = w4.z; Ws[lc+3][lr] = w4.w;
        __syncthreads();
#pragma unroll
        for (int kk = 0; kk < 8; kk++) {
            float ar[8], wr[8];
            *(float4*)&ar[0] = *(const float4*)&As[kk][ty*8];
            *(float4*)&ar[4] = *(const float4*)&As[kk][ty*8+4];
            *(float4*)&wr[0] = *(const float4*)&Ws[kk][tx*8];
            *(float4*)&wr[4] = *(const float4*)&Ws[kk][tx*8+4];
#pragma unroll
            for (int i = 0; i < 8; i++)
#pragma unroll
                for (int j = 0; j < 8; j++)
                    acc[i][j] += ar[i] * wr[j];
        }
    }

#pragma unroll
    for (int i = 0; i < 8; i++) {
        float* Cg = C + (size_t)(bm + ty*8 + i) * N + bn + tx*8;
        *(float4*)(Cg)   = make_float4(acc[i][0], acc[i][1], acc[i][2], acc[i][3]);
        *(float4*)(Cg+4) = make_float4(acc[i][4], acc[i][5], acc[i][6], acc[i][7]);
    }
}

// ---------------------------------------------------------------------------
// Flash attention forward, fp32, causal. One block = one 64-row q tile of one
// (b,h). 256 threads as 16x16; each thread owns a 4x4 score/out subtile.
// Q,K stored dk-major in smem (stride 68 to dodge bank conflicts), V natural.
// ---------------------------------------------------------------------------
#define QSTR 68
#define SMEM_FLASH ((3*64*QSTR + 64*64) * 4)

__global__ __launch_bounds__(256)
void flash_fwd() {
    extern __shared__ float sm[];
    float* Qt = sm;                 // [64][68], Qt[dk][row]
    float* Kt = sm + 64*QSTR;       // [64][68], Kt[dk][col]
    float* Ps = sm + 2*64*QSTR;     // [64][68], Ps[row][col]
    float* Vs = sm + 3*64*QSTR;     // [64][64], Vs[kv][dk]

    const int qi = gridDim.x - 1 - blockIdx.x;  // heavy tiles first
    const int h  = blockIdx.y;
    const int b  = blockIdx.z;
    const int tid = threadIdx.x;
    const int tx = tid & 15;
    const int ty = tid >> 4;

    // Load Q tile transposed
    const float* Qg = g_q + ((size_t)(b*S_ + qi*64)) * D_ + h*DK_;
#pragma unroll
    for (int it = 0; it < 4; it++) {
        int idx = tid + it*256;
        int r = idx >> 4;
        int c = (idx & 15) * 4;
        float4 qv = *(const float4*)(Qg + (size_t)r*D_ + c);
        Qt[(c+0)*QSTR + r] = qv.x;
        Qt[(c+1)*QSTR + r] = qv.y;
        Qt[(c+2)*QSTR + r] = qv.z;
        Qt[(c+3)*QSTR + r] = qv.w;
    }

    float m[4], l[4], o[4][4];
#pragma unroll
    for (int i = 0; i < 4; i++) {
        m[i] = -1e30f; l[i] = 0.f;
#pragma unroll
        for (int j = 0; j < 4; j++) o[i][j] = 0.f;
    }

    const float scale = 0.125f;  // 1/sqrt(64)

    for (int kt = 0; kt <= qi; kt++) {
        const float* Kg = g_k + ((size_t)(b*S_ + kt*64)) * D_ + h*DK_;
        const float* Vg = g_v + ((size_t)(b*S_ + kt*64)) * D_ + h*DK_;
        __syncthreads();   // previous PV gemm done before overwriting K/V/P
#pragma unroll
        for (int it = 0; it < 4; it++) {
            int idx = tid + it*256;
            int r = idx >> 4;
            int c = (idx & 15) * 4;
            float4 kv = *(const float4*)(Kg + (size_t)r*D_ + c);
            Kt[(c+0)*QSTR + r] = kv.x;
            Kt[(c+1)*QSTR + r] = kv.y;
            Kt[(c+2)*QSTR + r] = kv.z;
            Kt[(c+3)*QSTR + r] = kv.w;
            *(float4*)&Vs[r*64 + c] = *(const float4*)(Vg + (size_t)r*D_ + c);
        }
        __syncthreads();

        // ---- S = Q K^T (64x64 tile), each thread 4x4 ----
        float s[4][4];
#pragma unroll
        for (int i = 0; i < 4; i++)
#pragma unroll
            for (int j = 0; j < 4; j++) s[i][j] = 0.f;

#pragma unroll 4
        for (int kk = 0; kk < 64; kk++) {
            float4 q4 = *(const float4*)&Qt[kk*QSTR + ty*4];
            float4 k4 = *(const float4*)&Kt[kk*QSTR + tx*4];
            float qa[4] = {q4.x, q4.y, q4.z, q4.w};
            float ka[4] = {k4.x, k4.y, k4.z, k4.w};
#pragma unroll
            for (int i = 0; i < 4; i++)
#pragma unroll
                for (int j = 0; j < 4; j++)
                    s[i][j] += qa[i] * ka[j];
        }

        const bool diag = (kt == qi);
#pragma unroll
        for (int i = 0; i < 4; i++) {
            int qg = qi*64 + ty*4 + i;
#pragma unroll
            for (int j = 0; j < 4; j++) {
                int kg = kt*64 + tx*4 + j;
                s[i][j] = (diag && kg > qg) ? -1e30f : s[i][j] * scale;
            }
        }

        // ---- online softmax (row stats across 16 lanes) ----
#pragma unroll
        for (int i = 0; i < 4; i++) {
            float rm = fmaxf(fmaxf(s[i][0], s[i][1]), fmaxf(s[i][2], s[i][3]));
            rm = fmaxf(rm, __shfl_xor_sync(0xffffffffu, rm, 8));
            rm = fmaxf(rm, __shfl_xor_sync(0xffffffffu, rm, 4));
            rm = fmaxf(rm, __shfl_xor_sync(0xffffffffu, rm, 2));
            rm = fmaxf(rm, __shfl_xor_sync(0xffffffffu, rm, 1));
            float mn   = fmaxf(m[i], rm);
            float corr = __expf(m[i] - mn);
            float p0 = __expf(s[i][0] - mn);
            float p1 = __expf(s[i][1] - mn);
            float p2 = __expf(s[i][2] - mn);
            float p3 = __expf(s[i][3] - mn);
            float rs = (p0 + p1) + (p2 + p3);
            rs += __shfl_xor_sync(0xffffffffu, rs, 8);
            rs += __shfl_xor_sync(0xffffffffu, rs, 4);
            rs += __shfl_xor_sync(0xffffffffu, rs, 2);
            rs += __shfl_xor_sync(0xffffffffu, rs, 1);
            l[i] = l[i] * corr + rs;
#pragma unroll
            for (int j = 0; j < 4; j++) o[i][j] *= corr;
            m[i] = mn;
            *(float4*)&Ps[(ty*4+i)*QSTR + tx*4] = make_float4(p0, p1, p2, p3);
        }
        __syncthreads();

        // ---- O += P V (64x64 x 64x64) ----
#pragma unroll 2
        for (int kk = 0; kk < 64; kk++) {
            float pr[4];
#pragma unroll
            for (int i = 0; i < 4; i++) pr[i] = Ps[(ty*4+i)*QSTR + kk];
            float4 v4 = *(const float4*)&Vs[kk*64 + tx*4];
            float va[4] = {v4.x, v4.y, v4.z, v4.w};
#pragma unroll
            for (int i = 0; i < 4; i++)
#pragma unroll
                for (int j = 0; j < 4; j++)
                    o[i][j] += pr[i] * va[j];
        }
    }

    // ---- epilogue: O / l -> ctx [B,S,D] ----
    float* Og = g_ctx + ((size_t)(b*S_ + qi*64 + ty*4)) * D_ + h*DK_ + tx*4;
#pragma unroll
    for (int i = 0; i < 4; i++) {
        float inv = 1.f / l[i];
        *(float4*)(Og + (size_t)i*D_) =
            make_float4(o[i][0]*inv, o[i][1]*inv, o[i][2]*inv, o[i][3]*inv);
    }
}

// ---------------------------------------------------------------------------
extern "C" void kernel_launch(void* const* d_in, const int* in_sizes, int n_in,
                              void* d_out, int out_size) {
    const float* q   = (const float*)d_in[0];
    const float* k   = (const float*)d_in[1];
    const float* v   = (const float*)d_in[2];
    // d_in[3] = mask (int32 causal mask) — causality is baked into flash_fwd
    const float* w_q = (const float*)d_in[4];
    const float* w_k = (const float*)d_in[5];
    const float* w_v = (const float*)d_in[6];
    const float* w_o = (const float*)d_in[7];
    float* out = (float*)d_out;

    float *gq, *gk, *gv, *gctx;
    cudaGetSymbolAddress((void**)&gq,   g_q);
    cudaGetSymbolAddress((void**)&gk,   g_k);
    cudaGetSymbolAddress((void**)&gv,   g_v);
    cudaGetSymbolAddress((void**)&gctx, g_ctx);

    cudaFuncSetAttribute(flash_fwd, cudaFuncAttributeMaxDynamicSharedMemorySize,
                         SMEM_FLASH);

    dim3 gGemm(D_/128, M_/128);   // (8, 64)
    sgemm_nt<<<gGemm, 256>>>(q, w_q, gq);
    sgemm_nt<<<gGemm, 256>>>(k, w_k, gk);
    sgemm_nt<<<gGemm, 256>>>(v, w_v, gv);

    dim3 gAtt(S_/64, H_, B_);     // (32, 16, 4)
    flash_fwd<<<gAtt, 256, SMEM_FLASH>>>();

    sgemm_nt<<<gGemm, 256>>>(gctx, w_o, out);
}

// round 4
// speedup vs baseline: 1.6339x; 1.6339x over previous
#include <cuda_runtime.h>
#include <cuda_bf16.h>
#include <cstdint>

#define B_  4
#define S_  2048
#define D_  1024
#define H_  16
#define DK_ 64
#define M_  (B_*S_)   // 8192 rows
#define MW_ (D_*D_)   // 1M weight elems

// ---------------- scratch (no cudaMalloc allowed) ----------------
__device__ float g_q[M_*D_];
__device__ float g_k[M_*D_];
__device__ float g_v[M_*D_];
__device__ float g_ctx[M_*D_];
// bf16 pool: 8 input-sized (qh,ql,kh,kl,vh,vl,ch,cl) + 8 weight-sized
__device__ __nv_bfloat16 g_bf[(size_t)8*M_*D_ + (size_t)8*MW_];

// ---------------- helpers ----------------
__device__ __forceinline__ uint32_t smem_u32(const void* p) {
    uint32_t a;
    asm("{ .reg .u64 t; cvta.to.shared.u64 t, %1; cvt.u32.u64 %0, t; }"
        : "=r"(a) : "l"(p));
    return a;
}
#define CP16(dst, src) \
    asm volatile("cp.async.cg.shared.global [%0], [%1], 16;" \
                 :: "r"(dst), "l"(src))
#define CP_COMMIT() asm volatile("cp.async.commit_group;" ::: "memory")
#define CP_WAIT(n)  asm volatile("cp.async.wait_group %0;" :: "n"(n) : "memory")

__device__ __forceinline__ void ldm_x4(uint32_t& d0, uint32_t& d1,
                                       uint32_t& d2, uint32_t& d3, uint32_t a) {
    asm volatile("ldmatrix.sync.aligned.m8n8.x4.shared.b16 {%0,%1,%2,%3}, [%4];"
                 : "=r"(d0), "=r"(d1), "=r"(d2), "=r"(d3) : "r"(a));
}
__device__ __forceinline__ void mma_bf16(float& c0, float& c1, float& c2, float& c3,
                                         uint32_t a0, uint32_t a1, uint32_t a2, uint32_t a3,
                                         uint32_t b0, uint32_t b1) {
    asm volatile(
        "mma.sync.aligned.m16n8k16.row.col.f32.bf16.bf16.f32 "
        "{%0,%1,%2,%3}, {%4,%5,%6,%7}, {%8,%9}, {%0,%1,%2,%3};"
        : "+f"(c0), "+f"(c1), "+f"(c2), "+f"(c3)
        : "r"(a0), "r"(a1), "r"(a2), "r"(a3), "r"(b0), "r"(b1));
}

// ---------------------------------------------------------------------------
// fp32 -> (bf16 hi, bf16 lo) split
// ---------------------------------------------------------------------------
__global__ __launch_bounds__(256)
void split_bf16(const float4* __restrict__ x, __nv_bfloat16* __restrict__ hi,
                __nv_bfloat16* __restrict__ lo, int n4) {
    int i = blockIdx.x * blockDim.x + threadIdx.x;
    if (i >= n4) return;
    float4 v = x[i];
    float f[4] = {v.x, v.y, v.z, v.w};
    __nv_bfloat16 h[4], l[4];
#pragma unroll
    for (int j = 0; j < 4; j++) {
        h[j] = __float2bfloat16(f[j]);
        l[j] = __float2bfloat16(f[j] - __bfloat162float(h[j]));
    }
    *(uint2*)(hi + (size_t)i * 4) = *(uint2*)h;
    *(uint2*)(lo + (size_t)i * 4) = *(uint2*)l;
}

// ---------------------------------------------------------------------------
// HMMA split-bf16 GEMM: C[M,N] = A[M,K] @ W[N,K]^T (fp32-accurate, 3 passes)
// CTA tile 128x128, BK=32, 8 warps (2x4), warp tile 64x32, cp.async 2-stage.
// Smem rows padded to 40 bf16 (80B) -> conflict-free ldmatrix.
// ---------------------------------------------------------------------------
#define GBK   32
#define NCHK  (D_/GBK)            // 32
#define LDS_  40                  // padded row stride (bf16 elems)
#define TILEB (128*LDS_*2)        // 10240 B
#define STAGEB (4*TILEB)          // Ah,Al,Wh,Wl = 40960 B
#define SMEMG (2*STAGEB)          // 81920 B

__global__ __launch_bounds__(256, 2)
void gemm_hmma_split(const __nv_bfloat16* __restrict__ Ah,
                     const __nv_bfloat16* __restrict__ Al,
                     const __nv_bfloat16* __restrict__ Wh,
                     const __nv_bfloat16* __restrict__ Wl,
                     float* __restrict__ C) {
    extern __shared__ char smg[];
    const uint32_t sb = smem_u32(smg);
    const int tid  = threadIdx.x;
    const int lane = tid & 31;
    const int wid  = tid >> 5;
    const int wm   = wid & 1;         // 2 warps in M
    const int wn   = wid >> 1;        // 4 warps in N
    const int bm = blockIdx.y * 128;
    const int bn = blockIdx.x * 128;

    // global load assignment: 2 iters x (row = idx>>2, seg = idx&3), 16B each
    const int lrow = (tid >> 2);          // 0..63 (+64 on iter 1)
    const int lseg = (tid & 3) * 8;       // bf16 elem offset within 32

    const __nv_bfloat16* gp[4] = {
        Ah + (size_t)(bm + lrow) * D_ + lseg,
        Al + (size_t)(bm + lrow) * D_ + lseg,
        Wh + (size_t)(bn + lrow) * D_ + lseg,
        Wl + (size_t)(bn + lrow) * D_ + lseg };
    const uint32_t sofs = (uint32_t)(lrow * LDS_ + lseg) * 2;

    float acc[4][4][4];
#pragma unroll
    for (int f = 0; f < 4; f++)
#pragma unroll
        for (int g = 0; g < 4; g++)
#pragma unroll
            for (int e = 0; e < 4; e++) acc[f][g][e] = 0.f;

    // ldmatrix per-lane addresses (element offsets within a tile)
    const int arow = wm * 64 + (lane & 15);
    const int acol = (lane >> 4) * 8;
    const int brow = wn * 32 + (lane & 7) + ((lane >> 4) << 3);
    const int bcol = ((lane >> 3) & 1) * 8;

#define PREFETCH(c, buf) do {                                                 \
    uint32_t dst = sb + (buf) * STAGEB;                                       \
    const size_t gofs = (size_t)(c) * GBK;                                    \
    _Pragma("unroll")                                                         \
    for (int t = 0; t < 2; t++) {                                             \
        uint32_t so = dst + sofs + t * 64 * LDS_ * 2;                         \
        size_t go = gofs + (size_t)t * 64 * D_;                               \
        CP16(so + 0 * TILEB, gp[0] + go);                                     \
        CP16(so + 1 * TILEB, gp[1] + go);                                     \
        CP16(so + 2 * TILEB, gp[2] + go);                                     \
        CP16(so + 3 * TILEB, gp[3] + go);                                     \
    }                                                                         \
    CP_COMMIT();                                                              \
} while (0)

    PREFETCH(0, 0);

    for (int c = 0; c < NCHK; ++c) {
        const int buf = c & 1;
        if (c + 1 < NCHK) { PREFETCH(c + 1, buf ^ 1); CP_WAIT(1); }
        else              { CP_WAIT(0); }
        __syncthreads();

        const uint32_t st = sb + buf * STAGEB;
#pragma unroll
        for (int s16 = 0; s16 < 2; ++s16) {
            const uint32_t aoff = (uint32_t)(arow * LDS_ + s16 * 16 + acol) * 2;
            const uint32_t boff = (uint32_t)(brow * LDS_ + s16 * 16 + bcol) * 2;

            uint32_t ra[4][4], rbh[2][4], rbl[2][4];
#pragma unroll
            for (int f = 0; f < 4; f++)
                ldm_x4(ra[f][0], ra[f][1], ra[f][2], ra[f][3],
                       st + 0 * TILEB + aoff + (uint32_t)(f * 16 * LDS_ * 2));
#pragma unroll
            for (int p = 0; p < 2; p++) {
                ldm_x4(rbh[p][0], rbh[p][1], rbh[p][2], rbh[p][3],
                       st + 2 * TILEB + boff + (uint32_t)(p * 16 * LDS_ * 2));
                ldm_x4(rbl[p][0], rbl[p][1], rbl[p][2], rbl[p][3],
                       st + 3 * TILEB + boff + (uint32_t)(p * 16 * LDS_ * 2));
            }
            // pass 1: Ah*Wh, pass 2: Ah*Wl
#pragma unroll
            for (int f = 0; f < 4; f++)
#pragma unroll
                for (int p = 0; p < 2; p++) {
                    mma_bf16(acc[f][2*p][0],   acc[f][2*p][1],   acc[f][2*p][2],   acc[f][2*p][3],
                             ra[f][0], ra[f][1], ra[f][2], ra[f][3], rbh[p][0], rbh[p][1]);
                    mma_bf16(acc[f][2*p+1][0], acc[f][2*p+1][1], acc[f][2*p+1][2], acc[f][2*p+1][3],
                             ra[f][0], ra[f][1], ra[f][2], ra[f][3], rbh[p][2], rbh[p][3]);
                    mma_bf16(acc[f][2*p][0],   acc[f][2*p][1],   acc[f][2*p][2],   acc[f][2*p][3],
                             ra[f][0], ra[f][1], ra[f][2], ra[f][3], rbl[p][0], rbl[p][1]);
                    mma_bf16(acc[f][2*p+1][0], acc[f][2*p+1][1], acc[f][2*p+1][2], acc[f][2*p+1][3],
                             ra[f][0], ra[f][1], ra[f][2], ra[f][3], rbl[p][2], rbl[p][3]);
                }
            // pass 3: Al*Wh  (reuse ra regs)
#pragma unroll
            for (int f = 0; f < 4; f++)
                ldm_x4(ra[f][0], ra[f][1], ra[f][2], ra[f][3],
                       st + 1 * TILEB + aoff + (uint32_t)(f * 16 * LDS_ * 2));
#pragma unroll
            for (int f = 0; f < 4; f++)
#pragma unroll
                for (int p = 0; p < 2; p++) {
                    mma_bf16(acc[f][2*p][0],   acc[f][2*p][1],   acc[f][2*p][2],   acc[f][2*p][3],
                             ra[f][0], ra[f][1], ra[f][2], ra[f][3], rbh[p][0], rbh[p][1]);
                    mma_bf16(acc[f][2*p+1][0], acc[f][2*p+1][1], acc[f][2*p+1][2], acc[f][2*p+1][3],
                             ra[f][0], ra[f][1], ra[f][2], ra[f][3], rbh[p][2], rbh[p][3]);
                }
        }
        __syncthreads();
    }
#undef PREFETCH

    // epilogue: write C
    const int crow = bm + wm * 64 + (lane >> 2);
    const int ccol = bn + wn * 32 + 2 * (lane & 3);
#pragma unroll
    for (int f = 0; f < 4; f++)
#pragma unroll
        for (int g = 0; g < 4; g++) {
            float* p0 = C + (size_t)(crow + f * 16)     * D_ + ccol + g * 8;
            float* p1 = C + (size_t)(crow + f * 16 + 8) * D_ + ccol + g * 8;
            *(float2*)p0 = make_float2(acc[f][g][0], acc[f][g][1]);
            *(float2*)p1 = make_float2(acc[f][g][2], acc[f][g][3]);
        }
}

// ---------------------------------------------------------------------------
// Flash attention forward, fp32, causal (unchanged — R1-verified).
// ---------------------------------------------------------------------------
#define QSTR 68
#define SMEM_FLASH ((3*64*QSTR + 64*64) * 4)

__global__ __launch_bounds__(256)
void flash_fwd() {
    extern __shared__ float sm[];
    float* Qt = sm;
    float* Kt = sm + 64*QSTR;
    float* Ps = sm + 2*64*QSTR;
    float* Vs = sm + 3*64*QSTR;

    const int qi = gridDim.x - 1 - blockIdx.x;
    const int h  = blockIdx.y;
    const int b  = blockIdx.z;
    const int tid = threadIdx.x;
    const int tx = tid & 15;
    const int ty = tid >> 4;

    const float* Qg = g_q + ((size_t)(b*S_ + qi*64)) * D_ + h*DK_;
#pragma unroll
    for (int it = 0; it < 4; it++) {
        int idx = tid + it*256;
        int r = idx >> 4;
        int c = (idx & 15) * 4;
        float4 qv = *(const float4*)(Qg + (size_t)r*D_ + c);
        Qt[(c+0)*QSTR + r] = qv.x;
        Qt[(c+1)*QSTR + r] = qv.y;
        Qt[(c+2)*QSTR + r] = qv.z;
        Qt[(c+3)*QSTR + r] = qv.w;
    }

    float m[4], l[4], o[4][4];
#pragma unroll
    for (int i = 0; i < 4; i++) {
        m[i] = -1e30f; l[i] = 0.f;
#pragma unroll
        for (int j = 0; j < 4; j++) o[i][j] = 0.f;
    }

    const float scale = 0.125f;

    for (int kt = 0; kt <= qi; kt++) {
        const float* Kg = g_k + ((size_t)(b*S_ + kt*64)) * D_ + h*DK_;
        const float* Vg = g_v + ((size_t)(b*S_ + kt*64)) * D_ + h*DK_;
        __syncthreads();
#pragma unroll
        for (int it = 0; it < 4; it++) {
            int idx = tid + it*256;
            int r = idx >> 4;
            int c = (idx & 15) * 4;
            float4 kv = *(const float4*)(Kg + (size_t)r*D_ + c);
            Kt[(c+0)*QSTR + r] = kv.x;
            Kt[(c+1)*QSTR + r] = kv.y;
            Kt[(c+2)*QSTR + r] = kv.z;
            Kt[(c+3)*QSTR + r] = kv.w;
            *(float4*)&Vs[r*64 + c] = *(const float4*)(Vg + (size_t)r*D_ + c);
        }
        __syncthreads();

        float s[4][4];
#pragma unroll
        for (int i = 0; i < 4; i++)
#pragma unroll
            for (int j = 0; j < 4; j++) s[i][j] = 0.f;

#pragma unroll 4
        for (int kk = 0; kk < 64; kk++) {
            float4 q4 = *(const float4*)&Qt[kk*QSTR + ty*4];
            float4 k4 = *(const float4*)&Kt[kk*QSTR + tx*4];
            float qa[4] = {q4.x, q4.y, q4.z, q4.w};
            float ka[4] = {k4.x, k4.y, k4.z, k4.w};
#pragma unroll
            for (int i = 0; i < 4; i++)
#pragma unroll
                for (int j = 0; j < 4; j++)
                    s[i][j] += qa[i] * ka[j];
        }

        const bool diag = (kt == qi);
#pragma unroll
        for (int i = 0; i < 4; i++) {
            int qg = qi*64 + ty*4 + i;
#pragma unroll
            for (int j = 0; j < 4; j++) {
                int kg = kt*64 + tx*4 + j;
                s[i][j] = (diag && kg > qg) ? -1e30f : s[i][j] * scale;
            }
        }

#pragma unroll
        for (int i = 0; i < 4; i++) {
            float rm = fmaxf(fmaxf(s[i][0], s[i][1]), fmaxf(s[i][2], s[i][3]));
            rm = fmaxf(rm, __shfl_xor_sync(0xffffffffu, rm, 8));
            rm = fmaxf(rm, __shfl_xor_sync(0xffffffffu, rm, 4));
            rm = fmaxf(rm, __shfl_xor_sync(0xffffffffu, rm, 2));
            rm = fmaxf(rm, __shfl_xor_sync(0xffffffffu, rm, 1));
            float mn   = fmaxf(m[i], rm);
            float corr = __expf(m[i] - mn);
            float p0 = __expf(s[i][0] - mn);
            float p1 = __expf(s[i][1] - mn);
            float p2 = __expf(s[i][2] - mn);
            float p3 = __expf(s[i][3] - mn);
            float rs = (p0 + p1) + (p2 + p3);
            rs += __shfl_xor_sync(0xffffffffu, rs, 8);
            rs += __shfl_xor_sync(0xffffffffu, rs, 4);
            rs += __shfl_xor_sync(0xffffffffu, rs, 2);
            rs += __shfl_xor_sync(0xffffffffu, rs, 1);
            l[i] = l[i] * corr + rs;
#pragma unroll
            for (int j = 0; j < 4; j++) o[i][j] *= corr;
            m[i] = mn;
            *(float4*)&Ps[(ty*4+i)*QSTR + tx*4] = make_float4(p0, p1, p2, p3);
        }
        __syncthreads();

#pragma unroll 2
        for (int kk = 0; kk < 64; kk++) {
            float pr[4];
#pragma unroll
            for (int i = 0; i < 4; i++) pr[i] = Ps[(ty*4+i)*QSTR + kk];
            float4 v4 = *(const float4*)&Vs[kk*64 + tx*4];
            float va[4] = {v4.x, v4.y, v4.z, v4.w};
#pragma unroll
            for (int i = 0; i < 4; i++)
#pragma unroll
                for (int j = 0; j < 4; j++)
                    o[i][j] += pr[i] * va[j];
        }
    }

    float* Og = g_ctx + ((size_t)(b*S_ + qi*64 + ty*4)) * D_ + h*DK_ + tx*4;
#pragma unroll
    for (int i = 0; i < 4; i++) {
        float inv = 1.f / l[i];
        *(float4*)(Og + (size_t)i*D_) =
            make_float4(o[i][0]*inv, o[i][1]*inv, o[i][2]*inv, o[i][3]*inv);
    }
}

// ---------------------------------------------------------------------------
extern "C" void kernel_launch(void* const* d_in, const int* in_sizes, int n_in,
                              void* d_out, int out_size) {
    const float* q   = (const float*)d_in[0];
    const float* k   = (const float*)d_in[1];
    const float* v   = (const float*)d_in[2];
    const float* w_q = (const float*)d_in[4];
    const float* w_k = (const float*)d_in[5];
    const float* w_v = (const float*)d_in[6];
    const float* w_o = (const float*)d_in[7];
    float* out = (float*)d_out;

    float *gq, *gk, *gv, *gctx;
    __nv_bfloat16* bf;
    cudaGetSymbolAddress((void**)&gq,   g_q);
    cudaGetSymbolAddress((void**)&gk,   g_k);
    cudaGetSymbolAddress((void**)&gv,   g_v);
    cudaGetSymbolAddress((void**)&gctx, g_ctx);
    cudaGetSymbolAddress((void**)&bf,   g_bf);

    const size_t MD = (size_t)M_ * D_;
    __nv_bfloat16 *qh = bf + 0*MD, *ql = bf + 1*MD;
    __nv_bfloat16 *kh = bf + 2*MD, *kl = bf + 3*MD;
    __nv_bfloat16 *vh = bf + 4*MD, *vl = bf + 5*MD;
    __nv_bfloat16 *ch = bf + 6*MD, *cl = bf + 7*MD;
    __nv_bfloat16* wb = bf + 8*MD;
    __nv_bfloat16 *wqh = wb + 0*MW_, *wql = wb + 1*MW_;
    __nv_bfloat16 *wkh = wb + 2*MW_, *wkl = wb + 3*MW_;
    __nv_bfloat16 *wvh = wb + 4*MW_, *wvl = wb + 5*MW_;
    __nv_bfloat16 *woh = wb + 6*MW_, *wol = wb + 7*MW_;

    cudaFuncSetAttribute(flash_fwd, cudaFuncAttributeMaxDynamicSharedMemorySize,
                         SMEM_FLASH);
    cudaFuncSetAttribute(gemm_hmma_split,
                         cudaFuncAttributeMaxDynamicSharedMemorySize, SMEMG);

    const int n4i = (int)(MD / 4), n4w = MW_ / 4;
    split_bf16<<<n4i/256, 256>>>((const float4*)q,   qh,  ql,  n4i);
    split_bf16<<<n4i/256, 256>>>((const float4*)k,   kh,  kl,  n4i);
    split_bf16<<<n4i/256, 256>>>((const float4*)v,   vh,  vl,  n4i);
    split_bf16<<<n4w/256, 256>>>((const float4*)w_q, wqh, wql, n4w);
    split_bf16<<<n4w/256, 256>>>((const float4*)w_k, wkh, wkl, n4w);
    split_bf16<<<n4w/256, 256>>>((const float4*)w_v, wvh, wvl, n4w);
    split_bf16<<<n4w/256, 256>>>((const float4*)w_o, woh, wol, n4w);

    dim3 gGemm(D_/128, M_/128);   // (8, 64)
    gemm_hmma_split<<<gGemm, 256, SMEMG>>>(qh, ql, wqh, wql, gq);
    gemm_hmma_split<<<gGemm, 256, SMEMG>>>(kh, kl, wkh, wkl, gk);
    gemm_hmma_split<<<gGemm, 256, SMEMG>>>(vh, vl, wvh, wvl, gv);

    dim3 gAtt(S_/64, H_, B_);     // (32, 16, 4)
    flash_fwd<<<gAtt, 256, SMEM_FLASH>>>();

    split_bf16<<<n4i/256, 256>>>((const float4*)gctx, ch, cl, n4i);
    gemm_hmma_split<<<gGemm, 256, SMEMG>>>(ch, cl, woh, wol, out);
}

// round 6
// speedup vs baseline: 2.8983x; 1.7738x over previous
#include <cuda_runtime.h>
#include <cuda_bf16.h>
#include <cstdint>

#define B_  4
#define S_  2048
#define D_  1024
#define H_  16
#define DK_ 64
#define M_  (B_*S_)   // 8192 rows
#define MW_ (D_*D_)   // 1M weight elems
#define MD_ ((size_t)M_*D_)

// ---------------- scratch (no cudaMalloc allowed) ----------------
// bf16 pool: 14 input-sized + 8 weight-sized tiles
__device__ __nv_bfloat16 g_bf[14*MD_ + (size_t)8*MW_];

// ---------------- helpers ----------------
__device__ __forceinline__ uint32_t smem_u32(const void* p) {
    uint32_t a;
    asm("{ .reg .u64 t; cvta.to.shared.u64 t, %1; cvt.u32.u64 %0, t; }"
        : "=r"(a) : "l"(p));
    return a;
}
#define CP16(dst, src) \
    asm volatile("cp.async.cg.shared.global [%0], [%1], 16;" \
                 :: "r"(dst), "l"(src))
#define CP_COMMIT() asm volatile("cp.async.commit_group;" ::: "memory")
#define CP_WAIT(n)  asm volatile("cp.async.wait_group %0;" :: "n"(n) : "memory")

__device__ __forceinline__ void ldm_x4(uint32_t& d0, uint32_t& d1,
                                       uint32_t& d2, uint32_t& d3, uint32_t a) {
    asm volatile("ldmatrix.sync.aligned.m8n8.x4.shared.b16 {%0,%1,%2,%3}, [%4];"
                 : "=r"(d0), "=r"(d1), "=r"(d2), "=r"(d3) : "r"(a));
}
__device__ __forceinline__ void ldm_x4_t(uint32_t& d0, uint32_t& d1,
                                         uint32_t& d2, uint32_t& d3, uint32_t a) {
    asm volatile("ldmatrix.sync.aligned.m8n8.x4.trans.shared.b16 {%0,%1,%2,%3}, [%4];"
                 : "=r"(d0), "=r"(d1), "=r"(d2), "=r"(d3) : "r"(a));
}
__device__ __forceinline__ void mma_bf16(float& c0, float& c1, float& c2, float& c3,
                                         uint32_t a0, uint32_t a1, uint32_t a2, uint32_t a3,
                                         uint32_t b0, uint32_t b1) {
    asm volatile(
        "mma.sync.aligned.m16n8k16.row.col.f32.bf16.bf16.f32 "
        "{%0,%1,%2,%3}, {%4,%5,%6,%7}, {%8,%9}, {%0,%1,%2,%3};"
        : "+f"(c0), "+f"(c1), "+f"(c2), "+f"(c3)
        : "r"(a0), "r"(a1), "r"(a2), "r"(a3), "r"(b0), "r"(b1));
}
__device__ __forceinline__ void splitf(float x, __nv_bfloat16& h, __nv_bfloat16& l) {
    h = __float2bfloat16(x);
    l = __float2bfloat16(x - __bfloat162float(h));
}
__device__ __forceinline__ uint32_t b2u(__nv_bfloat16 a, __nv_bfloat16 b) {
    uint16_t ua = *reinterpret_cast<uint16_t*>(&a);
    uint16_t ub = *reinterpret_cast<uint16_t*>(&b);
    return (uint32_t)ua | ((uint32_t)ub << 16);
}

// ---------------------------------------------------------------------------
// fp32 -> (bf16 hi, bf16 lo) split
// ---------------------------------------------------------------------------
__global__ __launch_bounds__(256)
void split_bf16(const float4* __restrict__ x, __nv_bfloat16* __restrict__ hi,
                __nv_bfloat16* __restrict__ lo, int n4) {
    int i = blockIdx.x * blockDim.x + threadIdx.x;
    if (i >= n4) return;
    float4 v = x[i];
    float f[4] = {v.x, v.y, v.z, v.w};
    __nv_bfloat16 h[4], l[4];
#pragma unroll
    for (int j = 0; j < 4; j++) splitf(f[j], h[j], l[j]);
    *(uint2*)(hi + (size_t)i * 4) = *(uint2*)h;
    *(uint2*)(lo + (size_t)i * 4) = *(uint2*)l;
}

// ---------------------------------------------------------------------------
// HMMA split-bf16 GEMM: C = A @ W^T, 3 passes. Optional bf16 hi/lo output.
// ---------------------------------------------------------------------------
#define GBK   32
#define NCHK  (D_/GBK)            // 32
#define LDS_  40
#define TILEB (128*LDS_*2)
#define STAGEB (4*TILEB)
#define SMEMG (2*STAGEB)          // 81920 B

__global__ __launch_bounds__(256, 2)
void gemm_hmma_split(const __nv_bfloat16* __restrict__ Ah,
                     const __nv_bfloat16* __restrict__ Al,
                     const __nv_bfloat16* __restrict__ Wh,
                     const __nv_bfloat16* __restrict__ Wl,
                     float* __restrict__ C,
                     __nv_bfloat16* __restrict__ Chi,
                     __nv_bfloat16* __restrict__ Clo) {
    extern __shared__ char smg[];
    const uint32_t sb = smem_u32(smg);
    const int tid  = threadIdx.x;
    const int lane = tid & 31;
    const int wid  = tid >> 5;
    const int wm   = wid & 1;
    const int wn   = wid >> 1;
    const int bm = blockIdx.y * 128;
    const int bn = blockIdx.x * 128;

    const int lrow = (tid >> 2);
    const int lseg = (tid & 3) * 8;

    const __nv_bfloat16* gp[4] = {
        Ah + (size_t)(bm + lrow) * D_ + lseg,
        Al + (size_t)(bm + lrow) * D_ + lseg,
        Wh + (size_t)(bn + lrow) * D_ + lseg,
        Wl + (size_t)(bn + lrow) * D_ + lseg };
    const uint32_t sofs = (uint32_t)(lrow * LDS_ + lseg) * 2;

    float acc[4][4][4];
#pragma unroll
    for (int f = 0; f < 4; f++)
#pragma unroll
        for (int g = 0; g < 4; g++)
#pragma unroll
            for (int e = 0; e < 4; e++) acc[f][g][e] = 0.f;

    const int arow = wm * 64 + (lane & 15);
    const int acol = (lane >> 4) * 8;
    const int brow = wn * 32 + (lane & 7) + ((lane >> 4) << 3);
    const int bcol = ((lane >> 3) & 1) * 8;

#define PREFETCH(c, buf) do {                                                 \
    uint32_t dst = sb + (buf) * STAGEB;                                       \
    const size_t gofs = (size_t)(c) * GBK;                                    \
    _Pragma("unroll")                                                         \
    for (int t = 0; t < 2; t++) {                                             \
        uint32_t so = dst + sofs + t * 64 * LDS_ * 2;                         \
        size_t go = gofs + (size_t)t * 64 * D_;                               \
        CP16(so + 0 * TILEB, gp[0] + go);                                     \
        CP16(so + 1 * TILEB, gp[1] + go);                                     \
        CP16(so + 2 * TILEB, gp[2] + go);                                     \
        CP16(so + 3 * TILEB, gp[3] + go);                                     \
    }                                                                         \
    CP_COMMIT();                                                              \
} while (0)

    PREFETCH(0, 0);

    for (int c = 0; c < NCHK; ++c) {
        const int buf = c & 1;
        if (c + 1 < NCHK) { PREFETCH(c + 1, buf ^ 1); CP_WAIT(1); }
        else              { CP_WAIT(0); }
        __syncthreads();

        const uint32_t st = sb + buf * STAGEB;
#pragma unroll
        for (int s16 = 0; s16 < 2; ++s16) {
            const uint32_t aoff = (uint32_t)(arow * LDS_ + s16 * 16 + acol) * 2;
            const uint32_t boff = (uint32_t)(brow * LDS_ + s16 * 16 + bcol) * 2;

            uint32_t ra[4][4], rbh[2][4], rbl[2][4];
#pragma unroll
            for (int f = 0; f < 4; f++)
                ldm_x4(ra[f][0], ra[f][1], ra[f][2], ra[f][3],
                       st + 0 * TILEB + aoff + (uint32_t)(f * 16 * LDS_ * 2));
#pragma unroll
            for (int p = 0; p < 2; p++) {
                ldm_x4(rbh[p][0], rbh[p][1], rbh[p][2], rbh[p][3],
                       st + 2 * TILEB + boff + (uint32_t)(p * 16 * LDS_ * 2));
                ldm_x4(rbl[p][0], rbl[p][1], rbl[p][2], rbl[p][3],
                       st + 3 * TILEB + boff + (uint32_t)(p * 16 * LDS_ * 2));
            }
#pragma unroll
            for (int f = 0; f < 4; f++)
#pragma unroll
                for (int p = 0; p < 2; p++) {
                    mma_bf16(acc[f][2*p][0],   acc[f][2*p][1],   acc[f][2*p][2],   acc[f][2*p][3],
                             ra[f][0], ra[f][1], ra[f][2], ra[f][3], rbh[p][0], rbh[p][1]);
                    mma_bf16(acc[f][2*p+1][0], acc[f][2*p+1][1], acc[f][2*p+1][2], acc[f][2*p+1][3],
                             ra[f][0], ra[f][1], ra[f][2], ra[f][3], rbh[p][2], rbh[p][3]);
                    mma_bf16(acc[f][2*p][0],   acc[f][2*p][1],   acc[f][2*p][2],   acc[f][2*p][3],
                             ra[f][0], ra[f][1], ra[f][2], ra[f][3], rbl[p][0], rbl[p][1]);
                    mma_bf16(acc[f][2*p+1][0], acc[f][2*p+1][1], acc[f][2*p+1][2], acc[f][2*p+1][3],
                             ra[f][0], ra[f][1], ra[f][2], ra[f][3], rbl[p][2], rbl[p][3]);
                }
#pragma unroll
            for (int f = 0; f < 4; f++)
                ldm_x4(ra[f][0], ra[f][1], ra[f][2], ra[f][3],
                       st + 1 * TILEB + aoff + (uint32_t)(f * 16 * LDS_ * 2));
#pragma unroll
            for (int f = 0; f < 4; f++)
#pragma unroll
                for (int p = 0; p < 2; p++) {
                    mma_bf16(acc[f][2*p][0],   acc[f][2*p][1],   acc[f][2*p][2],   acc[f][2*p][3],
                             ra[f][0], ra[f][1], ra[f][2], ra[f][3], rbh[p][0], rbh[p][1]);
                    mma_bf16(acc[f][2*p+1][0], acc[f][2*p+1][1], acc[f][2*p+1][2], acc[f][2*p+1][3],
                             ra[f][0], ra[f][1], ra[f][2], ra[f][3], rbh[p][2], rbh[p][3]);
                }
        }
        __syncthreads();
    }
#undef PREFETCH

    const int crow = bm + wm * 64 + (lane >> 2);
    const int ccol = bn + wn * 32 + 2 * (lane & 3);
    if (Chi) {
#pragma unroll
        for (int f = 0; f < 4; f++)
#pragma unroll
            for (int g = 0; g < 4; g++) {
                size_t o0 = (size_t)(crow + f * 16)     * D_ + ccol + g * 8;
                size_t o1 = (size_t)(crow + f * 16 + 8) * D_ + ccol + g * 8;
                __nv_bfloat16 h0, h1, l0, l1;
                splitf(acc[f][g][0], h0, l0); splitf(acc[f][g][1], h1, l1);
                *(uint32_t*)(Chi + o0) = b2u(h0, h1);
                *(uint32_t*)(Clo + o0) = b2u(l0, l1);
                splitf(acc[f][g][2], h0, l0); splitf(acc[f][g][3], h1, l1);
                *(uint32_t*)(Chi + o1) = b2u(h0, h1);
                *(uint32_t*)(Clo + o1) = b2u(l0, l1);
            }
    } else {
#pragma unroll
        for (int f = 0; f < 4; f++)
#pragma unroll
            for (int g = 0; g < 4; g++) {
                float* p0 = C + (size_t)(crow + f * 16)     * D_ + ccol + g * 8;
                float* p1 = C + (size_t)(crow + f * 16 + 8) * D_ + ccol + g * 8;
                *(float2*)p0 = make_float2(acc[f][g][0], acc[f][g][1]);
                *(float2*)p1 = make_float2(acc[f][g][2], acc[f][g][3]);
            }
    }
}

// ---------------------------------------------------------------------------
// HMMA split-bf16 flash attention, causal.
// CTA: 128 q-rows of one (b,h); 8 warps x 16 rows. K-tile 64.
// ---------------------------------------------------------------------------
#define FQT 128
#define FKT 64
#define FSTR 72
#define QTILE1 (128*FSTR*2)       // one Q variant: 18432 B
#define QAREA  (2*QTILE1)
#define FT_B   (64*FSTR*2)        // 9216 B per K/V tile
#define STG_B  (4*FT_B)           // Kh,Kl,Vh,Vl
#define SMEMF  (QAREA + 2*STG_B)  // 110592 B

__global__ __launch_bounds__(256, 1)
void flash_hmma(const __nv_bfloat16* __restrict__ Qh_, const __nv_bfloat16* __restrict__ Ql_,
                const __nv_bfloat16* __restrict__ Kh_, const __nv_bfloat16* __restrict__ Kl_,
                const __nv_bfloat16* __restrict__ Vh_, const __nv_bfloat16* __restrict__ Vl_,
                __nv_bfloat16* __restrict__ Ch_, __nv_bfloat16* __restrict__ Cl_) {
    extern __shared__ char smf[];
    const uint32_t sb = smem_u32(smf);
    const int qt = gridDim.x - 1 - blockIdx.x;   // heavy tiles first
    const int h = blockIdx.y, b = blockIdx.z;
    const int tid = threadIdx.x, lane = tid & 31, w = tid >> 5;
    const int g = lane >> 2, tig = lane & 3;
    const int q8 = lane >> 3, r8 = lane & 7;

    const size_t rowQ0 = (size_t)b * S_ + (size_t)qt * FQT;
    const size_t colH  = (size_t)h * DK_;
    const size_t rowK0 = (size_t)b * S_;

    // ---- load Q hi/lo into smem [2][128][FSTR] ----
#pragma unroll
    for (int t = 0; t < 2; t++) {
        const __nv_bfloat16* src = t ? Ql_ : Qh_;
#pragma unroll
        for (int i = 0; i < 4; i++) {
            int idx = tid + i * 256;             // 1024 chunks of 16B
            int r = idx >> 3, c = idx & 7;
            *(uint4*)(smf + t * QTILE1 + (r * FSTR + c * 8) * 2) =
                *(const uint4*)(src + (rowQ0 + r) * D_ + colH + c * 8);
        }
    }

    const uint32_t stg0 = sb + QAREA;
#define PFETCH(kt_, buf_) do {                                                \
    const size_t kr = rowK0 + (size_t)(kt_) * FKT;                            \
    uint32_t dd = stg0 + (buf_) * STG_B;                                      \
    _Pragma("unroll")                                                         \
    for (int i2 = 0; i2 < 2; i2++) {                                          \
        int idx = tid + i2 * 256;                                             \
        int r = idx >> 3, c = idx & 7;                                        \
        uint32_t so = dd + (uint32_t)((r * FSTR + c * 8) * 2);                \
        size_t go = (kr + r) * D_ + colH + c * 8;                             \
        CP16(so + 0*FT_B, Kh_ + go);                                          \
        CP16(so + 1*FT_B, Kl_ + go);                                          \
        CP16(so + 2*FT_B, Vh_ + go);                                          \
        CP16(so + 3*FT_B, Vl_ + go);                                          \
    }                                                                         \
    CP_COMMIT();                                                              \
} while (0)

    PFETCH(0, 0);
    __syncthreads();

    // ---- Q fragments (A-layout) into registers ----
    uint32_t qfh[4][4], qfl[4][4];
    {
        const uint32_t qrow = (uint32_t)(w * 16 + 8 * (q8 & 1) + r8);
#pragma unroll
        for (int kc = 0; kc < 4; kc++) {
            uint32_t off = (qrow * FSTR + 16 * kc + 8 * (q8 >> 1)) * 2;
            ldm_x4(qfh[kc][0], qfh[kc][1], qfh[kc][2], qfh[kc][3], sb + off);
            ldm_x4(qfl[kc][0], qfl[kc][1], qfl[kc][2], qfl[kc][3], sb + QTILE1 + off);
        }
    }

    float oA[8][4];
#pragma unroll
    for (int j = 0; j < 8; j++)
#pragma unroll
        for (int e = 0; e < 4; e++) oA[j][e] = 0.f;
    float m0 = -1e30f, m1 = -1e30f, l0 = 0.f, l1 = 0.f;

    const int nkt = 2 * qt + 2;
    const int qbase = qt * FQT + w * 16;
    const float scale = 0.125f;

    for (int kt = 0; kt < nkt; kt++) {
        const int buf = kt & 1;
        if (kt + 1 < nkt) { PFETCH(kt + 1, buf ^ 1); CP_WAIT(1); }
        else              { CP_WAIT(0); }
        __syncthreads();

        if (kt * FKT <= qbase + 15) {
            const uint32_t stK = stg0 + buf * STG_B;
            float sA[8][4];
#pragma unroll
            for (int j = 0; j < 8; j++)
#pragma unroll
                for (int e = 0; e < 4; e++) sA[j][e] = 0.f;

            // ---- S = Q K^T, 3 split passes ----
            const uint32_t krow = (uint32_t)(8 * (q8 >> 1) + r8);
            const uint32_t kcol = (uint32_t)(8 * (q8 & 1));
#pragma unroll
            for (int kc = 0; kc < 4; kc++) {
                uint32_t kb[8][2];
                const uint32_t coff = (uint32_t)(16 * kc + kcol) * 2;
#pragma unroll
                for (int nf2 = 0; nf2 < 4; nf2++)
                    ldm_x4(kb[2*nf2][0], kb[2*nf2][1], kb[2*nf2+1][0], kb[2*nf2+1][1],
                           stK + ((16 * nf2 + krow) * FSTR) * 2 + coff);
#pragma unroll
                for (int j = 0; j < 8; j++) {
                    mma_bf16(sA[j][0], sA[j][1], sA[j][2], sA[j][3],
                             qfh[kc][0], qfh[kc][1], qfh[kc][2], qfh[kc][3], kb[j][0], kb[j][1]);
                    mma_bf16(sA[j][0], sA[j][1], sA[j][2], sA[j][3],
                             qfl[kc][0], qfl[kc][1], qfl[kc][2], qfl[kc][3], kb[j][0], kb[j][1]);
                }
#pragma unroll
                for (int nf2 = 0; nf2 < 4; nf2++)
                    ldm_x4(kb[2*nf2][0], kb[2*nf2][1], kb[2*nf2+1][0], kb[2*nf2+1][1],
                           stK + FT_B + ((16 * nf2 + krow) * FSTR) * 2 + coff);
#pragma unroll
                for (int j = 0; j < 8; j++)
                    mma_bf16(sA[j][0], sA[j][1], sA[j][2], sA[j][3],
                             qfh[kc][0], qfh[kc][1], qfh[kc][2], qfh[kc][3], kb[j][0], kb[j][1]);
            }

            // ---- scale + causal mask ----
#pragma unroll
            for (int j = 0; j < 8; j++)
#pragma unroll
                for (int e = 0; e < 4; e++) sA[j][e] *= scale;
            if (kt * FKT + FKT - 1 > qbase) {
                const int grow0 = qbase + g, grow1 = qbase + g + 8;
#pragma unroll
                for (int j = 0; j < 8; j++) {
                    int c0 = kt * FKT + 8 * j + 2 * tig;
                    if (c0     > grow0) sA[j][0] = -1e30f;
                    if (c0 + 1 > grow0) sA[j][1] = -1e30f;
                    if (c0     > grow1) sA[j][2] = -1e30f;
                    if (c0 + 1 > grow1) sA[j][3] = -1e30f;
                }
            }

            // ---- online softmax ----
            float t0 = -1e30f, t1 = -1e30f;
#pragma unroll
            for (int j = 0; j < 8; j++) {
                t0 = fmaxf(t0, fmaxf(sA[j][0], sA[j][1]));
                t1 = fmaxf(t1, fmaxf(sA[j][2], sA[j][3]));
            }
            t0 = fmaxf(t0, __shfl_xor_sync(0xffffffffu, t0, 1));
            t0 = fmaxf(t0, __shfl_xor_sync(0xffffffffu, t0, 2));
            t1 = fmaxf(t1, __shfl_xor_sync(0xffffffffu, t1, 1));
            t1 = fmaxf(t1, __shfl_xor_sync(0xffffffffu, t1, 2));
            const float mn0 = fmaxf(m0, t0), mn1 = fmaxf(m1, t1);
            const float cr0 = __expf(m0 - mn0), cr1 = __expf(m1 - mn1);

            uint32_t ph[4][4], pl[4][4];
            float rs0 = 0.f, rs1 = 0.f;
#pragma unroll
            for (int j = 0; j < 8; j++) {
                float p0 = __expf(sA[j][0] - mn0);
                float p1 = __expf(sA[j][1] - mn0);
                float p2 = __expf(sA[j][2] - mn1);
                float p3 = __expf(sA[j][3] - mn1);
                rs0 += p0 + p1; rs1 += p2 + p3;
                __nv_bfloat16 h0,h1,h2,h3,e0,e1,e2,e3;
                splitf(p0,h0,e0); splitf(p1,h1,e1);
                splitf(p2,h2,e2); splitf(p3,h3,e3);
                const int kc = j >> 1, o = (j & 1) * 2;
                ph[kc][o]   = b2u(h0,h1); pl[kc][o]   = b2u(e0,e1);
                ph[kc][o+1] = b2u(h2,h3); pl[kc][o+1] = b2u(e2,e3);
            }
            rs0 += __shfl_xor_sync(0xffffffffu, rs0, 1);
            rs0 += __shfl_xor_sync(0xffffffffu, rs0, 2);
            rs1 += __shfl_xor_sync(0xffffffffu, rs1, 1);
            rs1 += __shfl_xor_sync(0xffffffffu, rs1, 2);
            l0 = l0 * cr0 + rs0; l1 = l1 * cr1 + rs1;
            m0 = mn0; m1 = mn1;
#pragma unroll
            for (int j = 0; j < 8; j++) {
                oA[j][0] *= cr0; oA[j][1] *= cr0;
                oA[j][2] *= cr1; oA[j][3] *= cr1;
            }

            // ---- O += P V, 3 split passes ----
            const uint32_t vrow = (uint32_t)(8 * (q8 & 1) + r8);
            const uint32_t vcol = (uint32_t)(8 * (q8 >> 1));
#pragma unroll
            for (int kc2 = 0; kc2 < 4; kc2++) {
                uint32_t vb[8][2];
#pragma unroll
                for (int ng2 = 0; ng2 < 4; ng2++)
                    ldm_x4_t(vb[2*ng2][0], vb[2*ng2][1], vb[2*ng2+1][0], vb[2*ng2+1][1],
                             stK + 2*FT_B + ((16*kc2 + vrow) * FSTR + 16*ng2 + vcol) * 2);
#pragma unroll
                for (int j = 0; j < 8; j++) {
                    mma_bf16(oA[j][0], oA[j][1], oA[j][2], oA[j][3],
                             ph[kc2][0], ph[kc2][1], ph[kc2][2], ph[kc2][3], vb[j][0], vb[j][1]);
                    mma_bf16(oA[j][0], oA[j][1], oA[j][2], oA[j][3],
                             pl[kc2][0], pl[kc2][1], pl[kc2][2], pl[kc2][3], vb[j][0], vb[j][1]);
                }
#pragma unroll
                for (int ng2 = 0; ng2 < 4; ng2++)
                    ldm_x4_t(vb[2*ng2][0], vb[2*ng2][1], vb[2*ng2+1][0], vb[2*ng2+1][1],
                             stK + 3*FT_B + ((16*kc2 + vrow) * FSTR + 16*ng2 + vcol) * 2);
#pragma unroll
                for (int j = 0; j < 8; j++)
                    mma_bf16(oA[j][0], oA[j][1], oA[j][2], oA[j][3],
                             ph[kc2][0], ph[kc2][1], ph[kc2][2], ph[kc2][3], vb[j][0], vb[j][1]);
            }
        }
        __syncthreads();
    }
#undef PFETCH

    // ---- epilogue: normalize, split to hi/lo bf16 ----
    const float inv0 = 1.f / l0, inv1 = 1.f / l1;
    const size_t r0g = rowQ0 + w * 16 + g;
    const size_t r1g = r0g + 8;
#pragma unroll
    for (int j = 0; j < 8; j++) {
        const size_t col = colH + 8 * j + 2 * tig;
        __nv_bfloat16 h0, h1, l0b, l1b;
        splitf(oA[j][0] * inv0, h0, l0b); splitf(oA[j][1] * inv0, h1, l1b);
        *(uint32_t*)(Ch_ + r0g * D_ + col) = b2u(h0, h1);
        *(uint32_t*)(Cl_ + r0g * D_ + col) = b2u(l0b, l1b);
        splitf(oA[j][2] * inv1, h0, l0b); splitf(oA[j][3] * inv1, h1, l1b);
        *(uint32_t*)(Ch_ + r1g * D_ + col) = b2u(h0, h1);
        *(uint32_t*)(Cl_ + r1g * D_ + col) = b2u(l0b, l1b);
    }
}

// ---------------------------------------------------------------------------
extern "C" void kernel_launch(void* const* d_in, const int* in_sizes, int n_in,
                              void* d_out, int out_size) {
    const float* q   = (const float*)d_in[0];
    const float* k   = (const float*)d_in[1];
    const float* v   = (const float*)d_in[2];
    const float* w_q = (const float*)d_in[4];
    const float* w_k = (const float*)d_in[5];
    const float* w_v = (const float*)d_in[6];
    const float* w_o = (const float*)d_in[7];
    float* out = (float*)d_out;

    __nv_bfloat16* bf;
    cudaGetSymbolAddress((void**)&bf, g_bf);

    // input splits
    __nv_bfloat16 *xqh = bf + 0*MD_, *xql = bf + 1*MD_;
    __nv_bfloat16 *xkh = bf + 2*MD_, *xkl = bf + 3*MD_;
    __nv_bfloat16 *xvh = bf + 4*MD_, *xvl = bf + 5*MD_;
    // projected Q/K/V splits
    __nv_bfloat16 *qh = bf + 6*MD_,  *ql = bf + 7*MD_;
    __nv_bfloat16 *kh = bf + 8*MD_,  *kl = bf + 9*MD_;
    __nv_bfloat16 *vh = bf + 10*MD_, *vl = bf + 11*MD_;
    // attention context splits
    __nv_bfloat16 *ch = bf + 12*MD_, *cl = bf + 13*MD_;
    // weight splits
    __nv_bfloat16* wb = bf + 14*MD_;
    __nv_bfloat16 *wqh = wb + 0*MW_, *wql = wb + 1*MW_;
    __nv_bfloat16 *wkh = wb + 2*MW_, *wkl = wb + 3*MW_;
    __nv_bfloat16 *wvh = wb + 4*MW_, *wvl = wb + 5*MW_;
    __nv_bfloat16 *woh = wb + 6*MW_, *wol = wb + 7*MW_;

    cudaFuncSetAttribute(gemm_hmma_split,
                         cudaFuncAttributeMaxDynamicSharedMemorySize, SMEMG);
    cudaFuncSetAttribute(flash_hmma,
                         cudaFuncAttributeMaxDynamicSharedMemorySize, SMEMF);

    const int n4i = (int)(MD_ / 4), n4w = MW_ / 4;
    split_bf16<<<n4i/256, 256>>>((const float4*)q,   xqh, xql, n4i);
    split_bf16<<<n4i/256, 256>>>((const float4*)k,   xkh, xkl, n4i);
    split_bf16<<<n4i/256, 256>>>((const float4*)v,   xvh, xvl, n4i);
    split_bf16<<<n4w/256, 256>>>((const float4*)w_q, wqh, wql, n4w);
    split_bf16<<<n4w/256, 256>>>((const float4*)w_k, wkh, wkl, n4w);
    split_bf16<<<n4w/256, 256>>>((const float4*)w_v, wvh, wvl, n4w);
    split_bf16<<<n4w/256, 256>>>((const float4*)w_o, woh, wol, n4w);

    dim3 gGemm(D_/128, M_/128);   // (8, 64)
    gemm_hmma_split<<<gGemm, 256, SMEMG>>>(xqh, xql, wqh, wql, nullptr, qh, ql);
    gemm_hmma_split<<<gGemm, 256, SMEMG>>>(xkh, xkl, wkh, wkl, nullptr, kh, kl);
    gemm_hmma_split<<<gGemm, 256, SMEMG>>>(xvh, xvl, wvh, wvl, nullptr, vh, vl);

    dim3 gAtt(S_/FQT, H_, B_);    // (16, 16, 4)
    flash_hmma<<<gAtt, 256, SMEMF>>>(qh, ql, kh, kl, vh, vl, ch, cl);

    gemm_hmma_split<<<gGemm, 256, SMEMG>>>(ch, cl, woh, wol, out, nullptr, nullptr);
}

// round 7
// speedup vs baseline: 3.8281x; 1.3208x over previous
#include <cuda_runtime.h>
#include <cuda_bf16.h>
#include <cuda_fp16.h>
#include <cstdint>

#define B_  4
#define S_  2048
#define D_  1024
#define H_  16
#define DK_ 64
#define M_  (B_*S_)   // 8192 rows
#define MW_ (D_*D_)
#define MD_ ((size_t)M_*D_)

// ---------------- scratch pool (uint16 units; no cudaMalloc allowed) -------
__device__ uint16_t g_pool[14*MD_ + 8*(size_t)MW_];

// layout (element offsets, uint16 units)
#define OFF_XH  ((size_t)0)                    // 3*MD fp16: xq_h, xk_h, xv_h
#define OFF_XL  (3*MD_)                        // 3*MD fp16: lo parts
#define OFF_WH  (6*MD_)                        // 4*MW fp16: wq,wk,wv,wo
#define OFF_QKV (6*MD_ + 4*(size_t)MW_)        // 6*MD bf16: qh,ql,kh,kl,vh,vl
#define OFF_CH  (12*MD_ + 4*(size_t)MW_)       // MD fp16 ctx hi
#define OFF_CL  (13*MD_ + 4*(size_t)MW_)       // MD fp16 ctx lo

// ---------------- helpers ----------------
__device__ __forceinline__ uint32_t smem_u32(const void* p) {
    uint32_t a;
    asm("{ .reg .u64 t; cvta.to.shared.u64 t, %1; cvt.u32.u64 %0, t; }"
        : "=r"(a) : "l"(p));
    return a;
}
#define CP16(dst, src) \
    asm volatile("cp.async.cg.shared.global [%0], [%1], 16;" \
                 :: "r"(dst), "l"(src))
#define CP_COMMIT() asm volatile("cp.async.commit_group;" ::: "memory")
#define CP_WAIT0()  asm volatile("cp.async.wait_group 0;" ::: "memory")

__device__ __forceinline__ void ldm_x4(uint32_t& d0, uint32_t& d1,
                                       uint32_t& d2, uint32_t& d3, uint32_t a) {
    asm volatile("ldmatrix.sync.aligned.m8n8.x4.shared.b16 {%0,%1,%2,%3}, [%4];"
                 : "=r"(d0), "=r"(d1), "=r"(d2), "=r"(d3) : "r"(a));
}
__device__ __forceinline__ void ldm_x4_t(uint32_t& d0, uint32_t& d1,
                                         uint32_t& d2, uint32_t& d3, uint32_t a) {
    asm volatile("ldmatrix.sync.aligned.m8n8.x4.trans.shared.b16 {%0,%1,%2,%3}, [%4];"
                 : "=r"(d0), "=r"(d1), "=r"(d2), "=r"(d3) : "r"(a));
}
__device__ __forceinline__ void mma_bf16(float& c0, float& c1, float& c2, float& c3,
                                         uint32_t a0, uint32_t a1, uint32_t a2, uint32_t a3,
                                         uint32_t b0, uint32_t b1) {
    asm volatile(
        "mma.sync.aligned.m16n8k16.row.col.f32.bf16.bf16.f32 "
        "{%0,%1,%2,%3}, {%4,%5,%6,%7}, {%8,%9}, {%0,%1,%2,%3};"
        : "+f"(c0), "+f"(c1), "+f"(c2), "+f"(c3)
        : "r"(a0), "r"(a1), "r"(a2), "r"(a3), "r"(b0), "r"(b1));
}
__device__ __forceinline__ void mma_f16(float& c0, float& c1, float& c2, float& c3,
                                        uint32_t a0, uint32_t a1, uint32_t a2, uint32_t a3,
                                        uint32_t b0, uint32_t b1) {
    asm volatile(
        "mma.sync.aligned.m16n8k16.row.col.f32.f16.f16.f32 "
        "{%0,%1,%2,%3}, {%4,%5,%6,%7}, {%8,%9}, {%0,%1,%2,%3};"
        : "+f"(c0), "+f"(c1), "+f"(c2), "+f"(c3)
        : "r"(a0), "r"(a1), "r"(a2), "r"(a3), "r"(b0), "r"(b1));
}
__device__ __forceinline__ void splitf(float x, __nv_bfloat16& h, __nv_bfloat16& l) {
    h = __float2bfloat16(x);
    l = __float2bfloat16(x - __bfloat162float(h));
}
__device__ __forceinline__ void splith(float x, __half& h, __half& l) {
    h = __float2half_rn(x);
    l = __float2half_rn(x - __half2float(h));
}
__device__ __forceinline__ uint32_t b2u(__nv_bfloat16 a, __nv_bfloat16 b) {
    return (uint32_t)*(uint16_t*)&a | ((uint32_t)*(uint16_t*)&b << 16);
}
__device__ __forceinline__ uint32_t h2u(__half a, __half b) {
    return (uint32_t)*(uint16_t*)&a | ((uint32_t)*(uint16_t*)&b << 16);
}

// ---------------------------------------------------------------------------
// split inputs q,k,v (fp32) -> fp16 hi/lo into pool
// ---------------------------------------------------------------------------
__global__ __launch_bounds__(256)
void split_x(const float4* __restrict__ q, const float4* __restrict__ k,
             const float4* __restrict__ v) {
    const int which = blockIdx.y;
    const float4* src = which == 0 ? q : (which == 1 ? k : v);
    const size_t i = (size_t)blockIdx.x * 256 + threadIdx.x;   // n4 = MD/4
    float4 t = src[i];
    float f[4] = {t.x, t.y, t.z, t.w};
    __half h[4], l[4];
#pragma unroll
    for (int j = 0; j < 4; j++) splith(f[j], h[j], l[j]);
    ((uint2*)(g_pool + OFF_XH + (size_t)which * MD_))[i] = *(uint2*)h;
    ((uint2*)(g_pool + OFF_XL + (size_t)which * MD_))[i] = *(uint2*)l;
}

// convert 4 weights (fp32) -> fp16 into pool
__global__ __launch_bounds__(256)
void conv_w(const float4* __restrict__ wq, const float4* __restrict__ wk,
            const float4* __restrict__ wv, const float4* __restrict__ wo) {
    const int which = blockIdx.y;
    const float4* src = which == 0 ? wq : (which == 1 ? wk : (which == 2 ? wv : wo));
    const size_t i = (size_t)blockIdx.x * 256 + threadIdx.x;   // n4 = MW/4
    float4 t = src[i];
    __half h[4] = {__float2half_rn(t.x), __float2half_rn(t.y),
                   __float2half_rn(t.z), __float2half_rn(t.w)};
    ((uint2*)(g_pool + OFF_WH + (size_t)which * MW_))[i] = *(uint2*)h;
}

// ---------------------------------------------------------------------------
// fp16 2-pass HMMA GEMM: C = A @ W^T where A = Ah+Al (fp16 split), W = fp16.
// MODE 0: batched QKV (z selects), writes bf16 hi/lo for flash.
// MODE 1: output proj from ctx fp16 hi/lo, writes fp32.
// CTA tile 128x128, BK=32, 8 warps (2x4), warp tile 64x32, 2-stage cp.async.
// ---------------------------------------------------------------------------
#define LDS_  40
#define TILEB (128*LDS_*2)        // 10240 B
#define STG3  (3*TILEB)           // 30720 B
#define SMEMG (2*STG3)            // 61440 B

template<int MODE>
__global__ __launch_bounds__(256, 2)
void gemm_f16(float* __restrict__ Cout) {
    extern __shared__ char smg[];
    const uint32_t sb = smem_u32(smg);
    const int tid = threadIdx.x, lane = tid & 31, wid = tid >> 5;
    const int wm = wid & 1, wn = wid >> 1;
    const int bm = blockIdx.y * 128, bn = blockIdx.x * 128;
    const int z = blockIdx.z;

    const __half *Ah, *Al, *Wh;
    if (MODE == 0) {
        Ah = (const __half*)(g_pool + OFF_XH + (size_t)z * MD_);
        Al = (const __half*)(g_pool + OFF_XL + (size_t)z * MD_);
        Wh = (const __half*)(g_pool + OFF_WH + (size_t)z * MW_);
    } else {
        Ah = (const __half*)(g_pool + OFF_CH);
        Al = (const __half*)(g_pool + OFF_CL);
        Wh = (const __half*)(g_pool + OFF_WH + (size_t)3 * MW_);
    }

    const int lrow = tid >> 2;            // 0..63
    const int lseg = (tid & 3) * 8;       // fp16 elems
    const uint32_t sofs = (uint32_t)(lrow * LDS_ + lseg) * 2;

    float acc[4][4][4];
#pragma unroll
    for (int f = 0; f < 4; f++)
#pragma unroll
        for (int g = 0; g < 4; g++)
#pragma unroll
            for (int e = 0; e < 4; e++) acc[f][g][e] = 0.f;

    const int arow = wm * 64 + (lane & 15);
    const int acol = (lane >> 4) * 8;
    const int brow = wn * 32 + (lane & 7) + ((lane >> 4) << 3);
    const int bcol = ((lane >> 3) & 1) * 8;

#define PREFETCH(c, buf) do {                                                 \
    uint32_t dst = sb + (buf) * STG3;                                         \
    const size_t gofs = (size_t)(c) * 32;                                     \
    _Pragma("unroll")                                                         \
    for (int t = 0; t < 2; t++) {                                             \
        uint32_t so = dst + sofs + t * 64 * LDS_ * 2;                         \
        size_t ga = (size_t)(bm + lrow + t * 64) * D_ + gofs + lseg;          \
        size_t gw = (size_t)(bn + lrow + t * 64) * D_ + gofs + lseg;          \
        CP16(so + 0 * TILEB, Ah + ga);                                        \
        CP16(so + 1 * TILEB, Al + ga);                                        \
        CP16(so + 2 * TILEB, Wh + gw);                                        \
    }                                                                         \
    CP_COMMIT();                                                              \
} while (0)

    PREFETCH(0, 0);

    for (int c = 0; c < 32; ++c) {
        const int buf = c & 1;
        CP_WAIT0();
        __syncthreads();
        if (c + 1 < 32) PREFETCH(c + 1, buf ^ 1);

        const uint32_t st = sb + buf * STG3;
#pragma unroll
        for (int s16 = 0; s16 < 2; ++s16) {
            const uint32_t aoff = (uint32_t)(arow * LDS_ + s16 * 16 + acol) * 2;
            const uint32_t boff = (uint32_t)(brow * LDS_ + s16 * 16 + bcol) * 2;

            uint32_t ra[4][4], rb[2][4];
#pragma unroll
            for (int f = 0; f < 4; f++)
                ldm_x4(ra[f][0], ra[f][1], ra[f][2], ra[f][3],
                       st + 0 * TILEB + aoff + (uint32_t)(f * 16 * LDS_ * 2));
#pragma unroll
            for (int p = 0; p < 2; p++)
                ldm_x4(rb[p][0], rb[p][1], rb[p][2], rb[p][3],
                       st + 2 * TILEB + boff + (uint32_t)(p * 16 * LDS_ * 2));
#pragma unroll
            for (int f = 0; f < 4; f++)
#pragma unroll
                for (int p = 0; p < 2; p++) {
                    mma_f16(acc[f][2*p][0],   acc[f][2*p][1],   acc[f][2*p][2],   acc[f][2*p][3],
                            ra[f][0], ra[f][1], ra[f][2], ra[f][3], rb[p][0], rb[p][1]);
                    mma_f16(acc[f][2*p+1][0], acc[f][2*p+1][1], acc[f][2*p+1][2], acc[f][2*p+1][3],
                            ra[f][0], ra[f][1], ra[f][2], ra[f][3], rb[p][2], rb[p][3]);
                }
            // pass 2: Al * Wh
#pragma unroll
            for (int f = 0; f < 4; f++)
                ldm_x4(ra[f][0], ra[f][1], ra[f][2], ra[f][3],
                       st + 1 * TILEB + aoff + (uint32_t)(f * 16 * LDS_ * 2));
#pragma unroll
            for (int f = 0; f < 4; f++)
#pragma unroll
                for (int p = 0; p < 2; p++) {
                    mma_f16(acc[f][2*p][0],   acc[f][2*p][1],   acc[f][2*p][2],   acc[f][2*p][3],
                            ra[f][0], ra[f][1], ra[f][2], ra[f][3], rb[p][0], rb[p][1]);
                    mma_f16(acc[f][2*p+1][0], acc[f][2*p+1][1], acc[f][2*p+1][2], acc[f][2*p+1][3],
                            ra[f][0], ra[f][1], ra[f][2], ra[f][3], rb[p][2], rb[p][3]);
                }
        }
        __syncthreads();
    }
#undef PREFETCH

    const int crow = bm + wm * 64 + (lane >> 2);
    const int ccol = bn + wn * 32 + 2 * (lane & 3);
    if (MODE == 0) {
        __nv_bfloat16* Chi = (__nv_bfloat16*)(g_pool + OFF_QKV + (size_t)(2*z)   * MD_);
        __nv_bfloat16* Clo = (__nv_bfloat16*)(g_pool + OFF_QKV + (size_t)(2*z+1) * MD_);
#pragma unroll
        for (int f = 0; f < 4; f++)
#pragma unroll
            for (int g = 0; g < 4; g++) {
                size_t o0 = (size_t)(crow + f * 16)     * D_ + ccol + g * 8;
                size_t o1 = (size_t)(crow + f * 16 + 8) * D_ + ccol + g * 8;
                __nv_bfloat16 h0, h1, l0, l1;
                splitf(acc[f][g][0], h0, l0); splitf(acc[f][g][1], h1, l1);
                *(uint32_t*)(Chi + o0) = b2u(h0, h1);
                *(uint32_t*)(Clo + o0) = b2u(l0, l1);
                splitf(acc[f][g][2], h0, l0); splitf(acc[f][g][3], h1, l1);
                *(uint32_t*)(Chi + o1) = b2u(h0, h1);
                *(uint32_t*)(Clo + o1) = b2u(l0, l1);
            }
    } else {
#pragma unroll
        for (int f = 0; f < 4; f++)
#pragma unroll
            for (int g = 0; g < 4; g++) {
                float* p0 = Cout + (size_t)(crow + f * 16)     * D_ + ccol + g * 8;
                float* p1 = Cout + (size_t)(crow + f * 16 + 8) * D_ + ccol + g * 8;
                *(float2*)p0 = make_float2(acc[f][g][0], acc[f][g][1]);
                *(float2*)p1 = make_float2(acc[f][g][2], acc[f][g][3]);
            }
    }
}

// ---------------------------------------------------------------------------
// HMMA split-bf16 flash attention, causal (3-pass QK, 3-pass PV).
// CTA: 128 q-rows of one (b,h); 8 warps x 16 rows. K-tile 64. Single-sync DB.
// ---------------------------------------------------------------------------
#define FQT 128
#define FKT 64
#define FSTR 72
#define QTILE1 (128*FSTR*2)
#define QAREA  (2*QTILE1)
#define FT_B   (64*FSTR*2)
#define STG_B  (4*FT_B)
#define SMEMF  (QAREA + 2*STG_B)  // 110592 B

__global__ __launch_bounds__(256, 1)
void flash_hmma() {
    extern __shared__ char smf[];
    const uint32_t sb = smem_u32(smf);
    const int qt = gridDim.x - 1 - blockIdx.x;
    const int h = blockIdx.y, b = blockIdx.z;
    const int tid = threadIdx.x, lane = tid & 31, w = tid >> 5;
    const int g = lane >> 2, tig = lane & 3;
    const int q8 = lane >> 3, r8 = lane & 7;

    const __nv_bfloat16* Qh_ = (const __nv_bfloat16*)(g_pool + OFF_QKV + 0*MD_);
    const __nv_bfloat16* Ql_ = (const __nv_bfloat16*)(g_pool + OFF_QKV + 1*MD_);
    const __nv_bfloat16* Kh_ = (const __nv_bfloat16*)(g_pool + OFF_QKV + 2*MD_);
    const __nv_bfloat16* Kl_ = (const __nv_bfloat16*)(g_pool + OFF_QKV + 3*MD_);
    const __nv_bfloat16* Vh_ = (const __nv_bfloat16*)(g_pool + OFF_QKV + 4*MD_);
    const __nv_bfloat16* Vl_ = (const __nv_bfloat16*)(g_pool + OFF_QKV + 5*MD_);
    __half* Ch_ = (__half*)(g_pool + OFF_CH);
    __half* Cl_ = (__half*)(g_pool + OFF_CL);

    const size_t rowQ0 = (size_t)b * S_ + (size_t)qt * FQT;
    const size_t colH  = (size_t)h * DK_;
    const size_t rowK0 = (size_t)b * S_;

    const uint32_t stg0 = sb + QAREA;
#define PFETCH(kt_, buf_) do {                                                \
    const size_t kr = rowK0 + (size_t)(kt_) * FKT;                            \
    uint32_t dd = stg0 + (buf_) * STG_B;                                      \
    _Pragma("unroll")                                                         \
    for (int i2 = 0; i2 < 2; i2++) {                                          \
        int idx = tid + i2 * 256;                                             \
        int r = idx >> 3, c = idx & 7;                                        \
        uint32_t so = dd + (uint32_t)((r * FSTR + c * 8) * 2);                \
        size_t go = (kr + r) * D_ + colH + c * 8;                             \
        CP16(so + 0*FT_B, Kh_ + go);                                          \
        CP16(so + 1*FT_B, Kl_ + go);                                          \
        CP16(so + 2*FT_B, Vh_ + go);                                          \
        CP16(so + 3*FT_B, Vl_ + go);                                          \
    }                                                                         \
    CP_COMMIT();                                                              \
} while (0)

    PFETCH(0, 0);

    // ---- load Q hi/lo into smem [2][128][FSTR] ----
#pragma unroll
    for (int t = 0; t < 2; t++) {
        const __nv_bfloat16* src = t ? Ql_ : Qh_;
#pragma unroll
        for (int i = 0; i < 4; i++) {
            int idx = tid + i * 256;
            int r = idx >> 3, c = idx & 7;
            *(uint4*)(smf + t * QTILE1 + (r * FSTR + c * 8) * 2) =
                *(const uint4*)(src + (rowQ0 + r) * D_ + colH + c * 8);
        }
    }
    __syncthreads();

    // ---- Q fragments into registers ----
    uint32_t qfh[4][4], qfl[4][4];
    {
        const uint32_t qrow = (uint32_t)(w * 16 + 8 * (q8 & 1) + r8);
#pragma unroll
        for (int kc = 0; kc < 4; kc++) {
            uint32_t off = (qrow * FSTR + 16 * kc + 8 * (q8 >> 1)) * 2;
            ldm_x4(qfh[kc][0], qfh[kc][1], qfh[kc][2], qfh[kc][3], sb + off);
            ldm_x4(qfl[kc][0], qfl[kc][1], qfl[kc][2], qfl[kc][3], sb + QTILE1 + off);
        }
    }

    float oA[8][4];
#pragma unroll
    for (int j = 0; j < 8; j++)
#pragma unroll
        for (int e = 0; e < 4; e++) oA[j][e] = 0.f;
    float m0 = -1e30f, m1 = -1e30f, l0 = 0.f, l1 = 0.f;

    const int nkt = 2 * qt + 2;
    const int qbase = qt * FQT + w * 16;
    const float scale = 0.125f;

    for (int kt = 0; kt < nkt; kt++) {
        const int buf = kt & 1;
        CP_WAIT0();
        __syncthreads();
        if (kt + 1 < nkt) PFETCH(kt + 1, buf ^ 1);

        if (kt * FKT <= qbase + 15) {
            const uint32_t stK = stg0 + buf * STG_B;
            float sA[8][4];
#pragma unroll
            for (int j = 0; j < 8; j++)
#pragma unroll
                for (int e = 0; e < 4; e++) sA[j][e] = 0.f;

            const uint32_t krow = (uint32_t)(8 * (q8 >> 1) + r8);
            const uint32_t kcol = (uint32_t)(8 * (q8 & 1));
#pragma unroll
            for (int kc = 0; kc < 4; kc++) {
                uint32_t kb[8][2];
                const uint32_t coff = (uint32_t)(16 * kc + kcol) * 2;
#pragma unroll
                for (int nf2 = 0; nf2 < 4; nf2++)
                    ldm_x4(kb[2*nf2][0], kb[2*nf2][1], kb[2*nf2+1][0], kb[2*nf2+1][1],
                           stK + ((16 * nf2 + krow) * FSTR) * 2 + coff);
#pragma unroll
                for (int j = 0; j < 8; j++) {
                    mma_bf16(sA[j][0], sA[j][1], sA[j][2], sA[j][3],
                             qfh[kc][0], qfh[kc][1], qfh[kc][2], qfh[kc][3], kb[j][0], kb[j][1]);
                    mma_bf16(sA[j][0], sA[j][1], sA[j][2], sA[j][3],
                             qfl[kc][0], qfl[kc][1], qfl[kc][2], qfl[kc][3], kb[j][0], kb[j][1]);
                }
#pragma unroll
                for (int nf2 = 0; nf2 < 4; nf2++)
                    ldm_x4(kb[2*nf2][0], kb[2*nf2][1], kb[2*nf2+1][0], kb[2*nf2+1][1],
                           stK + FT_B + ((16 * nf2 + krow) * FSTR) * 2 + coff);
#pragma unroll
                for (int j = 0; j < 8; j++)
                    mma_bf16(sA[j][0], sA[j][1], sA[j][2], sA[j][3],
                             qfh[kc][0], qfh[kc][1], qfh[kc][2], qfh[kc][3], kb[j][0], kb[j][1]);
            }

#pragma unroll
            for (int j = 0; j < 8; j++)
#pragma unroll
                for (int e = 0; e < 4; e++) sA[j][e] *= scale;
            if (kt * FKT + FKT - 1 > qbase) {
                const int grow0 = qbase + g, grow1 = qbase + g + 8;
#pragma unroll
                for (int j = 0; j < 8; j++) {
                    int c0 = kt * FKT + 8 * j + 2 * tig;
                    if (c0     > grow0) sA[j][0] = -1e30f;
                    if (c0 + 1 > grow0) sA[j][1] = -1e30f;
                    if (c0     > grow1) sA[j][2] = -1e30f;
                    if (c0 + 1 > grow1) sA[j][3] = -1e30f;
                }
            }

            float t0 = -1e30f, t1 = -1e30f;
#pragma unroll
            for (int j = 0; j < 8; j++) {
                t0 = fmaxf(t0, fmaxf(sA[j][0], sA[j][1]));
                t1 = fmaxf(t1, fmaxf(sA[j][2], sA[j][3]));
            }
            t0 = fmaxf(t0, __shfl_xor_sync(0xffffffffu, t0, 1));
            t0 = fmaxf(t0, __shfl_xor_sync(0xffffffffu, t0, 2));
            t1 = fmaxf(t1, __shfl_xor_sync(0xffffffffu, t1, 1));
            t1 = fmaxf(t1, __shfl_xor_sync(0xffffffffu, t1, 2));
            const float mn0 = fmaxf(m0, t0), mn1 = fmaxf(m1, t1);
            const float cr0 = __expf(m0 - mn0), cr1 = __expf(m1 - mn1);

            uint32_t ph[4][4], pl[4][4];
            float rs0 = 0.f, rs1 = 0.f;
#pragma unroll
            for (int j = 0; j < 8; j++) {
                float p0 = __expf(sA[j][0] - mn0);
                float p1 = __expf(sA[j][1] - mn0);
                float p2 = __expf(sA[j][2] - mn1);
                float p3 = __expf(sA[j][3] - mn1);
                rs0 += p0 + p1; rs1 += p2 + p3;
                __nv_bfloat16 h0,h1,h2,h3,e0,e1,e2,e3;
                splitf(p0,h0,e0); splitf(p1,h1,e1);
                splitf(p2,h2,e2); splitf(p3,h3,e3);
                const int kc = j >> 1, o = (j & 1) * 2;
                ph[kc][o]   = b2u(h0,h1); pl[kc][o]   = b2u(e0,e1);
                ph[kc][o+1] = b2u(h2,h3); pl[kc][o+1] = b2u(e2,e3);
            }
            rs0 += __shfl_xor_sync(0xffffffffu, rs0, 1);
            rs0 += __shfl_xor_sync(0xffffffffu, rs0, 2);
            rs1 += __shfl_xor_sync(0xffffffffu, rs1, 1);
            rs1 += __shfl_xor_sync(0xffffffffu, rs1, 2);
            l0 = l0 * cr0 + rs0; l1 = l1 * cr1 + rs1;
            m0 = mn0; m1 = mn1;
#pragma unroll
            for (int j = 0; j < 8; j++) {
                oA[j][0] *= cr0; oA[j][1] *= cr0;
                oA[j][2] *= cr1; oA[j][3] *= cr1;
            }

            const uint32_t vrow = (uint32_t)(8 * (q8 & 1) + r8);
            const uint32_t vcol = (uint32_t)(8 * (q8 >> 1));
#pragma unroll
            for (int kc2 = 0; kc2 < 4; kc2++) {
                uint32_t vb[8][2];
#pragma unroll
                for (int ng2 = 0; ng2 < 4; ng2++)
                    ldm_x4_t(vb[2*ng2][0], vb[2*ng2][1], vb[2*ng2+1][0], vb[2*ng2+1][1],
                             stK + 2*FT_B + ((16*kc2 + vrow) * FSTR + 16*ng2 + vcol) * 2);
#pragma unroll
                for (int j = 0; j < 8; j++) {
                    mma_bf16(oA[j][0], oA[j][1], oA[j][2], oA[j][3],
                             ph[kc2][0], ph[kc2][1], ph[kc2][2], ph[kc2][3], vb[j][0], vb[j][1]);
                    mma_bf16(oA[j][0], oA[j][1], oA[j][2], oA[j][3],
                             pl[kc2][0], pl[kc2][1], pl[kc2][2], pl[kc2][3], vb[j][0], vb[j][1]);
                }
#pragma unroll
                for (int ng2 = 0; ng2 < 4; ng2++)
                    ldm_x4_t(vb[2*ng2][0], vb[2*ng2][1], vb[2*ng2+1][0], vb[2*ng2+1][1],
                             stK + 3*FT_B + ((16*kc2 + vrow) * FSTR + 16*ng2 + vcol) * 2);
#pragma unroll
                for (int j = 0; j < 8; j++)
                    mma_bf16(oA[j][0], oA[j][1], oA[j][2], oA[j][3],
                             ph[kc2][0], ph[kc2][1], ph[kc2][2], ph[kc2][3], vb[j][0], vb[j][1]);
            }
        }
        __syncthreads();
    }
#undef PFETCH

    // ---- epilogue: normalize, split to fp16 hi/lo ctx ----
    const float inv0 = 1.f / l0, inv1 = 1.f / l1;
    const size_t r0g = rowQ0 + w * 16 + g;
    const size_t r1g = r0g + 8;
#pragma unroll
    for (int j = 0; j < 8; j++) {
        const size_t col = colH + 8 * j + 2 * tig;
        __half h0, h1, l0b, l1b;
        splith(oA[j][0] * inv0, h0, l0b); splith(oA[j][1] * inv0, h1, l1b);
        *(uint32_t*)(Ch_ + r0g * D_ + col) = h2u(h0, h1);
        *(uint32_t*)(Cl_ + r0g * D_ + col) = h2u(l0b, l1b);
        splith(oA[j][2] * inv1, h0, l0b); splith(oA[j][3] * inv1, h1, l1b);
        *(uint32_t*)(Ch_ + r1g * D_ + col) = h2u(h0, h1);
        *(uint32_t*)(Cl_ + r1g * D_ + col) = h2u(l0b, l1b);
    }
}

// ---------------------------------------------------------------------------
extern "C" void kernel_launch(void* const* d_in, const int* in_sizes, int n_in,
                              void* d_out, int out_size) {
    const float* q   = (const float*)d_in[0];
    const float* k   = (const float*)d_in[1];
    const float* v   = (const float*)d_in[2];
    const float* w_q = (const float*)d_in[4];
    const float* w_k = (const float*)d_in[5];
    const float* w_v = (const float*)d_in[6];
    const float* w_o = (const float*)d_in[7];
    float* out = (float*)d_out;

    cudaFuncSetAttribute(gemm_f16<0>,
                         cudaFuncAttributeMaxDynamicSharedMemorySize, SMEMG);
    cudaFuncSetAttribute(gemm_f16<1>,
                         cudaFuncAttributeMaxDynamicSharedMemorySize, SMEMG);
    cudaFuncSetAttribute(flash_hmma,
                         cudaFuncAttributeMaxDynamicSharedMemorySize, SMEMF);

    split_x<<<dim3((unsigned)(MD_/4/256), 3), 256>>>(
        (const float4*)q, (const float4*)k, (const float4*)v);
    conv_w<<<dim3(MW_/4/256, 4), 256>>>(
        (const float4*)w_q, (const float4*)w_k, (const float4*)w_v, (const float4*)w_o);

    gemm_f16<0><<<dim3(D_/128, M_/128, 3), 256, SMEMG>>>(nullptr);

    flash_hmma<<<dim3(S_/FQT, H_, B_), 256, SMEMF>>>();

    gemm_f16<1><<<dim3(D_/128, M_/128, 1), 256, SMEMG>>>(out);
}

// round 8
// speedup vs baseline: 4.1732x; 1.0901x over previous
#include <cuda_runtime.h>
#include <cuda_bf16.h>
#include <cuda_fp16.h>
#include <cstdint>

#define B_  4
#define S_  2048
#define D_  1024
#define H_  16
#define DK_ 64
#define M_  (B_*S_)   // 8192 rows
#define MW_ (D_*D_)
#define MD_ ((size_t)M_*D_)

// ---------------- scratch pool (uint16 units; no cudaMalloc allowed) -------
__device__ uint16_t g_pool[12*MD_ + 4*(size_t)MW_];

#define OFF_XH  ((size_t)0)                    // 3*MD fp16: x q,k,v hi
#define OFF_XL  (3*MD_)                        // 3*MD fp16: lo
#define OFF_WH  (6*MD_)                        // 4*MW fp16: wq,wk,wv,wo
#define OFF_QH  (6*MD_ + 4*(size_t)MW_)        // MD fp16
#define OFF_QL  (7*MD_ + 4*(size_t)MW_)        // MD fp16
#define OFF_KH  (8*MD_ + 4*(size_t)MW_)        // MD fp16 (single)
#define OFF_VH  (9*MD_ + 4*(size_t)MW_)        // MD fp16 (single)
#define OFF_CH  (10*MD_ + 4*(size_t)MW_)       // MD fp16 ctx hi
#define OFF_CL  (11*MD_ + 4*(size_t)MW_)       // MD fp16 ctx lo

// ---------------- helpers ----------------
__device__ __forceinline__ uint32_t smem_u32(const void* p) {
    uint32_t a;
    asm("{ .reg .u64 t; cvta.to.shared.u64 t, %1; cvt.u32.u64 %0, t; }"
        : "=r"(a) : "l"(p));
    return a;
}
#define CP16(dst, src) \
    asm volatile("cp.async.cg.shared.global [%0], [%1], 16;" \
                 :: "r"(dst), "l"(src))
#define CP_COMMIT() asm volatile("cp.async.commit_group;" ::: "memory")
#define CP_WAIT0()  asm volatile("cp.async.wait_group 0;" ::: "memory")
#define CP_WAIT1()  asm volatile("cp.async.wait_group 1;" ::: "memory")

__device__ __forceinline__ void ldm_x4(uint32_t& d0, uint32_t& d1,
                                       uint32_t& d2, uint32_t& d3, uint32_t a) {
    asm volatile("ldmatrix.sync.aligned.m8n8.x4.shared.b16 {%0,%1,%2,%3}, [%4];"
                 : "=r"(d0), "=r"(d1), "=r"(d2), "=r"(d3) : "r"(a));
}
__device__ __forceinline__ void ldm_x4_t(uint32_t& d0, uint32_t& d1,
                                         uint32_t& d2, uint32_t& d3, uint32_t a) {
    asm volatile("ldmatrix.sync.aligned.m8n8.x4.trans.shared.b16 {%0,%1,%2,%3}, [%4];"
                 : "=r"(d0), "=r"(d1), "=r"(d2), "=r"(d3) : "r"(a));
}
__device__ __forceinline__ void mma_f16(float& c0, float& c1, float& c2, float& c3,
                                        uint32_t a0, uint32_t a1, uint32_t a2, uint32_t a3,
                                        uint32_t b0, uint32_t b1) {
    asm volatile(
        "mma.sync.aligned.m16n8k16.row.col.f32.f16.f16.f32 "
        "{%0,%1,%2,%3}, {%4,%5,%6,%7}, {%8,%9}, {%0,%1,%2,%3};"
        : "+f"(c0), "+f"(c1), "+f"(c2), "+f"(c3)
        : "r"(a0), "r"(a1), "r"(a2), "r"(a3), "r"(b0), "r"(b1));
}
__device__ __forceinline__ void splith(float x, __half& h, __half& l) {
    h = __float2half_rn(x);
    l = __float2half_rn(x - __half2float(h));
}
__device__ __forceinline__ uint32_t h2u(__half a, __half b) {
    return (uint32_t)*(uint16_t*)&a | ((uint32_t)*(uint16_t*)&b << 16);
}

// ---------------------------------------------------------------------------
// split inputs q,k,v (fp32) -> fp16 hi/lo
// ---------------------------------------------------------------------------
__global__ __launch_bounds__(256)
void split_x(const float4* __restrict__ q, const float4* __restrict__ k,
             const float4* __restrict__ v) {
    const int which = blockIdx.y;
    const float4* src = which == 0 ? q : (which == 1 ? k : v);
    const size_t i = (size_t)blockIdx.x * 256 + threadIdx.x;
    float4 t = src[i];
    float f[4] = {t.x, t.y, t.z, t.w};
    __half h[4], l[4];
#pragma unroll
    for (int j = 0; j < 4; j++) splith(f[j], h[j], l[j]);
    ((uint2*)(g_pool + OFF_XH + (size_t)which * MD_))[i] = *(uint2*)h;
    ((uint2*)(g_pool + OFF_XL + (size_t)which * MD_))[i] = *(uint2*)l;
}

__global__ __launch_bounds__(256)
void conv_w(const float4* __restrict__ wq, const float4* __restrict__ wk,
            const float4* __restrict__ wv, const float4* __restrict__ wo) {
    const int which = blockIdx.y;
    const float4* src = which == 0 ? wq : (which == 1 ? wk : (which == 2 ? wv : wo));
    const size_t i = (size_t)blockIdx.x * 256 + threadIdx.x;
    float4 t = src[i];
    __half h[4] = {__float2half_rn(t.x), __float2half_rn(t.y),
                   __float2half_rn(t.z), __float2half_rn(t.w)};
    ((uint2*)(g_pool + OFF_WH + (size_t)which * MW_))[i] = *(uint2*)h;
}

// ---------------------------------------------------------------------------
// fp16 2-pass HMMA GEMM, 3-stage cp.async, one sync/iter.
// MODE 0: batched QKV (z): z=0 -> fp16 hi/lo (Q), z=1/2 -> fp16 single (K/V).
// MODE 1: out proj from ctx hi/lo -> fp32.
// ---------------------------------------------------------------------------
#define LDS_  40
#define TILEB (128*LDS_*2)        // 10240 B
#define STG3  (3*TILEB)           // 30720 B (Ah,Al,W)
#define SMEMG (3*STG3)            // 92160 B

template<int MODE>
__global__ __launch_bounds__(256, 2)
void gemm_f16(float* __restrict__ Cout) {
    extern __shared__ char smg[];
    const uint32_t sb = smem_u32(smg);
    const int tid = threadIdx.x, lane = tid & 31, wid = tid >> 5;
    const int wm = wid & 1, wn = wid >> 1;
    const int bm = blockIdx.y * 128, bn = blockIdx.x * 128;
    const int z = blockIdx.z;

    const __half *Ah, *Al, *Wh;
    if (MODE == 0) {
        Ah = (const __half*)(g_pool + OFF_XH + (size_t)z * MD_);
        Al = (const __half*)(g_pool + OFF_XL + (size_t)z * MD_);
        Wh = (const __half*)(g_pool + OFF_WH + (size_t)z * MW_);
    } else {
        Ah = (const __half*)(g_pool + OFF_CH);
        Al = (const __half*)(g_pool + OFF_CL);
        Wh = (const __half*)(g_pool + OFF_WH + (size_t)3 * MW_);
    }

    const int lrow = tid >> 2;
    const int lseg = (tid & 3) * 8;
    const uint32_t sofs = (uint32_t)(lrow * LDS_ + lseg) * 2;

    float acc[4][4][4];
#pragma unroll
    for (int f = 0; f < 4; f++)
#pragma unroll
        for (int g = 0; g < 4; g++)
#pragma unroll
            for (int e = 0; e < 4; e++) acc[f][g][e] = 0.f;

    const int arow = wm * 64 + (lane & 15);
    const int acol = (lane >> 4) * 8;
    const int brow = wn * 32 + (lane & 7) + ((lane >> 4) << 3);
    const int bcol = ((lane >> 3) & 1) * 8;

#define PREFETCH(c, buf) do {                                                 \
    uint32_t dst = sb + (buf) * STG3;                                         \
    const size_t gofs = (size_t)(c) * 32;                                     \
    _Pragma("unroll")                                                         \
    for (int t = 0; t < 2; t++) {                                             \
        uint32_t so = dst + sofs + t * 64 * LDS_ * 2;                         \
        size_t ga = (size_t)(bm + lrow + t * 64) * D_ + gofs + lseg;          \
        size_t gw = (size_t)(bn + lrow + t * 64) * D_ + gofs + lseg;          \
        CP16(so + 0 * TILEB, Ah + ga);                                        \
        CP16(so + 1 * TILEB, Al + ga);                                        \
        CP16(so + 2 * TILEB, Wh + gw);                                        \
    }                                                                         \
    CP_COMMIT();                                                              \
} while (0)

    PREFETCH(0, 0);
    PREFETCH(1, 1);

    for (int c = 0; c < 32; ++c) {
        if (c + 1 < 32) CP_WAIT1(); else CP_WAIT0();
        __syncthreads();
        if (c + 2 < 32) {
            const int nb = (c + 2) % 3;
            PREFETCH(c + 2, nb);
        }

        const uint32_t st = sb + (c % 3) * STG3;
#pragma unroll
        for (int s16 = 0; s16 < 2; ++s16) {
            const uint32_t aoff = (uint32_t)(arow * LDS_ + s16 * 16 + acol) * 2;
            const uint32_t boff = (uint32_t)(brow * LDS_ + s16 * 16 + bcol) * 2;

            uint32_t ra[4][4], rb[2][4];
#pragma unroll
            for (int f = 0; f < 4; f++)
                ldm_x4(ra[f][0], ra[f][1], ra[f][2], ra[f][3],
                       st + 0 * TILEB + aoff + (uint32_t)(f * 16 * LDS_ * 2));
#pragma unroll
            for (int p = 0; p < 2; p++)
                ldm_x4(rb[p][0], rb[p][1], rb[p][2], rb[p][3],
                       st + 2 * TILEB + boff + (uint32_t)(p * 16 * LDS_ * 2));
#pragma unroll
            for (int f = 0; f < 4; f++)
#pragma unroll
                for (int p = 0; p < 2; p++) {
                    mma_f16(acc[f][2*p][0],   acc[f][2*p][1],   acc[f][2*p][2],   acc[f][2*p][3],
                            ra[f][0], ra[f][1], ra[f][2], ra[f][3], rb[p][0], rb[p][1]);
                    mma_f16(acc[f][2*p+1][0], acc[f][2*p+1][1], acc[f][2*p+1][2], acc[f][2*p+1][3],
                            ra[f][0], ra[f][1], ra[f][2], ra[f][3], rb[p][2], rb[p][3]);
                }
#pragma unroll
            for (int f = 0; f < 4; f++)
                ldm_x4(ra[f][0], ra[f][1], ra[f][2], ra[f][3],
                       st + 1 * TILEB + aoff + (uint32_t)(f * 16 * LDS_ * 2));
#pragma unroll
            for (int f = 0; f < 4; f++)
#pragma unroll
                for (int p = 0; p < 2; p++) {
                    mma_f16(acc[f][2*p][0],   acc[f][2*p][1],   acc[f][2*p][2],   acc[f][2*p][3],
                            ra[f][0], ra[f][1], ra[f][2], ra[f][3], rb[p][0], rb[p][1]);
                    mma_f16(acc[f][2*p+1][0], acc[f][2*p+1][1], acc[f][2*p+1][2], acc[f][2*p+1][3],
                            ra[f][0], ra[f][1], ra[f][2], ra[f][3], rb[p][2], rb[p][3]);
                }
        }
        __syncthreads();
    }
#undef PREFETCH

    const int crow = bm + wm * 64 + (lane >> 2);
    const int ccol = bn + wn * 32 + 2 * (lane & 3);
    if (MODE == 0) {
        if (z == 0) {
            __half* Qh = (__half*)(g_pool + OFF_QH);
            __half* Ql = (__half*)(g_pool + OFF_QL);
#pragma unroll
            for (int f = 0; f < 4; f++)
#pragma unroll
                for (int g = 0; g < 4; g++) {
                    size_t o0 = (size_t)(crow + f * 16)     * D_ + ccol + g * 8;
                    size_t o1 = (size_t)(crow + f * 16 + 8) * D_ + ccol + g * 8;
                    __half h0, h1, l0, l1;
                    splith(acc[f][g][0], h0, l0); splith(acc[f][g][1], h1, l1);
                    *(uint32_t*)(Qh + o0) = h2u(h0, h1);
                    *(uint32_t*)(Ql + o0) = h2u(l0, l1);
                    splith(acc[f][g][2], h0, l0); splith(acc[f][g][3], h1, l1);
                    *(uint32_t*)(Qh + o1) = h2u(h0, h1);
                    *(uint32_t*)(Ql + o1) = h2u(l0, l1);
                }
        } else {
            __half* Kv = (__half*)(g_pool + (z == 1 ? OFF_KH : OFF_VH));
#pragma unroll
            for (int f = 0; f < 4; f++)
#pragma unroll
                for (int g = 0; g < 4; g++) {
                    size_t o0 = (size_t)(crow + f * 16)     * D_ + ccol + g * 8;
                    size_t o1 = (size_t)(crow + f * 16 + 8) * D_ + ccol + g * 8;
                    *(uint32_t*)(Kv + o0) = h2u(__float2half_rn(acc[f][g][0]),
                                                __float2half_rn(acc[f][g][1]));
                    *(uint32_t*)(Kv + o1) = h2u(__float2half_rn(acc[f][g][2]),
                                                __float2half_rn(acc[f][g][3]));
                }
        }
    } else {
#pragma unroll
        for (int f = 0; f < 4; f++)
#pragma unroll
            for (int g = 0; g < 4; g++) {
                float* p0 = Cout + (size_t)(crow + f * 16)     * D_ + ccol + g * 8;
                float* p1 = Cout + (size_t)(crow + f * 16 + 8) * D_ + ccol + g * 8;
                *(float2*)p0 = make_float2(acc[f][g][0], acc[f][g][1]);
                *(float2*)p1 = make_float2(acc[f][g][2], acc[f][g][3]);
            }
    }
}

// ---------------------------------------------------------------------------
// fp16 2-pass flash attention, causal. Q fp16 hi/lo; K,V single fp16.
// 128 q-rows/CTA, 8 warps x 16 rows, K-tile 64, 3-stage cp.async.
// ---------------------------------------------------------------------------
#define FQT 128
#define FKT 64
#define FSTR 72
#define QTILE1 (128*FSTR*2)
#define QAREA  (2*QTILE1)         // 36864
#define FT_B   (64*FSTR*2)        // 9216
#define STG_B  (2*FT_B)           // Kh, Vh
#define SMEMF  (QAREA + 3*STG_B)  // 92160

__global__ __launch_bounds__(256, 1)
void flash_hmma() {
    extern __shared__ char smf[];
    const uint32_t sb = smem_u32(smf);
    const int qt = gridDim.x - 1 - blockIdx.x;
    const int h = blockIdx.y, b = blockIdx.z;
    const int tid = threadIdx.x, lane = tid & 31, w = tid >> 5;
    const int g = lane >> 2, tig = lane & 3;
    const int q8 = lane >> 3, r8 = lane & 7;

    const __half* Qh_ = (const __half*)(g_pool + OFF_QH);
    const __half* Ql_ = (const __half*)(g_pool + OFF_QL);
    const __half* Kh_ = (const __half*)(g_pool + OFF_KH);
    const __half* Vh_ = (const __half*)(g_pool + OFF_VH);
    __half* Ch_ = (__half*)(g_pool + OFF_CH);
    __half* Cl_ = (__half*)(g_pool + OFF_CL);

    const size_t rowQ0 = (size_t)b * S_ + (size_t)qt * FQT;
    const size_t colH  = (size_t)h * DK_;
    const size_t rowK0 = (size_t)b * S_;
    const int nkt = 2 * qt + 2;

    const uint32_t stg0 = sb + QAREA;
#define PFETCH(kt_, buf_) do {                                                \
    const size_t kr = rowK0 + (size_t)(kt_) * FKT;                            \
    uint32_t dd = stg0 + (buf_) * STG_B;                                      \
    _Pragma("unroll")                                                         \
    for (int i2 = 0; i2 < 2; i2++) {                                          \
        int idx = tid + i2 * 256;                                             \
        int r = idx >> 3, c = idx & 7;                                        \
        uint32_t so = dd + (uint32_t)((r * FSTR + c * 8) * 2);                \
        size_t go = (kr + r) * D_ + colH + c * 8;                             \
        CP16(so,        Kh_ + go);                                            \
        CP16(so + FT_B, Vh_ + go);                                            \
    }                                                                         \
    CP_COMMIT();                                                              \
} while (0)

    PFETCH(0, 0);
    PFETCH(1, 1);

    // ---- load Q hi/lo into smem ----
#pragma unroll
    for (int t = 0; t < 2; t++) {
        const __half* src = t ? Ql_ : Qh_;
#pragma unroll
        for (int i = 0; i < 4; i++) {
            int idx = tid + i * 256;
            int r = idx >> 3, c = idx & 7;
            *(uint4*)(smf + t * QTILE1 + (r * FSTR + c * 8) * 2) =
                *(const uint4*)(src + (rowQ0 + r) * D_ + colH + c * 8);
        }
    }
    __syncthreads();

    uint32_t qfh[4][4], qfl[4][4];
    {
        const uint32_t qrow = (uint32_t)(w * 16 + 8 * (q8 & 1) + r8);
#pragma unroll
        for (int kc = 0; kc < 4; kc++) {
            uint32_t off = (qrow * FSTR + 16 * kc + 8 * (q8 >> 1)) * 2;
            ldm_x4(qfh[kc][0], qfh[kc][1], qfh[kc][2], qfh[kc][3], sb + off);
            ldm_x4(qfl[kc][0], qfl[kc][1], qfl[kc][2], qfl[kc][3], sb + QTILE1 + off);
        }
    }

    float oA[8][4];
#pragma unroll
    for (int j = 0; j < 8; j++)
#pragma unroll
        for (int e = 0; e < 4; e++) oA[j][e] = 0.f;
    float m0 = -1e30f, m1 = -1e30f, l0 = 0.f, l1 = 0.f;

    const int qbase = qt * FQT + w * 16;
    const float scale = 0.125f;

    for (int kt = 0; kt < nkt; kt++) {
        if (kt + 1 < nkt) CP_WAIT1(); else CP_WAIT0();
        __syncthreads();
        if (kt + 2 < nkt) {
            const int nb = (kt + 2) % 3;
            PFETCH(kt + 2, nb);
        }

        if (kt * FKT <= qbase + 15) {
            const uint32_t stK = stg0 + (kt % 3) * STG_B;
            float sA[8][4];
#pragma unroll
            for (int j = 0; j < 8; j++)
#pragma unroll
                for (int e = 0; e < 4; e++) sA[j][e] = 0.f;

            // ---- S = Q K^T (2 passes: Qh, Ql vs Kh) ----
            const uint32_t krow = (uint32_t)(8 * (q8 >> 1) + r8);
            const uint32_t kcol = (uint32_t)(8 * (q8 & 1));
#pragma unroll
            for (int kc = 0; kc < 4; kc++) {
                uint32_t kb[8][2];
                const uint32_t coff = (uint32_t)(16 * kc + kcol) * 2;
#pragma unroll
                for (int nf2 = 0; nf2 < 4; nf2++)
                    ldm_x4(kb[2*nf2][0], kb[2*nf2][1], kb[2*nf2+1][0], kb[2*nf2+1][1],
                           stK + ((16 * nf2 + krow) * FSTR) * 2 + coff);
#pragma unroll
                for (int j = 0; j < 8; j++) {
                    mma_f16(sA[j][0], sA[j][1], sA[j][2], sA[j][3],
                            qfh[kc][0], qfh[kc][1], qfh[kc][2], qfh[kc][3], kb[j][0], kb[j][1]);
                    mma_f16(sA[j][0], sA[j][1], sA[j][2], sA[j][3],
                            qfl[kc][0], qfl[kc][1], qfl[kc][2], qfl[kc][3], kb[j][0], kb[j][1]);
                }
            }

#pragma unroll
            for (int j = 0; j < 8; j++)
#pragma unroll
                for (int e = 0; e < 4; e++) sA[j][e] *= scale;
            if (kt * FKT + FKT - 1 > qbase) {
                const int grow0 = qbase + g, grow1 = qbase + g + 8;
#pragma unroll
                for (int j = 0; j < 8; j++) {
                    int c0 = kt * FKT + 8 * j + 2 * tig;
                    if (c0     > grow0) sA[j][0] = -1e30f;
                    if (c0 + 1 > grow0) sA[j][1] = -1e30f;
                    if (c0     > grow1) sA[j][2] = -1e30f;
                    if (c0 + 1 > grow1) sA[j][3] = -1e30f;
                }
            }

            // ---- online softmax ----
            float t0 = -1e30f, t1 = -1e30f;
#pragma unroll
            for (int j = 0; j < 8; j++) {
                t0 = fmaxf(t0, fmaxf(sA[j][0], sA[j][1]));
                t1 = fmaxf(t1, fmaxf(sA[j][2], sA[j][3]));
            }
            t0 = fmaxf(t0, __shfl_xor_sync(0xffffffffu, t0, 1));
            t0 = fmaxf(t0, __shfl_xor_sync(0xffffffffu, t0, 2));
            t1 = fmaxf(t1, __shfl_xor_sync(0xffffffffu, t1, 1));
            t1 = fmaxf(t1, __shfl_xor_sync(0xffffffffu, t1, 2));
            const float mn0 = fmaxf(m0, t0), mn1 = fmaxf(m1, t1);
            const float cr0 = __expf(m0 - mn0), cr1 = __expf(m1 - mn1);

            uint32_t ph[4][4], pl[4][4];
            float rs0 = 0.f, rs1 = 0.f;
#pragma unroll
            for (int j = 0; j < 8; j++) {
                float p0 = __expf(sA[j][0] - mn0);
                float p1 = __expf(sA[j][1] - mn0);
                float p2 = __expf(sA[j][2] - mn1);
                float p3 = __expf(sA[j][3] - mn1);
                rs0 += p0 + p1; rs1 += p2 + p3;
                __half h0,h1,h2,h3,e0,e1,e2,e3;
                splith(p0,h0,e0); splith(p1,h1,e1);
                splith(p2,h2,e2); splith(p3,h3,e3);
                const int kc = j >> 1, o = (j & 1) * 2;
                ph[kc][o]   = h2u(h0,h1); pl[kc][o]   = h2u(e0,e1);
                ph[kc][o+1] = h2u(h2,h3); pl[kc][o+1] = h2u(e2,e3);
            }
            rs0 += __shfl_xor_sync(0xffffffffu, rs0, 1);
            rs0 += __shfl_xor_sync(0xffffffffu, rs0, 2);
            rs1 += __shfl_xor_sync(0xffffffffu, rs1, 1);
            rs1 += __shfl_xor_sync(0xffffffffu, rs1, 2);
            l0 = l0 * cr0 + rs0; l1 = l1 * cr1 + rs1;
            m0 = mn0; m1 = mn1;
#pragma unroll
            for (int j = 0; j < 8; j++) {
                oA[j][0] *= cr0; oA[j][1] *= cr0;
                oA[j][2] *= cr1; oA[j][3] *= cr1;
            }

            // ---- O += P V (2 passes: Ph, Pl vs Vh) ----
            const uint32_t vrow = (uint32_t)(8 * (q8 & 1) + r8);
            const uint32_t vcol = (uint32_t)(8 * (q8 >> 1));
#pragma unroll
            for (int kc2 = 0; kc2 < 4; kc2++) {
                uint32_t vb[8][2];
#pragma unroll
                for (int ng2 = 0; ng2 < 4; ng2++)
                    ldm_x4_t(vb[2*ng2][0], vb[2*ng2][1], vb[2*ng2+1][0], vb[2*ng2+1][1],
                             stK + FT_B + ((16*kc2 + vrow) * FSTR + 16*ng2 + vcol) * 2);
#pragma unroll
                for (int j = 0; j < 8; j++) {
                    mma_f16(oA[j][0], oA[j][1], oA[j][2], oA[j][3],
                            ph[kc2][0], ph[kc2][1], ph[kc2][2], ph[kc2][3], vb[j][0], vb[j][1]);
                    mma_f16(oA[j][0], oA[j][1], oA[j][2], oA[j][3],
                            pl[kc2][0], pl[kc2][1], pl[kc2][2], pl[kc2][3], vb[j][0], vb[j][1]);
                }
            }
        }
    }
#undef PFETCH

    // ---- epilogue: normalize, split fp16 hi/lo ----
    const float inv0 = 1.f / l0, inv1 = 1.f / l1;
    const size_t r0g = rowQ0 + w * 16 + g;
    const size_t r1g = r0g + 8;
#pragma unroll
    for (int j = 0; j < 8; j++) {
        const size_t col = colH + 8 * j + 2 * tig;
        __half h0, h1, l0b, l1b;
        splith(oA[j][0] * inv0, h0, l0b); splith(oA[j][1] * inv0, h1, l1b);
        *(uint32_t*)(Ch_ + r0g * D_ + col) = h2u(h0, h1);
        *(uint32_t*)(Cl_ + r0g * D_ + col) = h2u(l0b, l1b);
        splith(oA[j][2] * inv1, h0, l0b); splith(oA[j][3] * inv1, h1, l1b);
        *(uint32_t*)(Ch_ + r1g * D_ + col) = h2u(h0, h1);
        *(uint32_t*)(Cl_ + r1g * D_ + col) = h2u(l0b, l1b);
    }
}

// ---------------------------------------------------------------------------
extern "C" void kernel_launch(void* const* d_in, const int* in_sizes, int n_in,
                              void* d_out, int out_size) {
    const float* q   = (const float*)d_in[0];
    const float* k   = (const float*)d_in[1];
    const float* v   = (const float*)d_in[2];
    const float* w_q = (const float*)d_in[4];
    const float* w_k = (const float*)d_in[5];
    const float* w_v = (const float*)d_in[6];
    const float* w_o = (const float*)d_in[7];
    float* out = (float*)d_out;

    cudaFuncSetAttribute(gemm_f16<0>,
                         cudaFuncAttributeMaxDynamicSharedMemorySize, SMEMG);
    cudaFuncSetAttribute(gemm_f16<1>,
                         cudaFuncAttributeMaxDynamicSharedMemorySize, SMEMG);
    cudaFuncSetAttribute(flash_hmma,
                         cudaFuncAttributeMaxDynamicSharedMemorySize, SMEMF);

    split_x<<<dim3((unsigned)(MD_/4/256), 3), 256>>>(
        (const float4*)q, (const float4*)k, (const float4*)v);
    conv_w<<<dim3(MW_/4/256, 4), 256>>>(
        (const float4*)w_q, (const float4*)w_k, (const float4*)w_v, (const float4*)w_o);

    gemm_f16<0><<<dim3(D_/128, M_/128, 3), 256, SMEMG>>>(nullptr);

    flash_hmma<<<dim3(S_/FQT, H_, B_), 256, SMEMF>>>();

    gemm_f16<1><<<dim3(D_/128, M_/128, 1), 256, SMEMG>>>(out);
}

// round 9
// speedup vs baseline: 4.4237x; 1.0600x over previous
#include <cuda_runtime.h>
#include <cuda_bf16.h>
#include <cuda_fp16.h>
#include <cstdint>

#define B_  4
#define S_  2048
#define D_  1024
#define H_  16
#define DK_ 64
#define M_  (B_*S_)   // 8192 rows
#define MW_ (D_*D_)
#define MD_ ((size_t)M_*D_)

// ---------------- scratch pool (uint16 units; no cudaMalloc allowed) -------
__device__ uint16_t g_pool[12*MD_ + 4*(size_t)MW_];

#define OFF_XH  ((size_t)0)                    // 3*MD fp16: x q,k,v hi
#define OFF_XL  (3*MD_)                        // 3*MD fp16: lo
#define OFF_WH  (6*MD_)                        // 4*MW fp16: wq,wk,wv,wo
#define OFF_QH  (6*MD_ + 4*(size_t)MW_)        // MD fp16 (pre-scaled by 1/8)
#define OFF_QL  (7*MD_ + 4*(size_t)MW_)        // MD fp16
#define OFF_KH  (8*MD_ + 4*(size_t)MW_)        // MD fp16 (single)
#define OFF_VH  (9*MD_ + 4*(size_t)MW_)        // MD fp16 (single)
#define OFF_CH  (10*MD_ + 4*(size_t)MW_)       // MD fp16 ctx hi
#define OFF_CL  (11*MD_ + 4*(size_t)MW_)       // MD fp16 ctx lo

// ---------------- helpers ----------------
__device__ __forceinline__ uint32_t smem_u32(const void* p) {
    uint32_t a;
    asm("{ .reg .u64 t; cvta.to.shared.u64 t, %1; cvt.u32.u64 %0, t; }"
        : "=r"(a) : "l"(p));
    return a;
}
#define CP16(dst, src) \
    asm volatile("cp.async.cg.shared.global [%0], [%1], 16;" \
                 :: "r"(dst), "l"(src))
#define CP_COMMIT() asm volatile("cp.async.commit_group;" ::: "memory")
#define CP_WAIT0()  asm volatile("cp.async.wait_group 0;" ::: "memory")
#define CP_WAIT1()  asm volatile("cp.async.wait_group 1;" ::: "memory")

__device__ __forceinline__ void ldm_x4(uint32_t& d0, uint32_t& d1,
                                       uint32_t& d2, uint32_t& d3, uint32_t a) {
    asm volatile("ldmatrix.sync.aligned.m8n8.x4.shared.b16 {%0,%1,%2,%3}, [%4];"
                 : "=r"(d0), "=r"(d1), "=r"(d2), "=r"(d3) : "r"(a));
}
__device__ __forceinline__ void ldm_x4_t(uint32_t& d0, uint32_t& d1,
                                         uint32_t& d2, uint32_t& d3, uint32_t a) {
    asm volatile("ldmatrix.sync.aligned.m8n8.x4.trans.shared.b16 {%0,%1,%2,%3}, [%4];"
                 : "=r"(d0), "=r"(d1), "=r"(d2), "=r"(d3) : "r"(a));
}
__device__ __forceinline__ void mma_f16(float& c0, float& c1, float& c2, float& c3,
                                        uint32_t a0, uint32_t a1, uint32_t a2, uint32_t a3,
                                        uint32_t b0, uint32_t b1) {
    asm volatile(
        "mma.sync.aligned.m16n8k16.row.col.f32.f16.f16.f32 "
        "{%0,%1,%2,%3}, {%4,%5,%6,%7}, {%8,%9}, {%0,%1,%2,%3};"
        : "+f"(c0), "+f"(c1), "+f"(c2), "+f"(c3)
        : "r"(a0), "r"(a1), "r"(a2), "r"(a3), "r"(b0), "r"(b1));
}
__device__ __forceinline__ void splith(float x, __half& h, __half& l) {
    h = __float2half_rn(x);
    l = __float2half_rn(x - __half2float(h));
}
__device__ __forceinline__ uint32_t h2u(__half a, __half b) {
    return (uint32_t)*(uint16_t*)&a | ((uint32_t)*(uint16_t*)&b << 16);
}

// ---------------------------------------------------------------------------
// split inputs q,k,v (fp32) -> fp16 hi/lo
// ---------------------------------------------------------------------------
__global__ __launch_bounds__(256)
void split_x(const float4* __restrict__ q, const float4* __restrict__ k,
             const float4* __restrict__ v) {
    const int which = blockIdx.y;
    const float4* src = which == 0 ? q : (which == 1 ? k : v);
    const size_t i = (size_t)blockIdx.x * 256 + threadIdx.x;
    float4 t = src[i];
    float f[4] = {t.x, t.y, t.z, t.w};
    __half h[4], l[4];
#pragma unroll
    for (int j = 0; j < 4; j++) splith(f[j], h[j], l[j]);
    ((uint2*)(g_pool + OFF_XH + (size_t)which * MD_))[i] = *(uint2*)h;
    ((uint2*)(g_pool + OFF_XL + (size_t)which * MD_))[i] = *(uint2*)l;
}

__global__ __launch_bounds__(256)
void conv_w(const float4* __restrict__ wq, const float4* __restrict__ wk,
            const float4* __restrict__ wv, const float4* __restrict__ wo) {
    const int which = blockIdx.y;
    const float4* src = which == 0 ? wq : (which == 1 ? wk : (which == 2 ? wv : wo));
    const size_t i = (size_t)blockIdx.x * 256 + threadIdx.x;
    float4 t = src[i];
    __half h[4] = {__float2half_rn(t.x), __float2half_rn(t.y),
                   __float2half_rn(t.z), __float2half_rn(t.w)};
    ((uint2*)(g_pool + OFF_WH + (size_t)which * MW_))[i] = *(uint2*)h;
}

// ---------------------------------------------------------------------------
// fp16 2-pass HMMA GEMM, 3-stage cp.async, one sync/iter.
// MODE 0: batched QKV (z): z=0 -> Q fp16 hi/lo scaled 1/8; z=1/2 -> K/V fp16.
// MODE 1: out proj from ctx hi/lo -> fp32.
// ---------------------------------------------------------------------------
#define LDS_  40
#define TILEB (128*LDS_*2)        // 10240 B
#define STG3  (3*TILEB)           // 30720 B (Ah,Al,W)
#define SMEMG (3*STG3)            // 92160 B

template<int MODE>
__global__ __launch_bounds__(256, 2)
void gemm_f16(float* __restrict__ Cout) {
    extern __shared__ char smg[];
    const uint32_t sb = smem_u32(smg);
    const int tid = threadIdx.x, lane = tid & 31, wid = tid >> 5;
    const int wm = wid & 1, wn = wid >> 1;
    const int bm = blockIdx.y * 128, bn = blockIdx.x * 128;
    const int z = blockIdx.z;

    const __half *Ah, *Al, *Wh;
    if (MODE == 0) {
        Ah = (const __half*)(g_pool + OFF_XH + (size_t)z * MD_);
        Al = (const __half*)(g_pool + OFF_XL + (size_t)z * MD_);
        Wh = (const __half*)(g_pool + OFF_WH + (size_t)z * MW_);
    } else {
        Ah = (const __half*)(g_pool + OFF_CH);
        Al = (const __half*)(g_pool + OFF_CL);
        Wh = (const __half*)(g_pool + OFF_WH + (size_t)3 * MW_);
    }

    const int lrow = tid >> 2;
    const int lseg = (tid & 3) * 8;
    const uint32_t sofs = (uint32_t)(lrow * LDS_ + lseg) * 2;

    float acc[4][4][4];
#pragma unroll
    for (int f = 0; f < 4; f++)
#pragma unroll
        for (int g = 0; g < 4; g++)
#pragma unroll
            for (int e = 0; e < 4; e++) acc[f][g][e] = 0.f;

    const int arow = wm * 64 + (lane & 15);
    const int acol = (lane >> 4) * 8;
    const int brow = wn * 32 + (lane & 7) + ((lane >> 4) << 3);
    const int bcol = ((lane >> 3) & 1) * 8;

#define PREFETCH(c, buf) do {                                                 \
    uint32_t dst = sb + (buf) * STG3;                                         \
    const size_t gofs = (size_t)(c) * 32;                                     \
    _Pragma("unroll")                                                         \
    for (int t = 0; t < 2; t++) {                                             \
        uint32_t so = dst + sofs + t * 64 * LDS_ * 2;                         \
        size_t ga = (size_t)(bm + lrow + t * 64) * D_ + gofs + lseg;          \
        size_t gw = (size_t)(bn + lrow + t * 64) * D_ + gofs + lseg;          \
        CP16(so + 0 * TILEB, Ah + ga);                                        \
        CP16(so + 1 * TILEB, Al + ga);                                        \
        CP16(so + 2 * TILEB, Wh + gw);                                        \
    }                                                                         \
    CP_COMMIT();                                                              \
} while (0)

    PREFETCH(0, 0);
    PREFETCH(1, 1);

    for (int c = 0; c < 32; ++c) {
        if (c + 1 < 32) CP_WAIT1(); else CP_WAIT0();
        __syncthreads();
        if (c + 2 < 32) {
            const int nb = (c + 2) % 3;
            PREFETCH(c + 2, nb);
        }

        const uint32_t st = sb + (c % 3) * STG3;
#pragma unroll
        for (int s16 = 0; s16 < 2; ++s16) {
            const uint32_t aoff = (uint32_t)(arow * LDS_ + s16 * 16 + acol) * 2;
            const uint32_t boff = (uint32_t)(brow * LDS_ + s16 * 16 + bcol) * 2;

            uint32_t ra[4][4], rb[2][4];
#pragma unroll
            for (int f = 0; f < 4; f++)
                ldm_x4(ra[f][0], ra[f][1], ra[f][2], ra[f][3],
                       st + 0 * TILEB + aoff + (uint32_t)(f * 16 * LDS_ * 2));
#pragma unroll
            for (int p = 0; p < 2; p++)
                ldm_x4(rb[p][0], rb[p][1], rb[p][2], rb[p][3],
                       st + 2 * TILEB + boff + (uint32_t)(p * 16 * LDS_ * 2));
#pragma unroll
            for (int f = 0; f < 4; f++)
#pragma unroll
                for (int p = 0; p < 2; p++) {
                    mma_f16(acc[f][2*p][0],   acc[f][2*p][1],   acc[f][2*p][2],   acc[f][2*p][3],
                            ra[f][0], ra[f][1], ra[f][2], ra[f][3], rb[p][0], rb[p][1]);
                    mma_f16(acc[f][2*p+1][0], acc[f][2*p+1][1], acc[f][2*p+1][2], acc[f][2*p+1][3],
                            ra[f][0], ra[f][1], ra[f][2], ra[f][3], rb[p][2], rb[p][3]);
                }
#pragma unroll
            for (int f = 0; f < 4; f++)
                ldm_x4(ra[f][0], ra[f][1], ra[f][2], ra[f][3],
                       st + 1 * TILEB + aoff + (uint32_t)(f * 16 * LDS_ * 2));
#pragma unroll
            for (int f = 0; f < 4; f++)
#pragma unroll
                for (int p = 0; p < 2; p++) {
                    mma_f16(acc[f][2*p][0],   acc[f][2*p][1],   acc[f][2*p][2],   acc[f][2*p][3],
                            ra[f][0], ra[f][1], ra[f][2], ra[f][3], rb[p][0], rb[p][1]);
                    mma_f16(acc[f][2*p+1][0], acc[f][2*p+1][1], acc[f][2*p+1][2], acc[f][2*p+1][3],
                            ra[f][0], ra[f][1], ra[f][2], ra[f][3], rb[p][2], rb[p][3]);
                }
        }
        __syncthreads();
    }
#undef PREFETCH

    const int crow = bm + wm * 64 + (lane >> 2);
    const int ccol = bn + wn * 32 + 2 * (lane & 3);
    if (MODE == 0) {
        if (z == 0) {
            // Q: fold softmax scale 1/8 (exact pow2) into both halves
            __half* Qh = (__half*)(g_pool + OFF_QH);
            __half* Ql = (__half*)(g_pool + OFF_QL);
#pragma unroll
            for (int f = 0; f < 4; f++)
#pragma unroll
                for (int g = 0; g < 4; g++) {
                    size_t o0 = (size_t)(crow + f * 16)     * D_ + ccol + g * 8;
                    size_t o1 = (size_t)(crow + f * 16 + 8) * D_ + ccol + g * 8;
                    __half h0, h1, l0, l1;
                    splith(acc[f][g][0] * 0.125f, h0, l0);
                    splith(acc[f][g][1] * 0.125f, h1, l1);
                    *(uint32_t*)(Qh + o0) = h2u(h0, h1);
                    *(uint32_t*)(Ql + o0) = h2u(l0, l1);
                    splith(acc[f][g][2] * 0.125f, h0, l0);
                    splith(acc[f][g][3] * 0.125f, h1, l1);
                    *(uint32_t*)(Qh + o1) = h2u(h0, h1);
                    *(uint32_t*)(Ql + o1) = h2u(l0, l1);
                }
        } else {
            __half* Kv = (__half*)(g_pool + (z == 1 ? OFF_KH : OFF_VH));
#pragma unroll
            for (int f = 0; f < 4; f++)
#pragma unroll
                for (int g = 0; g < 4; g++) {
                    size_t o0 = (size_t)(crow + f * 16)     * D_ + ccol + g * 8;
                    size_t o1 = (size_t)(crow + f * 16 + 8) * D_ + ccol + g * 8;
                    *(uint32_t*)(Kv + o0) = h2u(__float2half_rn(acc[f][g][0]),
                                                __float2half_rn(acc[f][g][1]));
                    *(uint32_t*)(Kv + o1) = h2u(__float2half_rn(acc[f][g][2]),
                                                __float2half_rn(acc[f][g][3]));
                }
        }
    } else {
#pragma unroll
        for (int f = 0; f < 4; f++)
#pragma unroll
            for (int g = 0; g < 4; g++) {
                float* p0 = Cout + (size_t)(crow + f * 16)     * D_ + ccol + g * 8;
                float* p1 = Cout + (size_t)(crow + f * 16 + 8) * D_ + ccol + g * 8;
                *(float2*)p0 = make_float2(acc[f][g][0], acc[f][g][1]);
                *(float2*)p1 = make_float2(acc[f][g][2], acc[f][g][3]);
            }
    }
}

// ---------------------------------------------------------------------------
// fp16 2-pass flash attention, causal. Q fp16 hi/lo (pre-scaled); K,V fp16.
// 64 q-rows/CTA, 4 warps x 16 rows, K-tile 64, 2-stage cp.async, 3 CTAs/SM.
// ---------------------------------------------------------------------------
#define FQT 64
#define NW  4
#define NTH 128
#define FKT 64
#define FSTR 72
#define QTILE1 (FQT*FSTR*2)       // 9216
#define QAREA  (2*QTILE1)         // 18432
#define FT_B   (64*FSTR*2)        // 9216
#define STG_B  (2*FT_B)           // Kh, Vh = 18432
#define SMEMF  (QAREA + 2*STG_B)  // 55296

__global__ __launch_bounds__(NTH, 3)
void flash_hmma() {
    extern __shared__ char smf[];
    const uint32_t sb = smem_u32(smf);
    const int qt = gridDim.x - 1 - blockIdx.x;   // heavy tiles first
    const int h = blockIdx.y, b = blockIdx.z;
    const int tid = threadIdx.x, lane = tid & 31, w = tid >> 5;
    const int g = lane >> 2, tig = lane & 3;
    const int q8 = lane >> 3, r8 = lane & 7;

    const __half* Qh_ = (const __half*)(g_pool + OFF_QH);
    const __half* Ql_ = (const __half*)(g_pool + OFF_QL);
    const __half* Kh_ = (const __half*)(g_pool + OFF_KH);
    const __half* Vh_ = (const __half*)(g_pool + OFF_VH);
    __half* Ch_ = (__half*)(g_pool + OFF_CH);
    __half* Cl_ = (__half*)(g_pool + OFF_CL);

    const size_t rowQ0 = (size_t)b * S_ + (size_t)qt * FQT;
    const size_t colH  = (size_t)h * DK_;
    const size_t rowK0 = (size_t)b * S_;
    const int nkt = qt + 1;

    const uint32_t stg0 = sb + QAREA;
#define PFETCH(kt_, buf_) do {                                                \
    const size_t kr = rowK0 + (size_t)(kt_) * FKT;                            \
    uint32_t dd = stg0 + (buf_) * STG_B;                                      \
    _Pragma("unroll")                                                         \
    for (int i2 = 0; i2 < 4; i2++) {                                          \
        int idx = tid + i2 * NTH;                                             \
        int r = idx >> 3, c = idx & 7;                                        \
        uint32_t so = dd + (uint32_t)((r * FSTR + c * 8) * 2);                \
        size_t go = (kr + r) * D_ + colH + c * 8;                             \
        CP16(so,        Kh_ + go);                                            \
        CP16(so + FT_B, Vh_ + go);                                            \
    }                                                                         \
    CP_COMMIT();                                                              \
} while (0)

    PFETCH(0, 0);

    // ---- load Q hi/lo into smem ----
#pragma unroll
    for (int t = 0; t < 2; t++) {
        const __half* src = t ? Ql_ : Qh_;
#pragma unroll
        for (int i = 0; i < 4; i++) {
            int idx = tid + i * NTH;             // 512 chunks of 16B
            int r = idx >> 3, c = idx & 7;
            *(uint4*)(smf + t * QTILE1 + (r * FSTR + c * 8) * 2) =
                *(const uint4*)(src + (rowQ0 + r) * D_ + colH + c * 8);
        }
    }
    __syncthreads();

    uint32_t qfh[4][4], qfl[4][4];
    {
        const uint32_t qrow = (uint32_t)(w * 16 + 8 * (q8 & 1) + r8);
#pragma unroll
        for (int kc = 0; kc < 4; kc++) {
            uint32_t off = (qrow * FSTR + 16 * kc + 8 * (q8 >> 1)) * 2;
            ldm_x4(qfh[kc][0], qfh[kc][1], qfh[kc][2], qfh[kc][3], sb + off);
            ldm_x4(qfl[kc][0], qfl[kc][1], qfl[kc][2], qfl[kc][3], sb + QTILE1 + off);
        }
    }

    float oA[8][4];
#pragma unroll
    for (int j = 0; j < 8; j++)
#pragma unroll
        for (int e = 0; e < 4; e++) oA[j][e] = 0.f;
    float m0 = -1e30f, m1 = -1e30f, l0 = 0.f, l1 = 0.f;

    const int qbase = qt * FQT + w * 16;

    for (int kt = 0; kt < nkt; kt++) {
        const int buf = kt & 1;
        if (kt + 1 < nkt) { PFETCH(kt + 1, buf ^ 1); CP_WAIT1(); }
        else              { CP_WAIT0(); }
        __syncthreads();

        {
            const uint32_t stK = stg0 + buf * STG_B;
            float sA[8][4];
#pragma unroll
            for (int j = 0; j < 8; j++)
#pragma unroll
                for (int e = 0; e < 4; e++) sA[j][e] = 0.f;

            // ---- S = Q K^T (2 passes: Qh, Ql vs Kh) ----
            const uint32_t krow = (uint32_t)(8 * (q8 >> 1) + r8);
            const uint32_t kcol = (uint32_t)(8 * (q8 & 1));
#pragma unroll
            for (int kc = 0; kc < 4; kc++) {
                uint32_t kb[8][2];
                const uint32_t coff = (uint32_t)(16 * kc + kcol) * 2;
#pragma unroll
                for (int nf2 = 0; nf2 < 4; nf2++)
                    ldm_x4(kb[2*nf2][0], kb[2*nf2][1], kb[2*nf2+1][0], kb[2*nf2+1][1],
                           stK + ((16 * nf2 + krow) * FSTR) * 2 + coff);
#pragma unroll
                for (int j = 0; j < 8; j++) {
                    mma_f16(sA[j][0], sA[j][1], sA[j][2], sA[j][3],
                            qfh[kc][0], qfh[kc][1], qfh[kc][2], qfh[kc][3], kb[j][0], kb[j][1]);
                    mma_f16(sA[j][0], sA[j][1], sA[j][2], sA[j][3],
                            qfl[kc][0], qfl[kc][1], qfl[kc][2], qfl[kc][3], kb[j][0], kb[j][1]);
                }
            }

            // ---- causal mask (only the diagonal K-tile needs it) ----
            if (kt == nkt - 1) {
                const int grow0 = qbase + g, grow1 = qbase + g + 8;
#pragma unroll
                for (int j = 0; j < 8; j++) {
                    int c0 = kt * FKT + 8 * j + 2 * tig;
                    if (c0     > grow0) sA[j][0] = -1e30f;
                    if (c0 + 1 > grow0) sA[j][1] = -1e30f;
                    if (c0     > grow1) sA[j][2] = -1e30f;
                    if (c0 + 1 > grow1) sA[j][3] = -1e30f;
                }
            }

            // ---- online softmax ----
            float t0 = -1e30f, t1 = -1e30f;
#pragma unroll
            for (int j = 0; j < 8; j++) {
                t0 = fmaxf(t0, fmaxf(sA[j][0], sA[j][1]));
                t1 = fmaxf(t1, fmaxf(sA[j][2], sA[j][3]));
            }
            t0 = fmaxf(t0, __shfl_xor_sync(0xffffffffu, t0, 1));
            t0 = fmaxf(t0, __shfl_xor_sync(0xffffffffu, t0, 2));
            t1 = fmaxf(t1, __shfl_xor_sync(0xffffffffu, t1, 1));
            t1 = fmaxf(t1, __shfl_xor_sync(0xffffffffu, t1, 2));
            const float mn0 = fmaxf(m0, t0), mn1 = fmaxf(m1, t1);
            const float cr0 = __expf(m0 - mn0), cr1 = __expf(m1 - mn1);

            uint32_t ph[4][4], pl[4][4];
            float rs0 = 0.f, rs1 = 0.f;
#pragma unroll
            for (int j = 0; j < 8; j++) {
                float p0 = __expf(sA[j][0] - mn0);
                float p1 = __expf(sA[j][1] - mn0);
                float p2 = __expf(sA[j][2] - mn1);
                float p3 = __expf(sA[j][3] - mn1);
                rs0 += p0 + p1; rs1 += p2 + p3;
                __half h0,h1,h2,h3,e0,e1,e2,e3;
                splith(p0,h0,e0); splith(p1,h1,e1);
                splith(p2,h2,e2); splith(p3,h3,e3);
                const int kc = j >> 1, o = (j & 1) * 2;
                ph[kc][o]   = h2u(h0,h1); pl[kc][o]   = h2u(e0,e1);
                ph[kc][o+1] = h2u(h2,h3); pl[kc][o+1] = h2u(e2,e3);
            }
            rs0 += __shfl_xor_sync(0xffffffffu, rs0, 1);
            rs0 += __shfl_xor_sync(0xffffffffu, rs0, 2);
            rs1 += __shfl_xor_sync(0xffffffffu, rs1, 1);
            rs1 += __shfl_xor_sync(0xffffffffu, rs1, 2);
            l0 = l0 * cr0 + rs0; l1 = l1 * cr1 + rs1;
            m0 = mn0; m1 = mn1;
#pragma unroll
            for (int j = 0; j < 8; j++) {
                oA[j][0] *= cr0; oA[j][1] *= cr0;
                oA[j][2] *= cr1; oA[j][3] *= cr1;
            }

            // ---- O += P V (2 passes: Ph, Pl vs Vh) ----
            const uint32_t vrow = (uint32_t)(8 * (q8 & 1) + r8);
            const uint32_t vcol = (uint32_t)(8 * (q8 >> 1));
#pragma unroll
            for (int kc2 = 0; kc2 < 4; kc2++) {
                uint32_t vb[8][2];
#pragma unroll
                for (int ng2 = 0; ng2 < 4; ng2++)
                    ldm_x4_t(vb[2*ng2][0], vb[2*ng2][1], vb[2*ng2+1][0], vb[2*ng2+1][1],
                             stK + FT_B + ((16*kc2 + vrow) * FSTR + 16*ng2 + vcol) * 2);
#pragma unroll
                for (int j = 0; j < 8; j++) {
                    mma_f16(oA[j][0], oA[j][1], oA[j][2], oA[j][3],
                            ph[kc2][0], ph[kc2][1], ph[kc2][2], ph[kc2][3], vb[j][0], vb[j][1]);
                    mma_f16(oA[j][0], oA[j][1], oA[j][2], oA[j][3],
                            pl[kc2][0], pl[kc2][1], pl[kc2][2], pl[kc2][3], vb[j][0], vb[j][1]);
                }
            }
        }
        __syncthreads();
    }
#undef PFETCH

    // ---- epilogue: normalize, split fp16 hi/lo ----
    const float inv0 = 1.f / l0, inv1 = 1.f / l1;
    const size_t r0g = rowQ0 + w * 16 + g;
    const size_t r1g = r0g + 8;
#pragma unroll
    for (int j = 0; j < 8; j++) {
        const size_t col = colH + 8 * j + 2 * tig;
        __half h0, h1, l0b, l1b;
        splith(oA[j][0] * inv0, h0, l0b); splith(oA[j][1] * inv0, h1, l1b);
        *(uint32_t*)(Ch_ + r0g * D_ + col) = h2u(h0, h1);
        *(uint32_t*)(Cl_ + r0g * D_ + col) = h2u(l0b, l1b);
        splith(oA[j][2] * inv1, h0, l0b); splith(oA[j][3] * inv1, h1, l1b);
        *(uint32_t*)(Ch_ + r1g * D_ + col) = h2u(h0, h1);
        *(uint32_t*)(Cl_ + r1g * D_ + col) = h2u(l0b, l1b);
    }
}

// ---------------------------------------------------------------------------
extern "C" void kernel_launch(void* const* d_in, const int* in_sizes, int n_in,
                              void* d_out, int out_size) {
    const float* q   = (const float*)d_in[0];
    const float* k   = (const float*)d_in[1];
    const float* v   = (const float*)d_in[2];
    const float* w_q = (const float*)d_in[4];
    const float* w_k = (const float*)d_in[5];
    const float* w_v = (const float*)d_in[6];
    const float* w_o = (const float*)d_in[7];
    float* out = (float*)d_out;

    cudaFuncSetAttribute(gemm_f16<0>,
                         cudaFuncAttributeMaxDynamicSharedMemorySize, SMEMG);
    cudaFuncSetAttribute(gemm_f16<1>,
                         cudaFuncAttributeMaxDynamicSharedMemorySize, SMEMG);
    cudaFuncSetAttribute(flash_hmma,
                         cudaFuncAttributeMaxDynamicSharedMemorySize, SMEMF);

    split_x<<<dim3((unsigned)(MD_/4/256), 3), 256>>>(
        (const float4*)q, (const float4*)k, (const float4*)v);
    conv_w<<<dim3(MW_/4/256, 4), 256>>>(
        (const float4*)w_q, (const float4*)w_k, (const float4*)w_v, (const float4*)w_o);

    gemm_f16<0><<<dim3(D_/128, M_/128, 3), 256, SMEMG>>>(nullptr);

    flash_hmma<<<dim3(S_/FQT, H_, B_), NTH, SMEMF>>>();

    gemm_f16<1><<<dim3(D_/128, M_/128, 1), 256, SMEMG>>>(out);
}

// round 11
// speedup vs baseline: 5.4891x; 1.2408x over previous
#include <cuda_runtime.h>
#include <cuda_bf16.h>
#include <cuda_fp16.h>
#include <cstdint>

#define B_  4
#define S_  2048
#define D_  1024
#define H_  16
#define DK_ 64
#define M_  (B_*S_)   // 8192 rows
#define MW_ (D_*D_)
#define MD_ ((size_t)M_*D_)

// ---------------- scratch pool (uint16 units; no cudaMalloc allowed) -------
__device__ uint16_t g_pool[12*MD_ + 4*(size_t)MW_];

#define OFF_XH  ((size_t)0)                    // 3*MD fp16: x q,k,v hi
#define OFF_XL  (3*MD_)                        // 3*MD fp16: lo (only q's used)
#define OFF_WH  (6*MD_)                        // 4*MW fp16: wq,wk,wv,wo
#define OFF_QH  (6*MD_ + 4*(size_t)MW_)        // MD fp16 (pre-scaled by 1/8)
#define OFF_QL  (7*MD_ + 4*(size_t)MW_)        // MD fp16
#define OFF_KH  (8*MD_ + 4*(size_t)MW_)        // MD fp16 (single)
#define OFF_VH  (9*MD_ + 4*(size_t)MW_)        // MD fp16 (single)
#define OFF_CH  (10*MD_ + 4*(size_t)MW_)       // MD fp16 ctx hi
#define OFF_CL  (11*MD_ + 4*(size_t)MW_)       // MD fp16 ctx lo

// ---------------- helpers ----------------
__device__ __forceinline__ uint32_t smem_u32(const void* p) {
    uint32_t a;
    asm("{ .reg .u64 t; cvta.to.shared.u64 t, %1; cvt.u32.u64 %0, t; }"
        : "=r"(a) : "l"(p));
    return a;
}
#define CP16(dst, src) \
    asm volatile("cp.async.cg.shared.global [%0], [%1], 16;" \
                 :: "r"(dst), "l"(src))
#define CP_COMMIT() asm volatile("cp.async.commit_group;" ::: "memory")
#define CP_WAIT0()  asm volatile("cp.async.wait_group 0;" ::: "memory")
#define CP_WAIT1()  asm volatile("cp.async.wait_group 1;" ::: "memory")

__device__ __forceinline__ void ldm_x4(uint32_t& d0, uint32_t& d1,
                                       uint32_t& d2, uint32_t& d3, uint32_t a) {
    asm volatile("ldmatrix.sync.aligned.m8n8.x4.shared.b16 {%0,%1,%2,%3}, [%4];"
                 : "=r"(d0), "=r"(d1), "=r"(d2), "=r"(d3) : "r"(a));
}
__device__ __forceinline__ void ldm_x4_t(uint32_t& d0, uint32_t& d1,
                                         uint32_t& d2, uint32_t& d3, uint32_t a) {
    asm volatile("ldmatrix.sync.aligned.m8n8.x4.trans.shared.b16 {%0,%1,%2,%3}, [%4];"
                 : "=r"(d0), "=r"(d1), "=r"(d2), "=r"(d3) : "r"(a));
}
__device__ __forceinline__ void mma_f16(float& c0, float& c1, float& c2, float& c3,
                                        uint32_t a0, uint32_t a1, uint32_t a2, uint32_t a3,
                                        uint32_t b0, uint32_t b1) {
    asm volatile(
        "mma.sync.aligned.m16n8k16.row.col.f32.f16.f16.f32 "
        "{%0,%1,%2,%3}, {%4,%5,%6,%7}, {%8,%9}, {%0,%1,%2,%3};"
        : "+f"(c0), "+f"(c1), "+f"(c2), "+f"(c3)
        : "r"(a0), "r"(a1), "r"(a2), "r"(a3), "r"(b0), "r"(b1));
}
__device__ __forceinline__ void splith(float x, __half& h, __half& l) {
    h = __float2half_rn(x);
    l = __float2half_rn(x - __half2float(h));
}
__device__ __forceinline__ uint32_t h2u(__half a, __half b) {
    return (uint32_t)*(uint16_t*)&a | ((uint32_t)*(uint16_t*)&b << 16);
}

// ---------------------------------------------------------------------------
// split inputs q,k,v (fp32) -> fp16 hi/lo
// ---------------------------------------------------------------------------
__global__ __launch_bounds__(256)
void split_x(const float4* __restrict__ q, const float4* __restrict__ k,
             const float4* __restrict__ v) {
    const int which = blockIdx.y;
    const float4* src = which == 0 ? q : (which == 1 ? k : v);
    const size_t i = (size_t)blockIdx.x * 256 + threadIdx.x;
    float4 t = src[i];
    float f[4] = {t.x, t.y, t.z, t.w};
    __half h[4], l[4];
#pragma unroll
    for (int j = 0; j < 4; j++) splith(f[j], h[j], l[j]);
    ((uint2*)(g_pool + OFF_XH + (size_t)which * MD_))[i] = *(uint2*)h;
    ((uint2*)(g_pool + OFF_XL + (size_t)which * MD_))[i] = *(uint2*)l;
}

__global__ __launch_bounds__(256)
void conv_w(const float4* __restrict__ wq, const float4* __restrict__ wk,
            const float4* __restrict__ wv, const float4* __restrict__ wo) {
    const int which = blockIdx.y;
    const float4* src = which == 0 ? wq : (which == 1 ? wk : (which == 2 ? wv : wo));
    const size_t i = (size_t)blockIdx.x * 256 + threadIdx.x;
    float4 t = src[i];
    __half h[4] = {__float2half_rn(t.x), __float2half_rn(t.y),
                   __float2half_rn(t.z), __float2half_rn(t.w)};
    ((uint2*)(g_pool + OFF_WH + (size_t)which * MW_))[i] = *(uint2*)h;
}

// ---------------------------------------------------------------------------
// fp16 HMMA GEMM, 3-stage cp.async, one sync/iter.
// MODE 0, z=0: Q proj, 2-pass, out fp16 hi/lo scaled 1/8.
// MODE 0, z=1/2: K/V proj, 1-PASS (hi only), out fp16 single.
// MODE 1: out proj from ctx hi/lo, 2-pass, out fp32.
// ---------------------------------------------------------------------------
#define LDS_  40
#define TILEB (128*LDS_*2)        // 10240 B
#define STG3  (3*TILEB)           // 30720 B (Ah,Al,W)
#define SMEMG (3*STG3)            // 92160 B

template<int MODE>
__global__ __launch_bounds__(256, 2)
void gemm_f16(float* __restrict__ Cout) {
    extern __shared__ char smg[];
    const uint32_t sb = smem_u32(smg);
    const int tid = threadIdx.x, lane = tid & 31, wid = tid >> 5;
    const int wm = wid & 1, wn = wid >> 1;
    const int bm = blockIdx.y * 128, bn = blockIdx.x * 128;
    const int z = blockIdx.z;
    const bool two = (MODE == 1) || (z == 0);

    const __half *Ah, *Al, *Wh;
    if (MODE == 0) {
        Ah = (const __half*)(g_pool + OFF_XH + (size_t)z * MD_);
        Al = (const __half*)(g_pool + OFF_XL + (size_t)z * MD_);
        Wh = (const __half*)(g_pool + OFF_WH + (size_t)z * MW_);
    } else {
        Ah = (const __half*)(g_pool + OFF_CH);
        Al = (const __half*)(g_pool + OFF_CL);
        Wh = (const __half*)(g_pool + OFF_WH + (size_t)3 * MW_);
    }

    const int lrow = tid >> 2;
    const int lseg = (tid & 3) * 8;
    const uint32_t sofs = (uint32_t)(lrow * LDS_ + lseg) * 2;

    float acc[4][4][4];
#pragma unroll
    for (int f = 0; f < 4; f++)
#pragma unroll
        for (int g = 0; g < 4; g++)
#pragma unroll
            for (int e = 0; e < 4; e++) acc[f][g][e] = 0.f;

    const int arow = wm * 64 + (lane & 15);
    const int acol = (lane >> 4) * 8;
    const int brow = wn * 32 + (lane & 7) + ((lane >> 4) << 3);
    const int bcol = ((lane >> 3) & 1) * 8;

#define PREFETCH(c, buf) do {                                                 \
    uint32_t dst = sb + (buf) * STG3;                                         \
    const size_t gofs = (size_t)(c) * 32;                                     \
    _Pragma("unroll")                                                         \
    for (int t = 0; t < 2; t++) {                                             \
        uint32_t so = dst + sofs + t * 64 * LDS_ * 2;                         \
        size_t ga = (size_t)(bm + lrow + t * 64) * D_ + gofs + lseg;          \
        size_t gw = (size_t)(bn + lrow + t * 64) * D_ + gofs + lseg;          \
        CP16(so + 0 * TILEB, Ah + ga);                                        \
        if (two) CP16(so + 1 * TILEB, Al + ga);                               \
        CP16(so + 2 * TILEB, Wh + gw);                                        \
    }                                                                         \
    CP_COMMIT();                                                              \
} while (0)

    PREFETCH(0, 0);
    PREFETCH(1, 1);

    for (int c = 0; c < 32; ++c) {
        if (c + 1 < 32) CP_WAIT1(); else CP_WAIT0();
        __syncthreads();
        if (c + 2 < 32) {
            const int nb = (c + 2) % 3;
            PREFETCH(c + 2, nb);
        }

        const uint32_t st = sb + (c % 3) * STG3;
#pragma unroll
        for (int s16 = 0; s16 < 2; ++s16) {
            const uint32_t aoff = (uint32_t)(arow * LDS_ + s16 * 16 + acol) * 2;
            const uint32_t boff = (uint32_t)(brow * LDS_ + s16 * 16 + bcol) * 2;

            uint32_t ra[4][4], rb[2][4];
#pragma unroll
            for (int f = 0; f < 4; f++)
                ldm_x4(ra[f][0], ra[f][1], ra[f][2], ra[f][3],
                       st + 0 * TILEB + aoff + (uint32_t)(f * 16 * LDS_ * 2));
#pragma unroll
            for (int p = 0; p < 2; p++)
                ldm_x4(rb[p][0], rb[p][1], rb[p][2], rb[p][3],
                       st + 2 * TILEB + boff + (uint32_t)(p * 16 * LDS_ * 2));
#pragma unroll
            for (int f = 0; f < 4; f++)
#pragma unroll
                for (int p = 0; p < 2; p++) {
                    mma_f16(acc[f][2*p][0],   acc[f][2*p][1],   acc[f][2*p][2],   acc[f][2*p][3],
                            ra[f][0], ra[f][1], ra[f][2], ra[f][3], rb[p][0], rb[p][1]);
                    mma_f16(acc[f][2*p+1][0], acc[f][2*p+1][1], acc[f][2*p+1][2], acc[f][2*p+1][3],
                            ra[f][0], ra[f][1], ra[f][2], ra[f][3], rb[p][2], rb[p][3]);
                }
            if (two) {
#pragma unroll
                for (int f = 0; f < 4; f++)
                    ldm_x4(ra[f][0], ra[f][1], ra[f][2], ra[f][3],
                           st + 1 * TILEB + aoff + (uint32_t)(f * 16 * LDS_ * 2));
#pragma unroll
                for (int f = 0; f < 4; f++)
#pragma unroll
                    for (int p = 0; p < 2; p++) {
                        mma_f16(acc[f][2*p][0],   acc[f][2*p][1],   acc[f][2*p][2],   acc[f][2*p][3],
                                ra[f][0], ra[f][1], ra[f][2], ra[f][3], rb[p][0], rb[p][1]);
                        mma_f16(acc[f][2*p+1][0], acc[f][2*p+1][1], acc[f][2*p+1][2], acc[f][2*p+1][3],
                                ra[f][0], ra[f][1], ra[f][2], ra[f][3], rb[p][2], rb[p][3]);
                    }
            }
        }
        __syncthreads();
    }
#undef PREFETCH

    const int crow = bm + wm * 64 + (lane >> 2);
    const int ccol = bn + wn * 32 + 2 * (lane & 3);
    if (MODE == 0) {
        if (z == 0) {
            // Q: fold softmax scale 1/8 (exact pow2) into both halves
            __half* Qh = (__half*)(g_pool + OFF_QH);
            __half* Ql = (__half*)(g_pool + OFF_QL);
#pragma unroll
            for (int f = 0; f < 4; f++)
#pragma unroll
                for (int g = 0; g < 4; g++) {
                    size_t o0 = (size_t)(crow + f * 16)     * D_ + ccol + g * 8;
                    size_t o1 = (size_t)(crow + f * 16 + 8) * D_ + ccol + g * 8;
                    __half h0, h1, l0, l1;
                    splith(acc[f][g][0] * 0.125f, h0, l0);
                    splith(acc[f][g][1] * 0.125f, h1, l1);
                    *(uint32_t*)(Qh + o0) = h2u(h0, h1);
                    *(uint32_t*)(Ql + o0) = h2u(l0, l1);
                    splith(acc[f][g][2] * 0.125f, h0, l0);
                    splith(acc[f][g][3] * 0.125f, h1, l1);
                    *(uint32_t*)(Qh + o1) = h2u(h0, h1);
                    *(uint32_t*)(Ql + o1) = h2u(l0, l1);
                }
        } else {
            __half* Kv = (__half*)(g_pool + (z == 1 ? OFF_KH : OFF_VH));
#pragma unroll
            for (int f = 0; f < 4; f++)
#pragma unroll
                for (int g = 0; g < 4; g++) {
                    size_t o0 = (size_t)(crow + f * 16)     * D_ + ccol + g * 8;
                    size_t o1 = (size_t)(crow + f * 16 + 8) * D_ + ccol + g * 8;
                    *(uint32_t*)(Kv + o0) = h2u(__float2half_rn(acc[f][g][0]),
                                                __float2half_rn(acc[f][g][1]));
                    *(uint32_t*)(Kv + o1) = h2u(__float2half_rn(acc[f][g][2]),
                                                __float2half_rn(acc[f][g][3]));
                }
        }
    } else {
#pragma unroll
        for (int f = 0; f < 4; f++)
#pragma unroll
            for (int g = 0; g < 4; g++) {
                float* p0 = Cout + (size_t)(crow + f * 16)     * D_ + ccol + g * 8;
                float* p1 = Cout + (size_t)(crow + f * 16 + 8) * D_ + ccol + g * 8;
                *(float2*)p0 = make_float2(acc[f][g][0], acc[f][g][1]);
                *(float2*)p1 = make_float2(acc[f][g][2], acc[f][g][3]);
            }
    }
}

// ---------------------------------------------------------------------------
// fp16 flash attention, causal. Q fp16 hi/lo (pre-scaled); K,V fp16 single.
// QK^T: 2 passes (Qh,Ql). PV: 1 pass (P fp16 single).
// 64 q-rows/CTA, 4 warps x 16 rows, K-tile 64, 2-stage cp.async, 3 CTAs/SM.
// ---------------------------------------------------------------------------
#define FQT 64
#define NW  4
#define NTH 128
#define FKT 64
#define FSTR 72
#define QTILE1 (FQT*FSTR*2)       // 9216
#define QAREA  (2*QTILE1)         // 18432
#define FT_B   (64*FSTR*2)        // 9216
#define STG_B  (2*FT_B)           // Kh, Vh = 18432
#define SMEMF  (QAREA + 2*STG_B)  // 55296

__global__ __launch_bounds__(NTH, 3)
void flash_hmma() {
    extern __shared__ char smf[];
    const uint32_t sb = smem_u32(smf);
    const int qt = gridDim.x - 1 - blockIdx.x;   // heavy tiles first
    const int h = blockIdx.y, b = blockIdx.z;
    const int tid = threadIdx.x, lane = tid & 31, w = tid >> 5;
    const int g = lane >> 2, tig = lane & 3;
    const int q8 = lane >> 3, r8 = lane & 7;

    const __half* Qh_ = (const __half*)(g_pool + OFF_QH);
    const __half* Ql_ = (const __half*)(g_pool + OFF_QL);
    const __half* Kh_ = (const __half*)(g_pool + OFF_KH);
    const __half* Vh_ = (const __half*)(g_pool + OFF_VH);
    __half* Ch_ = (__half*)(g_pool + OFF_CH);
    __half* Cl_ = (__half*)(g_pool + OFF_CL);

    const size_t rowQ0 = (size_t)b * S_ + (size_t)qt * FQT;
    const size_t colH  = (size_t)h * DK_;
    const size_t rowK0 = (size_t)b * S_;
    const int nkt = qt + 1;

    const uint32_t stg0 = sb + QAREA;
#define PFETCH(kt_, buf_) do {                                                \
    const size_t kr = rowK0 + (size_t)(kt_) * FKT;                            \
    uint32_t dd = stg0 + (buf_) * STG_B;                                      \
    _Pragma("unroll")                                                         \
    for (int i2 = 0; i2 < 4; i2++) {                                          \
        int idx = tid + i2 * NTH;                                             \
        int r = idx >> 3, c = idx & 7;                                        \
        uint32_t so = dd + (uint32_t)((r * FSTR + c * 8) * 2);                \
        size_t go = (kr + r) * D_ + colH + c * 8;                             \
        CP16(so,        Kh_ + go);                                            \
        CP16(so + FT_B, Vh_ + go);                                            \
    }                                                                         \
    CP_COMMIT();                                                              \
} while (0)

    PFETCH(0, 0);

    // ---- load Q hi/lo into smem ----
#pragma unroll
    for (int t = 0; t < 2; t++) {
        const __half* src = t ? Ql_ : Qh_;
#pragma unroll
        for (int i = 0; i < 4; i++) {
            int idx = tid + i * NTH;
            int r = idx >> 3, c = idx & 7;
            *(uint4*)(smf + t * QTILE1 + (r * FSTR + c * 8) * 2) =
                *(const uint4*)(src + (rowQ0 + r) * D_ + colH + c * 8);
        }
    }
    __syncthreads();

    uint32_t qfh[4][4], qfl[4][4];
    {
        const uint32_t qrow = (uint32_t)(w * 16 + 8 * (q8 & 1) + r8);
#pragma unroll
        for (int kc = 0; kc < 4; kc++) {
            uint32_t off = (qrow * FSTR + 16 * kc + 8 * (q8 >> 1)) * 2;
            ldm_x4(qfh[kc][0], qfh[kc][1], qfh[kc][2], qfh[kc][3], sb + off);
            ldm_x4(qfl[kc][0], qfl[kc][1], qfl[kc][2], qfl[kc][3], sb + QTILE1 + off);
        }
    }

    float oA[8][4];
#pragma unroll
    for (int j = 0; j < 8; j++)
#pragma unroll
        for (int e = 0; e < 4; e++) oA[j][e] = 0.f;
    float m0 = -1e30f, m1 = -1e30f, l0 = 0.f, l1 = 0.f;

    const int qbase = qt * FQT + w * 16;

    for (int kt = 0; kt < nkt; kt++) {
        const int buf = kt & 1;
        if (kt + 1 < nkt) { PFETCH(kt + 1, buf ^ 1); CP_WAIT1(); }
        else              { CP_WAIT0(); }
        __syncthreads();

        {
            const uint32_t stK = stg0 + buf * STG_B;
            float sA[8][4];
#pragma unroll
            for (int j = 0; j < 8; j++)
#pragma unroll
                for (int e = 0; e < 4; e++) sA[j][e] = 0.f;

            // ---- S = Q K^T (2 passes: Qh, Ql vs Kh) ----
            const uint32_t krow = (uint32_t)(8 * (q8 >> 1) + r8);
            const uint32_t kcol = (uint32_t)(8 * (q8 & 1));
#pragma unroll
            for (int kc = 0; kc < 4; kc++) {
                uint32_t kb[8][2];
                const uint32_t coff = (uint32_t)(16 * kc + kcol) * 2;
#pragma unroll
                for (int nf2 = 0; nf2 < 4; nf2++)
                    ldm_x4(kb[2*nf2][0], kb[2*nf2][1], kb[2*nf2+1][0], kb[2*nf2+1][1],
                           stK + ((16 * nf2 + krow) * FSTR) * 2 + coff);
#pragma unroll
                for (int j = 0; j < 8; j++) {
                    mma_f16(sA[j][0], sA[j][1], sA[j][2], sA[j][3],
                            qfh[kc][0], qfh[kc][1], qfh[kc][2], qfh[kc][3], kb[j][0], kb[j][1]);
                    mma_f16(sA[j][0], sA[j][1], sA[j][2], sA[j][3],
                            qfl[kc][0], qfl[kc][1], qfl[kc][2], qfl[kc][3], kb[j][0], kb[j][1]);
                }
            }

            // ---- causal mask (only the diagonal K-tile needs it) ----
            if (kt == nkt - 1) {
                const int grow0 = qbase + g, grow1 = qbase + g + 8;
#pragma unroll
                for (int j = 0; j < 8; j++) {
                    int c0 = kt * FKT + 8 * j + 2 * tig;
                    if (c0     > grow0) sA[j][0] = -1e30f;
                    if (c0 + 1 > grow0) sA[j][1] = -1e30f;
                    if (c0     > grow1) sA[j][2] = -1e30f;
                    if (c0 + 1 > grow1) sA[j][3] = -1e30f;
                }
            }

            // ---- online softmax ----
            float t0 = -1e30f, t1 = -1e30f;
#pragma unroll
            for (int j = 0; j < 8; j++) {
                t0 = fmaxf(t0, fmaxf(sA[j][0], sA[j][1]));
                t1 = fmaxf(t1, fmaxf(sA[j][2], sA[j][3]));
            }
            t0 = fmaxf(t0, __shfl_xor_sync(0xffffffffu, t0, 1));
            t0 = fmaxf(t0, __shfl_xor_sync(0xffffffffu, t0, 2));
            t1 = fmaxf(t1, __shfl_xor_sync(0xffffffffu, t1, 1));
            t1 = fmaxf(t1, __shfl_xor_sync(0xffffffffu, t1, 2));
            const float mn0 = fmaxf(m0, t0), mn1 = fmaxf(m1, t1);
            const float cr0 = __expf(m0 - mn0), cr1 = __expf(m1 - mn1);

            uint32_t ph[4][4];
            float rs0 = 0.f, rs1 = 0.f;
#pragma unroll
            for (int j = 0; j < 8; j++) {
                float p0 = __expf(sA[j][0] - mn0);
                float p1 = __expf(sA[j][1] - mn0);
                float p2 = __expf(sA[j][2] - mn1);
                float p3 = __expf(sA[j][3] - mn1);
                rs0 += p0 + p1; rs1 += p2 + p3;
                const int kc = j >> 1, o = (j & 1) * 2;
                ph[kc][o]   = h2u(__float2half_rn(p0), __float2half_rn(p1));
                ph[kc][o+1] = h2u(__float2half_rn(p2), __float2half_rn(p3));
            }
            rs0 += __shfl_xor_sync(0xffffffffu, rs0, 1);
            rs0 += __shfl_xor_sync(0xffffffffu, rs0, 2);
            rs1 += __shfl_xor_sync(0xffffffffu, rs1, 1);
            rs1 += __shfl_xor_sync(0xffffffffu, rs1, 2);
            l0 = l0 * cr0 + rs0; l1 = l1 * cr1 + rs1;
            m0 = mn0; m1 = mn1;
#pragma unroll
            for (int j = 0; j < 8; j++) {
                oA[j][0] *= cr0; oA[j][1] *= cr0;
                oA[j][2] *= cr1; oA[j][3] *= cr1;
            }

            // ---- O += P V (1 pass: P fp16) ----
            const uint32_t vrow = (uint32_t)(8 * (q8 & 1) + r8);
            const uint32_t vcol = (uint32_t)(8 * (q8 >> 1));
#pragma unroll
            for (int kc2 = 0; kc2 < 4; kc2++) {
                uint32_t vb[8][2];
#pragma unroll
                for (int ng2 = 0; ng2 < 4; ng2++)
                    ldm_x4_t(vb[2*ng2][0], vb[2*ng2][1], vb[2*ng2+1][0], vb[2*ng2+1][1],
                             stK + FT_B + ((16*kc2 + vrow) * FSTR + 16*ng2 + vcol) * 2);
#pragma unroll
                for (int j = 0; j < 8; j++)
                    mma_f16(oA[j][0], oA[j][1], oA[j][2], oA[j][3],
                            ph[kc2][0], ph[kc2][1], ph[kc2][2], ph[kc2][3], vb[j][0], vb[j][1]);
            }
        }
        __syncthreads();
    }
#undef PFETCH

    // ---- epilogue: normalize, split fp16 hi/lo ----
    const float inv0 = 1.f / l0, inv1 = 1.f / l1;
    const size_t r0g = rowQ0 + w * 16 + g;
    const size_t r1g = r0g + 8;
#pragma unroll
    for (int j = 0; j < 8; j++) {
        const size_t col = colH + 8 * j + 2 * tig;
        __half h0, h1, l0b, l1b;
        splith(oA[j][0] * inv0, h0, l0b); splith(oA[j][1] * inv0, h1, l1b);
        *(uint32_t*)(Ch_ + r0g * D_ + col) = h2u(h0, h1);
        *(uint32_t*)(Cl_ + r0g * D_ + col) = h2u(l0b, l1b);
        splith(oA[j][2] * inv1, h0, l0b); splith(oA[j][3] * inv1, h1, l1b);
        *(uint32_t*)(Ch_ + r1g * D_ + col) = h2u(h0, h1);
        *(uint32_t*)(Cl_ + r1g * D_ + col) = h2u(l0b, l1b);
    }
}

// ---------------------------------------------------------------------------
extern "C" void kernel_launch(void* const* d_in, const int* in_sizes, int n_in,
                              void* d_out, int out_size) {
    const float* q   = (const float*)d_in[0];
    const float* k   = (const float*)d_in[1];
    const float* v   = (const float*)d_in[2];
    const float* w_q = (const float*)d_in[4];
    const float* w_k = (const float*)d_in[5];
    const float* w_v = (const float*)d_in[6];
    const float* w_o = (const float*)d_in[7];
    float* out = (float*)d_out;

    cudaFuncSetAttribute(gemm_f16<0>,
                         cudaFuncAttributeMaxDynamicSharedMemorySize, SMEMG);
    cudaFuncSetAttribute(gemm_f16<1>,
                         cudaFuncAttributeMaxDynamicSharedMemorySize, SMEMG);
    cudaFuncSetAttribute(flash_hmma,
                         cudaFuncAttributeMaxDynamicSharedMemorySize, SMEMF);

    split_x<<<dim3((unsigned)(MD_/4/256), 3), 256>>>(
        (const float4*)q, (const float4*)k, (const float4*)v);
    conv_w<<<dim3(MW_/4/256, 4), 256>>>(
        (const float4*)w_q, (const float4*)w_k, (const float4*)w_v, (const float4*)w_o);

    gemm_f16<0><<<dim3(D_/128, M_/128, 3), 256, SMEMG>>>(nullptr);

    flash_hmma<<<dim3(S_/FQT, H_, B_), NTH, SMEMF>>>();

    gemm_f16<1><<<dim3(D_/128, M_/128, 1), 256, SMEMG>>>(out);
}

// round 12
// speedup vs baseline: 5.5631x; 1.0135x over previous
#include <cuda_runtime.h>
#include <cuda_bf16.h>
#include <cuda_fp16.h>
#include <cstdint>

#define B_  4
#define S_  2048
#define D_  1024
#define H_  16
#define DK_ 64
#define M_  (B_*S_)   // 8192 rows
#define MW_ (D_*D_)
#define MD_ ((size_t)M_*D_)

// ---------------- scratch pool (uint16 units; no cudaMalloc allowed) -------
__device__ uint16_t g_pool[12*MD_ + 4*(size_t)MW_];

#define OFF_XH  ((size_t)0)                    // 3*MD fp16: x q,k,v hi
#define OFF_XL  (3*MD_)                        // 3*MD fp16: lo (only q's used)
#define OFF_WH  (6*MD_)                        // 4*MW fp16: wq,wk,wv,wo
#define OFF_QH  (6*MD_ + 4*(size_t)MW_)        // MD fp16 (pre-scaled log2e/8)
#define OFF_QL  (7*MD_ + 4*(size_t)MW_)        // MD fp16
#define OFF_KH  (8*MD_ + 4*(size_t)MW_)        // MD fp16 (single)
#define OFF_VH  (9*MD_ + 4*(size_t)MW_)        // MD fp16 (single)
#define OFF_CH  (10*MD_ + 4*(size_t)MW_)       // MD fp16 ctx hi
#define OFF_CL  (11*MD_ + 4*(size_t)MW_)       // MD fp16 ctx lo

// softmax scale 1/8 folded with log2(e): exp(x) == exp2(x*log2e)
#define QSCALE 0.18033688011112042f

// ---------------- helpers ----------------
__device__ __forceinline__ uint32_t smem_u32(const void* p) {
    uint32_t a;
    asm("{ .reg .u64 t; cvta.to.shared.u64 t, %1; cvt.u32.u64 %0, t; }"
        : "=r"(a) : "l"(p));
    return a;
}
__device__ __forceinline__ float ex2f(float x) {
    float r;
    asm("ex2.approx.f32 %0, %1;" : "=f"(r) : "f"(x));
    return r;
}
#define CP16(dst, src) \
    asm volatile("cp.async.cg.shared.global [%0], [%1], 16;" \
                 :: "r"(dst), "l"(src))
#define CP_COMMIT() asm volatile("cp.async.commit_group;" ::: "memory")
#define CP_WAIT0()  asm volatile("cp.async.wait_group 0;" ::: "memory")
#define CP_WAIT1()  asm volatile("cp.async.wait_group 1;" ::: "memory")

__device__ __forceinline__ void ldm_x4(uint32_t& d0, uint32_t& d1,
                                       uint32_t& d2, uint32_t& d3, uint32_t a) {
    asm volatile("ldmatrix.sync.aligned.m8n8.x4.shared.b16 {%0,%1,%2,%3}, [%4];"
                 : "=r"(d0), "=r"(d1), "=r"(d2), "=r"(d3) : "r"(a));
}
__device__ __forceinline__ void ldm_x4_t(uint32_t& d0, uint32_t& d1,
                                         uint32_t& d2, uint32_t& d3, uint32_t a) {
    asm volatile("ldmatrix.sync.aligned.m8n8.x4.trans.shared.b16 {%0,%1,%2,%3}, [%4];"
                 : "=r"(d0), "=r"(d1), "=r"(d2), "=r"(d3) : "r"(a));
}
__device__ __forceinline__ void mma_f16(float& c0, float& c1, float& c2, float& c3,
                                        uint32_t a0, uint32_t a1, uint32_t a2, uint32_t a3,
                                        uint32_t b0, uint32_t b1) {
    asm volatile(
        "mma.sync.aligned.m16n8k16.row.col.f32.f16.f16.f32 "
        "{%0,%1,%2,%3}, {%4,%5,%6,%7}, {%8,%9}, {%0,%1,%2,%3};"
        : "+f"(c0), "+f"(c1), "+f"(c2), "+f"(c3)
        : "r"(a0), "r"(a1), "r"(a2), "r"(a3), "r"(b0), "r"(b1));
}
__device__ __forceinline__ void splith(float x, __half& h, __half& l) {
    h = __float2half_rn(x);
    l = __float2half_rn(x - __half2float(h));
}
__device__ __forceinline__ uint32_t h2u(__half a, __half b) {
    return (uint32_t)*(uint16_t*)&a | ((uint32_t)*(uint16_t*)&b << 16);
}

// ---------------------------------------------------------------------------
// split inputs q,k,v (fp32) -> fp16 hi/lo
// ---------------------------------------------------------------------------
__global__ __launch_bounds__(256)
void split_x(const float4* __restrict__ q, const float4* __restrict__ k,
             const float4* __restrict__ v) {
    const int which = blockIdx.y;
    const float4* src = which == 0 ? q : (which == 1 ? k : v);
    const size_t i = (size_t)blockIdx.x * 256 + threadIdx.x;
    float4 t = src[i];
    float f[4] = {t.x, t.y, t.z, t.w};
    __half h[4], l[4];
#pragma unroll
    for (int j = 0; j < 4; j++) splith(f[j], h[j], l[j]);
    ((uint2*)(g_pool + OFF_XH + (size_t)which * MD_))[i] = *(uint2*)h;
    ((uint2*)(g_pool + OFF_XL + (size_t)which * MD_))[i] = *(uint2*)l;
}

__global__ __launch_bounds__(256)
void conv_w(const float4* __restrict__ wq, const float4* __restrict__ wk,
            const float4* __restrict__ wv, const float4* __restrict__ wo) {
    const int which = blockIdx.y;
    const float4* src = which == 0 ? wq : (which == 1 ? wk : (which == 2 ? wv : wo));
    const size_t i = (size_t)blockIdx.x * 256 + threadIdx.x;
    float4 t = src[i];
    __half h[4] = {__float2half_rn(t.x), __float2half_rn(t.y),
                   __float2half_rn(t.z), __float2half_rn(t.w)};
    ((uint2*)(g_pool + OFF_WH + (size_t)which * MW_))[i] = *(uint2*)h;
}

// ---------------------------------------------------------------------------
// fp16 HMMA GEMM, 3-stage cp.async, ONE sync per chunk.
// MODE 0, z=0: Q proj, 2-pass, out fp16 hi/lo scaled by QSCALE.
// MODE 0, z=1/2: K/V proj, 1-PASS, out fp16 single.
// MODE 1: out proj from ctx hi/lo, 2-pass, out fp32.
// ---------------------------------------------------------------------------
#define LDS_  40
#define TILEB (128*LDS_*2)        // 10240 B
#define STG3  (3*TILEB)           // 30720 B (Ah,Al,W)
#define SMEMG (3*STG3)            // 92160 B

template<int MODE>
__global__ __launch_bounds__(256, 2)
void gemm_f16(float* __restrict__ Cout) {
    extern __shared__ char smg[];
    const uint32_t sb = smem_u32(smg);
    const int tid = threadIdx.x, lane = tid & 31, wid = tid >> 5;
    const int wm = wid & 1, wn = wid >> 1;
    const int bm = blockIdx.y * 128, bn = blockIdx.x * 128;
    const int z = blockIdx.z;
    const bool two = (MODE == 1) || (z == 0);

    const __half *Ah, *Al, *Wh;
    if (MODE == 0) {
        Ah = (const __half*)(g_pool + OFF_XH + (size_t)z * MD_);
        Al = (const __half*)(g_pool + OFF_XL + (size_t)z * MD_);
        Wh = (const __half*)(g_pool + OFF_WH + (size_t)z * MW_);
    } else {
        Ah = (const __half*)(g_pool + OFF_CH);
        Al = (const __half*)(g_pool + OFF_CL);
        Wh = (const __half*)(g_pool + OFF_WH + (size_t)3 * MW_);
    }

    const int lrow = tid >> 2;
    const int lseg = (tid & 3) * 8;
    const uint32_t sofs = (uint32_t)(lrow * LDS_ + lseg) * 2;

    float acc[4][4][4];
#pragma unroll
    for (int f = 0; f < 4; f++)
#pragma unroll
        for (int g = 0; g < 4; g++)
#pragma unroll
            for (int e = 0; e < 4; e++) acc[f][g][e] = 0.f;

    const int arow = wm * 64 + (lane & 15);
    const int acol = (lane >> 4) * 8;
    const int brow = wn * 32 + (lane & 7) + ((lane >> 4) << 3);
    const int bcol = ((lane >> 3) & 1) * 8;

#define PREFETCH(c, buf) do {                                                 \
    uint32_t dst = sb + (buf) * STG3;                                         \
    const size_t gofs = (size_t)(c) * 32;                                     \
    _Pragma("unroll")                                                         \
    for (int t = 0; t < 2; t++) {                                             \
        uint32_t so = dst + sofs + t * 64 * LDS_ * 2;                         \
        size_t ga = (size_t)(bm + lrow + t * 64) * D_ + gofs + lseg;          \
        size_t gw = (size_t)(bn + lrow + t * 64) * D_ + gofs + lseg;          \
        CP16(so + 0 * TILEB, Ah + ga);                                        \
        if (two) CP16(so + 1 * TILEB, Al + ga);                               \
        CP16(so + 2 * TILEB, Wh + gw);                                        \
    }                                                                         \
    CP_COMMIT();                                                              \
} while (0)

    PREFETCH(0, 0);
    PREFETCH(1, 1);

    for (int c = 0; c < 32; ++c) {
        if (c + 1 < 32) CP_WAIT1(); else CP_WAIT0();
        __syncthreads();
        if (c + 2 < 32) {
            const int nb = (c + 2) % 3;
            PREFETCH(c + 2, nb);
        }

        const uint32_t st = sb + (c % 3) * STG3;
#pragma unroll
        for (int s16 = 0; s16 < 2; ++s16) {
            const uint32_t aoff = (uint32_t)(arow * LDS_ + s16 * 16 + acol) * 2;
            const uint32_t boff = (uint32_t)(brow * LDS_ + s16 * 16 + bcol) * 2;

            uint32_t ra[4][4], rb[2][4];
#pragma unroll
            for (int f = 0; f < 4; f++)
                ldm_x4(ra[f][0], ra[f][1], ra[f][2], ra[f][3],
                       st + 0 * TILEB + aoff + (uint32_t)(f * 16 * LDS_ * 2));
#pragma unroll
            for (int p = 0; p < 2; p++)
                ldm_x4(rb[p][0], rb[p][1], rb[p][2], rb[p][3],
                       st + 2 * TILEB + boff + (uint32_t)(p * 16 * LDS_ * 2));
#pragma unroll
            for (int f = 0; f < 4; f++)
#pragma unroll
                for (int p = 0; p < 2; p++) {
                    mma_f16(acc[f][2*p][0],   acc[f][2*p][1],   acc[f][2*p][2],   acc[f][2*p][3],
                            ra[f][0], ra[f][1], ra[f][2], ra[f][3], rb[p][0], rb[p][1]);
                    mma_f16(acc[f][2*p+1][0], acc[f][2*p+1][1], acc[f][2*p+1][2], acc[f][2*p+1][3],
                            ra[f][0], ra[f][1], ra[f][2], ra[f][3], rb[p][2], rb[p][3]);
                }
            if (two) {
#pragma unroll
                for (int f = 0; f < 4; f++)
                    ldm_x4(ra[f][0], ra[f][1], ra[f][2], ra[f][3],
                           st + 1 * TILEB + aoff + (uint32_t)(f * 16 * LDS_ * 2));
#pragma unroll
                for (int f = 0; f < 4; f++)
#pragma unroll
                    for (int p = 0; p < 2; p++) {
                        mma_f16(acc[f][2*p][0],   acc[f][2*p][1],   acc[f][2*p][2],   acc[f][2*p][3],
                                ra[f][0], ra[f][1], ra[f][2], ra[f][3], rb[p][0], rb[p][1]);
                        mma_f16(acc[f][2*p+1][0], acc[f][2*p+1][1], acc[f][2*p+1][2], acc[f][2*p+1][3],
                                ra[f][0], ra[f][1], ra[f][2], ra[f][3], rb[p][2], rb[p][3]);
                    }
            }
        }
        // no trailing sync: leading sync of iter c+1 orders reads of buf(c%3)
        // before the prefetch into it at iter c+3.
    }
#undef PREFETCH

    const int crow = bm + wm * 64 + (lane >> 2);
    const int ccol = bn + wn * 32 + 2 * (lane & 3);
    if (MODE == 0) {
        if (z == 0) {
            // Q: fold softmax scale * log2e into both halves
            __half* Qh = (__half*)(g_pool + OFF_QH);
            __half* Ql = (__half*)(g_pool + OFF_QL);
#pragma unroll
            for (int f = 0; f < 4; f++)
#pragma unroll
                for (int g = 0; g < 4; g++) {
                    size_t o0 = (size_t)(crow + f * 16)     * D_ + ccol + g * 8;
                    size_t o1 = (size_t)(crow + f * 16 + 8) * D_ + ccol + g * 8;
                    __half h0, h1, l0, l1;
                    splith(acc[f][g][0] * QSCALE, h0, l0);
                    splith(acc[f][g][1] * QSCALE, h1, l1);
                    *(uint32_t*)(Qh + o0) = h2u(h0, h1);
                    *(uint32_t*)(Ql + o0) = h2u(l0, l1);
                    splith(acc[f][g][2] * QSCALE, h0, l0);
                    splith(acc[f][g][3] * QSCALE, h1, l1);
                    *(uint32_t*)(Qh + o1) = h2u(h0, h1);
                    *(uint32_t*)(Ql + o1) = h2u(l0, l1);
                }
        } else {
            __half* Kv = (__half*)(g_pool + (z == 1 ? OFF_KH : OFF_VH));
#pragma unroll
            for (int f = 0; f < 4; f++)
#pragma unroll
                for (int g = 0; g < 4; g++) {
                    size_t o0 = (size_t)(crow + f * 16)     * D_ + ccol + g * 8;
                    size_t o1 = (size_t)(crow + f * 16 + 8) * D_ + ccol + g * 8;
                    *(uint32_t*)(Kv + o0) = h2u(__float2half_rn(acc[f][g][0]),
                                                __float2half_rn(acc[f][g][1]));
                    *(uint32_t*)(Kv + o1) = h2u(__float2half_rn(acc[f][g][2]),
                                                __float2half_rn(acc[f][g][3]));
                }
        }
    } else {
#pragma unroll
        for (int f = 0; f < 4; f++)
#pragma unroll
            for (int g = 0; g < 4; g++) {
                float* p0 = Cout + (size_t)(crow + f * 16)     * D_ + ccol + g * 8;
                float* p1 = Cout + (size_t)(crow + f * 16 + 8) * D_ + ccol + g * 8;
                *(float2*)p0 = make_float2(acc[f][g][0], acc[f][g][1]);
                *(float2*)p1 = make_float2(acc[f][g][2], acc[f][g][3]);
            }
    }
}

// ---------------------------------------------------------------------------
// fp16 flash attention, causal, exp2 domain. Q fp16 hi/lo; K,V fp16 single.
// QK^T: 2 passes. PV: 1 pass. 64 q-rows/CTA, 4 warps, K-tile 64,
// 2-stage cp.async, 4 CTAs/SM (Q fragments re-read from smem per kc).
// ---------------------------------------------------------------------------
#define FQT 64
#define NW  4
#define NTH 128
#define FKT 64
#define FSTR 72
#define QTILE1 (FQT*FSTR*2)       // 9216
#define QAREA  (2*QTILE1)         // 18432
#define FT_B   (64*FSTR*2)        // 9216
#define STG_B  (2*FT_B)           // Kh, Vh = 18432
#define SMEMF  (QAREA + 2*STG_B)  // 55296

__global__ __launch_bounds__(NTH, 4)
void flash_hmma() {
    extern __shared__ char smf[];
    const uint32_t sb = smem_u32(smf);
    const int qt = gridDim.x - 1 - blockIdx.x;   // heavy tiles first
    const int h = blockIdx.y, b = blockIdx.z;
    const int tid = threadIdx.x, lane = tid & 31, w = tid >> 5;
    const int g = lane >> 2, tig = lane & 3;
    const int q8 = lane >> 3, r8 = lane & 7;

    const __half* Qh_ = (const __half*)(g_pool + OFF_QH);
    const __half* Ql_ = (const __half*)(g_pool + OFF_QL);
    const __half* Kh_ = (const __half*)(g_pool + OFF_KH);
    const __half* Vh_ = (const __half*)(g_pool + OFF_VH);
    __half* Ch_ = (__half*)(g_pool + OFF_CH);
    __half* Cl_ = (__half*)(g_pool + OFF_CL);

    const size_t rowQ0 = (size_t)b * S_ + (size_t)qt * FQT;
    const size_t colH  = (size_t)h * DK_;
    const size_t rowK0 = (size_t)b * S_;
    const int nkt = qt + 1;

    const uint32_t stg0 = sb + QAREA;
#define PFETCH(kt_, buf_) do {                                                \
    const size_t kr = rowK0 + (size_t)(kt_) * FKT;                            \
    uint32_t dd = stg0 + (buf_) * STG_B;                                      \
    _Pragma("unroll")                                                         \
    for (int i2 = 0; i2 < 4; i2++) {                                          \
        int idx = tid + i2 * NTH;                                             \
        int r = idx >> 3, c = idx & 7;                                        \
        uint32_t so = dd + (uint32_t)((r * FSTR + c * 8) * 2);                \
        size_t go = (kr + r) * D_ + colH + c * 8;                             \
        CP16(so,        Kh_ + go);                                            \
        CP16(so + FT_B, Vh_ + go);                                            \
    }                                                                         \
    CP_COMMIT();                                                              \
} while (0)

    PFETCH(0, 0);

    // ---- load Q hi/lo into smem ----
#pragma unroll
    for (int t = 0; t < 2; t++) {
        const __half* src = t ? Ql_ : Qh_;
#pragma unroll
        for (int i = 0; i < 4; i++) {
            int idx = tid + i * NTH;
            int r = idx >> 3, c = idx & 7;
            *(uint4*)(smf + t * QTILE1 + (r * FSTR + c * 8) * 2) =
                *(const uint4*)(src + (rowQ0 + r) * D_ + colH + c * 8);
        }
    }
    __syncthreads();

    // per-kc Q fragment smem offsets (fragments re-read each iteration;
    // keeps regs <=128 for 4 CTAs/SM)
    const uint32_t qrow = (uint32_t)(w * 16 + 8 * (q8 & 1) + r8);
    uint32_t qoff[4];
#pragma unroll
    for (int kc = 0; kc < 4; kc++)
        qoff[kc] = (qrow * FSTR + 16 * kc + 8 * (q8 >> 1)) * 2;

    float oA[8][4];
#pragma unroll
    for (int j = 0; j < 8; j++)
#pragma unroll
        for (int e = 0; e < 4; e++) oA[j][e] = 0.f;
    float m0 = -1e30f, m1 = -1e30f, l0 = 0.f, l1 = 0.f;

    const int qbase = qt * FQT + w * 16;

    for (int kt = 0; kt < nkt; kt++) {
        const int buf = kt & 1;
        if (kt + 1 < nkt) { PFETCH(kt + 1, buf ^ 1); CP_WAIT1(); }
        else              { CP_WAIT0(); }
        __syncthreads();

        {
            const uint32_t stK = stg0 + buf * STG_B;
            float sA[8][4];
#pragma unroll
            for (int j = 0; j < 8; j++)
#pragma unroll
                for (int e = 0; e < 4; e++) sA[j][e] = 0.f;

            // ---- S = Q K^T (2 passes: Qh, Ql vs Kh), exp2 units ----
            const uint32_t krow = (uint32_t)(8 * (q8 >> 1) + r8);
            const uint32_t kcol = (uint32_t)(8 * (q8 & 1));
#pragma unroll
            for (int kc = 0; kc < 4; kc++) {
                uint32_t kb[8][2];
                const uint32_t coff = (uint32_t)(16 * kc + kcol) * 2;
#pragma unroll
                for (int nf2 = 0; nf2 < 4; nf2++)
                    ldm_x4(kb[2*nf2][0], kb[2*nf2][1], kb[2*nf2+1][0], kb[2*nf2+1][1],
                           stK + ((16 * nf2 + krow) * FSTR) * 2 + coff);
                uint32_t qf[4];
                ldm_x4(qf[0], qf[1], qf[2], qf[3], sb + qoff[kc]);
#pragma unroll
                for (int j = 0; j < 8; j++)
                    mma_f16(sA[j][0], sA[j][1], sA[j][2], sA[j][3],
                            qf[0], qf[1], qf[2], qf[3], kb[j][0], kb[j][1]);
                ldm_x4(qf[0], qf[1], qf[2], qf[3], sb + QTILE1 + qoff[kc]);
#pragma unroll
                for (int j = 0; j < 8; j++)
                    mma_f16(sA[j][0], sA[j][1], sA[j][2], sA[j][3],
                            qf[0], qf[1], qf[2], qf[3], kb[j][0], kb[j][1]);
            }

            // ---- causal mask (only the diagonal K-tile needs it) ----
            if (kt == nkt - 1) {
                const int grow0 = qbase + g, grow1 = qbase + g + 8;
#pragma unroll
                for (int j = 0; j < 8; j++) {
                    int c0 = kt * FKT + 8 * j + 2 * tig;
                    if (c0     > grow0) sA[j][0] = -1e30f;
                    if (c0 + 1 > grow0) sA[j][1] = -1e30f;
                    if (c0     > grow1) sA[j][2] = -1e30f;
                    if (c0 + 1 > grow1) sA[j][3] = -1e30f;
                }
            }

            // ---- online softmax in exp2 domain ----
            float t0 = -1e30f, t1 = -1e30f;
#pragma unroll
            for (int j = 0; j < 8; j++) {
                t0 = fmaxf(t0, fmaxf(sA[j][0], sA[j][1]));
                t1 = fmaxf(t1, fmaxf(sA[j][2], sA[j][3]));
            }
            t0 = fmaxf(t0, __shfl_xor_sync(0xffffffffu, t0, 1));
            t0 = fmaxf(t0, __shfl_xor_sync(0xffffffffu, t0, 2));
            t1 = fmaxf(t1, __shfl_xor_sync(0xffffffffu, t1, 1));
            t1 = fmaxf(t1, __shfl_xor_sync(0xffffffffu, t1, 2));
            const float mn0 = fmaxf(m0, t0), mn1 = fmaxf(m1, t1);
            const float cr0 = ex2f(m0 - mn0), cr1 = ex2f(m1 - mn1);

            uint32_t ph[4][4];
            float rs0 = 0.f, rs1 = 0.f;
#pragma unroll
            for (int j = 0; j < 8; j++) {
                float p0 = ex2f(sA[j][0] - mn0);
                float p1 = ex2f(sA[j][1] - mn0);
                float p2 = ex2f(sA[j][2] - mn1);
                float p3 = ex2f(sA[j][3] - mn1);
                rs0 += p0 + p1; rs1 += p2 + p3;
                const int kc = j >> 1, o = (j & 1) * 2;
                ph[kc][o]   = h2u(__float2half_rn(p0), __float2half_rn(p1));
                ph[kc][o+1] = h2u(__float2half_rn(p2), __float2half_rn(p3));
            }
            rs0 += __shfl_xor_sync(0xffffffffu, rs0, 1);
            rs0 += __shfl_xor_sync(0xffffffffu, rs0, 2);
            rs1 += __shfl_xor_sync(0xffffffffu, rs1, 1);
            rs1 += __shfl_xor_sync(0xffffffffu, rs1, 2);
            l0 = l0 * cr0 + rs0; l1 = l1 * cr1 + rs1;
            m0 = mn0; m1 = mn1;
#pragma unroll
            for (int j = 0; j < 8; j++) {
                oA[j][0] *= cr0; oA[j][1] *= cr0;
                oA[j][2] *= cr1; oA[j][3] *= cr1;
            }

            // ---- O += P V (1 pass: P fp16) ----
            const uint32_t vrow = (uint32_t)(8 * (q8 & 1) + r8);
            const uint32_t vcol = (uint32_t)(8 * (q8 >> 1));
#pragma unroll
            for (int kc2 = 0; kc2 < 4; kc2++) {
                uint32_t vb[8][2];
#pragma unroll
                for (int ng2 = 0; ng2 < 4; ng2++)
                    ldm_x4_t(vb[2*ng2][0], vb[2*ng2][1], vb[2*ng2+1][0], vb[2*ng2+1][1],
                             stK + FT_B + ((16*kc2 + vrow) * FSTR + 16*ng2 + vcol) * 2);
#pragma unroll
                for (int j = 0; j < 8; j++)
                    mma_f16(oA[j][0], oA[j][1], oA[j][2], oA[j][3],
                            ph[kc2][0], ph[kc2][1], ph[kc2][2], ph[kc2][3], vb[j][0], vb[j][1]);
            }
        }
        __syncthreads();
    }
#undef PFETCH

    // ---- epilogue: normalize, split fp16 hi/lo ----
    const float inv0 = 1.f / l0, inv1 = 1.f / l1;
    const size_t r0g = rowQ0 + w * 16 + g;
    const size_t r1g = r0g + 8;
#pragma unroll
    for (int j = 0; j < 8; j++) {
        const size_t col = colH + 8 * j + 2 * tig;
        __half h0, h1, l0b, l1b;
        splith(oA[j][0] * inv0, h0, l0b); splith(oA[j][1] * inv0, h1, l1b);
        *(uint32_t*)(Ch_ + r0g * D_ + col) = h2u(h0, h1);
        *(uint32_t*)(Cl_ + r0g * D_ + col) = h2u(l0b, l1b);
        splith(oA[j][2] * inv1, h0, l0b); splith(oA[j][3] * inv1, h1, l1b);
        *(uint32_t*)(Ch_ + r1g * D_ + col) = h2u(h0, h1);
        *(uint32_t*)(Cl_ + r1g * D_ + col) = h2u(l0b, l1b);
    }
}

// ---------------------------------------------------------------------------
extern "C" void kernel_launch(void* const* d_in, const int* in_sizes, int n_in,
                              void* d_out, int out_size) {
    const float* q   = (const float*)d_in[0];
    const float* k   = (const float*)d_in[1];
    const float* v   = (const float*)d_in[2];
    const float* w_q = (const float*)d_in[4];
    const float* w_k = (const float*)d_in[5];
    const float* w_v = (const float*)d_in[6];
    const float* w_o = (const float*)d_in[7];
    float* out = (float*)d_out;

    cudaFuncSetAttribute(gemm_f16<0>,
                         cudaFuncAttributeMaxDynamicSharedMemorySize, SMEMG);
    cudaFuncSetAttribute(gemm_f16<1>,
                         cudaFuncAttributeMaxDynamicSharedMemorySize, SMEMG);
    cudaFuncSetAttribute(flash_hmma,
                         cudaFuncAttributeMaxDynamicSharedMemorySize, SMEMF);

    split_x<<<dim3((unsigned)(MD_/4/256), 3), 256>>>(
        (const float4*)q, (const float4*)k, (const float4*)v);
    conv_w<<<dim3(MW_/4/256, 4), 256>>>(
        (const float4*)w_q, (const float4*)w_k, (const float4*)w_v, (const float4*)w_o);

    gemm_f16<0><<<dim3(D_/128, M_/128, 3), 256, SMEMG>>>(nullptr);

    flash_hmma<<<dim3(S_/FQT, H_, B_), NTH, SMEMF>>>();

    gemm_f16<1><<<dim3(D_/128, M_/128, 1), 256, SMEMG>>>(out);
}

// round 13
// speedup vs baseline: 6.7313x; 1.2100x over previous
#include <cuda_runtime.h>
#include <cuda_bf16.h>
#include <cuda_fp16.h>
#include <cstdint>

#define B_  4
#define S_  2048
#define D_  1024
#define H_  16
#define DK_ 64
#define M_  (B_*S_)   // 8192 rows
#define MW_ (D_*D_)
#define MD_ ((size_t)M_*D_)

// ---------------- scratch pool (uint16 units; no cudaMalloc allowed) -------
__device__ uint16_t g_pool[12*MD_ + 4*(size_t)MW_];

#define OFF_XH  ((size_t)0)                    // 3*MD fp16: x q,k,v (single)
#define OFF_WH  (6*MD_)                        // 4*MW fp16: wq,wk,wv,wo
#define OFF_QH  (6*MD_ + 4*(size_t)MW_)        // MD fp16 (pre-scaled log2e/8)
#define OFF_QL  (7*MD_ + 4*(size_t)MW_)        // MD fp16
#define OFF_KH  (8*MD_ + 4*(size_t)MW_)        // MD fp16 (single)
#define OFF_VH  (9*MD_ + 4*(size_t)MW_)        // MD fp16 (single)
#define OFF_CH  (10*MD_ + 4*(size_t)MW_)       // MD fp16 ctx (single)

// softmax scale 1/8 folded with log2(e): exp(x) == exp2(x*log2e)
#define QSCALE 0.18033688011112042f

// ---------------- helpers ----------------
__device__ __forceinline__ uint32_t smem_u32(const void* p) {
    uint32_t a;
    asm("{ .reg .u64 t; cvta.to.shared.u64 t, %1; cvt.u32.u64 %0, t; }"
        : "=r"(a) : "l"(p));
    return a;
}
__device__ __forceinline__ float ex2f(float x) {
    float r;
    asm("ex2.approx.f32 %0, %1;" : "=f"(r) : "f"(x));
    return r;
}
#define CP16(dst, src) \
    asm volatile("cp.async.cg.shared.global [%0], [%1], 16;" \
                 :: "r"(dst), "l"(src))
#define CP_COMMIT() asm volatile("cp.async.commit_group;" ::: "memory")
#define CP_WAIT0()  asm volatile("cp.async.wait_group 0;" ::: "memory")
#define CP_WAIT1()  asm volatile("cp.async.wait_group 1;" ::: "memory")

__device__ __forceinline__ void ldm_x4(uint32_t& d0, uint32_t& d1,
                                       uint32_t& d2, uint32_t& d3, uint32_t a) {
    asm volatile("ldmatrix.sync.aligned.m8n8.x4.shared.b16 {%0,%1,%2,%3}, [%4];"
                 : "=r"(d0), "=r"(d1), "=r"(d2), "=r"(d3) : "r"(a));
}
__device__ __forceinline__ void ldm_x4_t(uint32_t& d0, uint32_t& d1,
                                         uint32_t& d2, uint32_t& d3, uint32_t a) {
    asm volatile("ldmatrix.sync.aligned.m8n8.x4.trans.shared.b16 {%0,%1,%2,%3}, [%4];"
                 : "=r"(d0), "=r"(d1), "=r"(d2), "=r"(d3) : "r"(a));
}
__device__ __forceinline__ void mma_f16(float& c0, float& c1, float& c2, float& c3,
                                        uint32_t a0, uint32_t a1, uint32_t a2, uint32_t a3,
                                        uint32_t b0, uint32_t b1) {
    asm volatile(
        "mma.sync.aligned.m16n8k16.row.col.f32.f16.f16.f32 "
        "{%0,%1,%2,%3}, {%4,%5,%6,%7}, {%8,%9}, {%0,%1,%2,%3};"
        : "+f"(c0), "+f"(c1), "+f"(c2), "+f"(c3)
        : "r"(a0), "r"(a1), "r"(a2), "r"(a3), "r"(b0), "r"(b1));
}
__device__ __forceinline__ void splith(float x, __half& h, __half& l) {
    h = __float2half_rn(x);
    l = __float2half_rn(x - __half2float(h));
}
__device__ __forceinline__ uint32_t h2u(__half a, __half b) {
    return (uint32_t)*(uint16_t*)&a | ((uint32_t)*(uint16_t*)&b << 16);
}

// ---------------------------------------------------------------------------
// convert q,k,v (fp32) -> fp16 single
// ---------------------------------------------------------------------------
__global__ __launch_bounds__(256)
void conv_x(const float4* __restrict__ q, const float4* __restrict__ k,
            const float4* __restrict__ v) {
    const int which = blockIdx.y;
    const float4* src = which == 0 ? q : (which == 1 ? k : v);
    const size_t i = (size_t)blockIdx.x * 256 + threadIdx.x;
    float4 t = src[i];
    __half h[4] = {__float2half_rn(t.x), __float2half_rn(t.y),
                   __float2half_rn(t.z), __float2half_rn(t.w)};
    ((uint2*)(g_pool + OFF_XH + (size_t)which * MD_))[i] = *(uint2*)h;
}

__global__ __launch_bounds__(256)
void conv_w(const float4* __restrict__ wq, const float4* __restrict__ wk,
            const float4* __restrict__ wv, const float4* __restrict__ wo) {
    const int which = blockIdx.y;
    const float4* src = which == 0 ? wq : (which == 1 ? wk : (which == 2 ? wv : wo));
    const size_t i = (size_t)blockIdx.x * 256 + threadIdx.x;
    float4 t = src[i];
    __half h[4] = {__float2half_rn(t.x), __float2half_rn(t.y),
                   __float2half_rn(t.z), __float2half_rn(t.w)};
    ((uint2*)(g_pool + OFF_WH + (size_t)which * MW_))[i] = *(uint2*)h;
}

// ---------------------------------------------------------------------------
// fp16 1-pass HMMA GEMM, 3-stage cp.async, one sync per chunk.
// MODE 0: batched QKV (z): z=0 -> Q out fp16 hi/lo scaled QSCALE; z=1/2 K/V.
// MODE 1: out proj from ctx fp16 single -> fp32.
// ---------------------------------------------------------------------------
#define LDS_  40
#define TILEB (128*LDS_*2)        // 10240 B
#define STG2  (2*TILEB)           // 20480 B (A, W)
#define SMEMG (3*STG2)            // 61440 B

template<int MODE>
__global__ __launch_bounds__(256, 2)
void gemm_f16(float* __restrict__ Cout) {
    extern __shared__ char smg[];
    const uint32_t sb = smem_u32(smg);
    const int tid = threadIdx.x, lane = tid & 31, wid = tid >> 5;
    const int wm = wid & 1, wn = wid >> 1;
    const int bm = blockIdx.y * 128, bn = blockIdx.x * 128;
    const int z = blockIdx.z;

    const __half *Ah, *Wh;
    if (MODE == 0) {
        Ah = (const __half*)(g_pool + OFF_XH + (size_t)z * MD_);
        Wh = (const __half*)(g_pool + OFF_WH + (size_t)z * MW_);
    } else {
        Ah = (const __half*)(g_pool + OFF_CH);
        Wh = (const __half*)(g_pool + OFF_WH + (size_t)3 * MW_);
    }

    const int lrow = tid >> 2;
    const int lseg = (tid & 3) * 8;
    const uint32_t sofs = (uint32_t)(lrow * LDS_ + lseg) * 2;

    float acc[4][4][4];
#pragma unroll
    for (int f = 0; f < 4; f++)
#pragma unroll
        for (int g = 0; g < 4; g++)
#pragma unroll
            for (int e = 0; e < 4; e++) acc[f][g][e] = 0.f;

    const int arow = wm * 64 + (lane & 15);
    const int acol = (lane >> 4) * 8;
    const int brow = wn * 32 + (lane & 7) + ((lane >> 4) << 3);
    const int bcol = ((lane >> 3) & 1) * 8;

#define PREFETCH(c, buf) do {                                                 \
    uint32_t dst = sb + (buf) * STG2;                                         \
    const size_t gofs = (size_t)(c) * 32;                                     \
    _Pragma("unroll")                                                         \
    for (int t = 0; t < 2; t++) {                                             \
        uint32_t so = dst + sofs + t * 64 * LDS_ * 2;                         \
        size_t ga = (size_t)(bm + lrow + t * 64) * D_ + gofs + lseg;          \
        size_t gw = (size_t)(bn + lrow + t * 64) * D_ + gofs + lseg;          \
        CP16(so,         Ah + ga);                                            \
        CP16(so + TILEB, Wh + gw);                                            \
    }                                                                         \
    CP_COMMIT();                                                              \
} while (0)

    PREFETCH(0, 0);
    PREFETCH(1, 1);

    for (int c = 0; c < 32; ++c) {
        if (c + 1 < 32) CP_WAIT1(); else CP_WAIT0();
        __syncthreads();
        if (c + 2 < 32) {
            const int nb = (c + 2) % 3;
            PREFETCH(c + 2, nb);
        }

        const uint32_t st = sb + (c % 3) * STG2;
#pragma unroll
        for (int s16 = 0; s16 < 2; ++s16) {
            const uint32_t aoff = (uint32_t)(arow * LDS_ + s16 * 16 + acol) * 2;
            const uint32_t boff = (uint32_t)(brow * LDS_ + s16 * 16 + bcol) * 2;

            uint32_t ra[4][4], rb[2][4];
#pragma unroll
            for (int f = 0; f < 4; f++)
                ldm_x4(ra[f][0], ra[f][1], ra[f][2], ra[f][3],
                       st + aoff + (uint32_t)(f * 16 * LDS_ * 2));
#pragma unroll
            for (int p = 0; p < 2; p++)
                ldm_x4(rb[p][0], rb[p][1], rb[p][2], rb[p][3],
                       st + TILEB + boff + (uint32_t)(p * 16 * LDS_ * 2));
#pragma unroll
            for (int f = 0; f < 4; f++)
#pragma unroll
                for (int p = 0; p < 2; p++) {
                    mma_f16(acc[f][2*p][0],   acc[f][2*p][1],   acc[f][2*p][2],   acc[f][2*p][3],
                            ra[f][0], ra[f][1], ra[f][2], ra[f][3], rb[p][0], rb[p][1]);
                    mma_f16(acc[f][2*p+1][0], acc[f][2*p+1][1], acc[f][2*p+1][2], acc[f][2*p+1][3],
                            ra[f][0], ra[f][1], ra[f][2], ra[f][3], rb[p][2], rb[p][3]);
                }
        }
        // no trailing sync: leading sync of iter c+1 orders reads of buf(c%3)
        // before the prefetch into it at iter c+3.
    }
#undef PREFETCH

    const int crow = bm + wm * 64 + (lane >> 2);
    const int ccol = bn + wn * 32 + 2 * (lane & 3);
    if (MODE == 0) {
        if (z == 0) {
            // Q: fold softmax scale * log2e into both halves
            __half* Qh = (__half*)(g_pool + OFF_QH);
            __half* Ql = (__half*)(g_pool + OFF_QL);
#pragma unroll
            for (int f = 0; f < 4; f++)
#pragma unroll
                for (int g = 0; g < 4; g++) {
                    size_t o0 = (size_t)(crow + f * 16)     * D_ + ccol + g * 8;
                    size_t o1 = (size_t)(crow + f * 16 + 8) * D_ + ccol + g * 8;
                    __half h0, h1, l0, l1;
                    splith(acc[f][g][0] * QSCALE, h0, l0);
                    splith(acc[f][g][1] * QSCALE, h1, l1);
                    *(uint32_t*)(Qh + o0) = h2u(h0, h1);
                    *(uint32_t*)(Ql + o0) = h2u(l0, l1);
                    splith(acc[f][g][2] * QSCALE, h0, l0);
                    splith(acc[f][g][3] * QSCALE, h1, l1);
                    *(uint32_t*)(Qh + o1) = h2u(h0, h1);
                    *(uint32_t*)(Ql + o1) = h2u(l0, l1);
                }
        } else {
            __half* Kv = (__half*)(g_pool + (z == 1 ? OFF_KH : OFF_VH));
#pragma unroll
            for (int f = 0; f < 4; f++)
#pragma unroll
                for (int g = 0; g < 4; g++) {
                    size_t o0 = (size_t)(crow + f * 16)     * D_ + ccol + g * 8;
                    size_t o1 = (size_t)(crow + f * 16 + 8) * D_ + ccol + g * 8;
                    *(uint32_t*)(Kv + o0) = h2u(__float2half_rn(acc[f][g][0]),
                                                __float2half_rn(acc[f][g][1]));
                    *(uint32_t*)(Kv + o1) = h2u(__float2half_rn(acc[f][g][2]),
                                                __float2half_rn(acc[f][g][3]));
                }
        }
    } else {
#pragma unroll
        for (int f = 0; f < 4; f++)
#pragma unroll
            for (int g = 0; g < 4; g++) {
                float* p0 = Cout + (size_t)(crow + f * 16)     * D_ + ccol + g * 8;
                float* p1 = Cout + (size_t)(crow + f * 16 + 8) * D_ + ccol + g * 8;
                *(float2*)p0 = make_float2(acc[f][g][0], acc[f][g][1]);
                *(float2*)p1 = make_float2(acc[f][g][2], acc[f][g][3]);
            }
    }
}

// ---------------------------------------------------------------------------
// fp16 flash attention, causal, exp2 domain. Q fp16 hi/lo; K,V fp16 single.
// QK^T: 2 passes. PV: 1 pass. 64 q-rows/CTA, 4 warps, K-tile 64,
// 2-stage cp.async, 4 CTAs/SM. Ctx written as fp16 single.
// ---------------------------------------------------------------------------
#define FQT 64
#define NW  4
#define NTH 128
#define FKT 64
#define FSTR 72
#define QTILE1 (FQT*FSTR*2)       // 9216
#define QAREA  (2*QTILE1)         // 18432
#define FT_B   (64*FSTR*2)        // 9216
#define STG_B  (2*FT_B)           // Kh, Vh = 18432
#define SMEMF  (QAREA + 2*STG_B)  // 55296

__global__ __launch_bounds__(NTH, 4)
void flash_hmma() {
    extern __shared__ char smf[];
    const uint32_t sb = smem_u32(smf);
    const int qt = gridDim.x - 1 - blockIdx.x;   // heavy tiles first
    const int h = blockIdx.y, b = blockIdx.z;
    const int tid = threadIdx.x, lane = tid & 31, w = tid >> 5;
    const int g = lane >> 2, tig = lane & 3;
    const int q8 = lane >> 3, r8 = lane & 7;

    const __half* Qh_ = (const __half*)(g_pool + OFF_QH);
    const __half* Ql_ = (const __half*)(g_pool + OFF_QL);
    const __half* Kh_ = (const __half*)(g_pool + OFF_KH);
    const __half* Vh_ = (const __half*)(g_pool + OFF_VH);
    __half* Ch_ = (__half*)(g_pool + OFF_CH);

    const size_t rowQ0 = (size_t)b * S_ + (size_t)qt * FQT;
    const size_t colH  = (size_t)h * DK_;
    const size_t rowK0 = (size_t)b * S_;
    const int nkt = qt + 1;

    const uint32_t stg0 = sb + QAREA;
#define PFETCH(kt_, buf_) do {                                                \
    const size_t kr = rowK0 + (size_t)(kt_) * FKT;                            \
    uint32_t dd = stg0 + (buf_) * STG_B;                                      \
    _Pragma("unroll")                                                         \
    for (int i2 = 0; i2 < 4; i2++) {                                          \
        int idx = tid + i2 * NTH;                                             \
        int r = idx >> 3, c = idx & 7;                                        \
        uint32_t so = dd + (uint32_t)((r * FSTR + c * 8) * 2);                \
        size_t go = (kr + r) * D_ + colH + c * 8;                             \
        CP16(so,        Kh_ + go);                                            \
        CP16(so + FT_B, Vh_ + go);                                            \
    }                                                                         \
    CP_COMMIT();                                                              \
} while (0)

    PFETCH(0, 0);

    // ---- load Q hi/lo into smem ----
#pragma unroll
    for (int t = 0; t < 2; t++) {
        const __half* src = t ? Ql_ : Qh_;
#pragma unroll
        for (int i = 0; i < 4; i++) {
            int idx = tid + i * NTH;
            int r = idx >> 3, c = idx & 7;
            *(uint4*)(smf + t * QTILE1 + (r * FSTR + c * 8) * 2) =
                *(const uint4*)(src + (rowQ0 + r) * D_ + colH + c * 8);
        }
    }
    __syncthreads();

    const uint32_t qrow = (uint32_t)(w * 16 + 8 * (q8 & 1) + r8);
    uint32_t qoff[4];
#pragma unroll
    for (int kc = 0; kc < 4; kc++)
        qoff[kc] = (qrow * FSTR + 16 * kc + 8 * (q8 >> 1)) * 2;

    float oA[8][4];
#pragma unroll
    for (int j = 0; j < 8; j++)
#pragma unroll
        for (int e = 0; e < 4; e++) oA[j][e] = 0.f;
    float m0 = -1e30f, m1 = -1e30f, l0 = 0.f, l1 = 0.f;

    const int qbase = qt * FQT + w * 16;

    for (int kt = 0; kt < nkt; kt++) {
        const int buf = kt & 1;
        if (kt + 1 < nkt) { PFETCH(kt + 1, buf ^ 1); CP_WAIT1(); }
        else              { CP_WAIT0(); }
        __syncthreads();

        {
            const uint32_t stK = stg0 + buf * STG_B;
            float sA[8][4];
#pragma unroll
            for (int j = 0; j < 8; j++)
#pragma unroll
                for (int e = 0; e < 4; e++) sA[j][e] = 0.f;

            // ---- S = Q K^T (2 passes: Qh, Ql vs Kh), exp2 units ----
            const uint32_t krow = (uint32_t)(8 * (q8 >> 1) + r8);
            const uint32_t kcol = (uint32_t)(8 * (q8 & 1));
#pragma unroll
            for (int kc = 0; kc < 4; kc++) {
                uint32_t kb[8][2];
                const uint32_t coff = (uint32_t)(16 * kc + kcol) * 2;
#pragma unroll
                for (int nf2 = 0; nf2 < 4; nf2++)
                    ldm_x4(kb[2*nf2][0], kb[2*nf2][1], kb[2*nf2+1][0], kb[2*nf2+1][1],
                           stK + ((16 * nf2 + krow) * FSTR) * 2 + coff);
                uint32_t qf[4];
                ldm_x4(qf[0], qf[1], qf[2], qf[3], sb + qoff[kc]);
#pragma unroll
                for (int j = 0; j < 8; j++)
                    mma_f16(sA[j][0], sA[j][1], sA[j][2], sA[j][3],
                            qf[0], qf[1], qf[2], qf[3], kb[j][0], kb[j][1]);
                ldm_x4(qf[0], qf[1], qf[2], qf[3], sb + QTILE1 + qoff[kc]);
#pragma unroll
                for (int j = 0; j < 8; j++)
                    mma_f16(sA[j][0], sA[j][1], sA[j][2], sA[j][3],
                            qf[0], qf[1], qf[2], qf[3], kb[j][0], kb[j][1]);
            }

            // ---- causal mask (only the diagonal K-tile needs it) ----
            if (kt == nkt - 1) {
                const int grow0 = qbase + g, grow1 = qbase + g + 8;
#pragma unroll
                for (int j = 0; j < 8; j++) {
                    int c0 = kt * FKT + 8 * j + 2 * tig;
                    if (c0     > grow0) sA[j][0] = -1e30f;
                    if (c0 + 1 > grow0) sA[j][1] = -1e30f;
                    if (c0     > grow1) sA[j][2] = -1e30f;
                    if (c0 + 1 > grow1) sA[j][3] = -1e30f;
                }
            }

            // ---- online softmax in exp2 domain ----
            float t0 = -1e30f, t1 = -1e30f;
#pragma unroll
            for (int j = 0; j < 8; j++) {
                t0 = fmaxf(t0, fmaxf(sA[j][0], sA[j][1]));
                t1 = fmaxf(t1, fmaxf(sA[j][2], sA[j][3]));
            }
            t0 = fmaxf(t0, __shfl_xor_sync(0xffffffffu, t0, 1));
            t0 = fmaxf(t0, __shfl_xor_sync(0xffffffffu, t0, 2));
            t1 = fmaxf(t1, __shfl_xor_sync(0xffffffffu, t1, 1));
            t1 = fmaxf(t1, __shfl_xor_sync(0xffffffffu, t1, 2));
            const float mn0 = fmaxf(m0, t0), mn1 = fmaxf(m1, t1);
            const float cr0 = ex2f(m0 - mn0), cr1 = ex2f(m1 - mn1);

            uint32_t ph[4][4];
            float rs0 = 0.f, rs1 = 0.f;
#pragma unroll
            for (int j = 0; j < 8; j++) {
                float p0 = ex2f(sA[j][0] - mn0);
                float p1 = ex2f(sA[j][1] - mn0);
                float p2 = ex2f(sA[j][2] - mn1);
                float p3 = ex2f(sA[j][3] - mn1);
                rs0 += p0 + p1; rs1 += p2 + p3;
                const int kc = j >> 1, o = (j & 1) * 2;
                ph[kc][o]   = h2u(__float2half_rn(p0), __float2half_rn(p1));
                ph[kc][o+1] = h2u(__float2half_rn(p2), __float2half_rn(p3));
            }
            rs0 += __shfl_xor_sync(0xffffffffu, rs0, 1);
            rs0 += __shfl_xor_sync(0xffffffffu, rs0, 2);
            rs1 += __shfl_xor_sync(0xffffffffu, rs1, 1);
            rs1 += __shfl_xor_sync(0xffffffffu, rs1, 2);
            l0 = l0 * cr0 + rs0; l1 = l1 * cr1 + rs1;
            m0 = mn0; m1 = mn1;
#pragma unroll
            for (int j = 0; j < 8; j++) {
                oA[j][0] *= cr0; oA[j][1] *= cr0;
                oA[j][2] *= cr1; oA[j][3] *= cr1;
            }

            // ---- O += P V (1 pass: P fp16) ----
            const uint32_t vrow = (uint32_t)(8 * (q8 & 1) + r8);
            const uint32_t vcol = (uint32_t)(8 * (q8 >> 1));
#pragma unroll
            for (int kc2 = 0; kc2 < 4; kc2++) {
                uint32_t vb[8][2];
#pragma unroll
                for (int ng2 = 0; ng2 < 4; ng2++)
                    ldm_x4_t(vb[2*ng2][0], vb[2*ng2][1], vb[2*ng2+1][0], vb[2*ng2+1][1],
                             stK + FT_B + ((16*kc2 + vrow) * FSTR + 16*ng2 + vcol) * 2);
#pragma unroll
                for (int j = 0; j < 8; j++)
                    mma_f16(oA[j][0], oA[j][1], oA[j][2], oA[j][3],
                            ph[kc2][0], ph[kc2][1], ph[kc2][2], ph[kc2][3], vb[j][0], vb[j][1]);
            }
        }
        __syncthreads();
    }
#undef PFETCH

    // ---- epilogue: normalize, fp16 single ctx ----
    const float inv0 = 1.f / l0, inv1 = 1.f / l1;
    const size_t r0g = rowQ0 + w * 16 + g;
    const size_t r1g = r0g + 8;
#pragma unroll
    for (int j = 0; j < 8; j++) {
        const size_t col = colH + 8 * j + 2 * tig;
        *(uint32_t*)(Ch_ + r0g * D_ + col) =
            h2u(__float2half_rn(oA[j][0] * inv0), __float2half_rn(oA[j][1] * inv0));
        *(uint32_t*)(Ch_ + r1g * D_ + col) =
            h2u(__float2half_rn(oA[j][2] * inv1), __float2half_rn(oA[j][3] * inv1));
    }
}

// ---------------------------------------------------------------------------
extern "C" void kernel_launch(void* const* d_in, const int* in_sizes, int n_in,
                              void* d_out, int out_size) {
    const float* q   = (const float*)d_in[0];
    const float* k   = (const float*)d_in[1];
    const float* v   = (const float*)d_in[2];
    const float* w_q = (const float*)d_in[4];
    const float* w_k = (const float*)d_in[5];
    const float* w_v = (const float*)d_in[6];
    const float* w_o = (const float*)d_in[7];
    float* out = (float*)d_out;

    cudaFuncSetAttribute(gemm_f16<0>,
                         cudaFuncAttributeMaxDynamicSharedMemorySize, SMEMG);
    cudaFuncSetAttribute(gemm_f16<1>,
                         cudaFuncAttributeMaxDynamicSharedMemorySize, SMEMG);
    cudaFuncSetAttribute(flash_hmma,
                         cudaFuncAttributeMaxDynamicSharedMemorySize, SMEMF);

    conv_x<<<dim3((unsigned)(MD_/4/256), 3), 256>>>(
        (const float4*)q, (const float4*)k, (const float4*)v);
    conv_w<<<dim3(MW_/4/256, 4), 256>>>(
        (const float4*)w_q, (const float4*)w_k, (const float4*)w_v, (const float4*)w_o);

    gemm_f16<0><<<dim3(D_/128, M_/128, 3), 256, SMEMG>>>(nullptr);

    flash_hmma<<<dim3(S_/FQT, H_, B_), NTH, SMEMF>>>();

    gemm_f16<1><<<dim3(D_/128, M_/128, 1), 256, SMEMG>>>(out);
}

// round 17
// speedup vs baseline: 7.1706x; 1.0653x over previous
#include <cuda_runtime.h>
#include <cuda_bf16.h>
#include <cuda_fp16.h>
#include <cstdint>

#define B_  4
#define S_  2048
#define D_  1024
#define H_  16
#define DK_ 64
#define M_  (B_*S_)   // 8192 rows
#define MW_ (D_*D_)
#define MD_ ((size_t)M_*D_)

// ---------------- scratch pool (uint16 units; no cudaMalloc allowed) -------
__device__ uint16_t g_pool[12*MD_ + 4*(size_t)MW_];

#define OFF_XH  ((size_t)0)                    // 3*MD fp16: x q,k,v (single)
#define OFF_WH  (6*MD_)                        // 4*MW fp16: wq,wk,wv,wo
#define OFF_QH  (6*MD_ + 4*(size_t)MW_)        // MD fp16 (pre-scaled log2e/8)
#define OFF_KH  (8*MD_ + 4*(size_t)MW_)        // MD fp16 (single)
#define OFF_VH  (9*MD_ + 4*(size_t)MW_)        // MD fp16 (single)
#define OFF_CH  (10*MD_ + 4*(size_t)MW_)       // MD fp16 ctx (single)

// softmax scale 1/8 folded with log2(e): exp(x) == exp2(x*log2e)
#define QSCALE 0.18033688011112042f

// ---------------- helpers ----------------
__device__ __forceinline__ uint32_t smem_u32(const void* p) {
    uint32_t a;
    asm("{ .reg .u64 t; cvta.to.shared.u64 t, %1; cvt.u32.u64 %0, t; }"
        : "=r"(a) : "l"(p));
    return a;
}
__device__ __forceinline__ float ex2f(float x) {
    float r;
    asm("ex2.approx.f32 %0, %1;" : "=f"(r) : "f"(x));
    return r;
}
#define CP16(dst, src) \
    asm volatile("cp.async.cg.shared.global [%0], [%1], 16;" \
                 :: "r"(dst), "l"(src))
#define CP_COMMIT() asm volatile("cp.async.commit_group;" ::: "memory")
#define CP_WAIT0()  asm volatile("cp.async.wait_group 0;" ::: "memory")
#define CP_WAIT1()  asm volatile("cp.async.wait_group 1;" ::: "memory")

__device__ __forceinline__ void ldm_x4(uint32_t& d0, uint32_t& d1,
                                       uint32_t& d2, uint32_t& d3, uint32_t a) {
    asm volatile("ldmatrix.sync.aligned.m8n8.x4.shared.b16 {%0,%1,%2,%3}, [%4];"
                 : "=r"(d0), "=r"(d1), "=r"(d2), "=r"(d3) : "r"(a));
}
__device__ __forceinline__ void ldm_x4_t(uint32_t& d0, uint32_t& d1,
                                         uint32_t& d2, uint32_t& d3, uint32_t a) {
    asm volatile("ldmatrix.sync.aligned.m8n8.x4.trans.shared.b16 {%0,%1,%2,%3}, [%4];"
                 : "=r"(d0), "=r"(d1), "=r"(d2), "=r"(d3) : "r"(a));
}
__device__ __forceinline__ void mma_f16(float& c0, float& c1, float& c2, float& c3,
                                        uint32_t a0, uint32_t a1, uint32_t a2, uint32_t a3,
                                        uint32_t b0, uint32_t b1) {
    asm volatile(
        "mma.sync.aligned.m16n8k16.row.col.f32.f16.f16.f32 "
        "{%0,%1,%2,%3}, {%4,%5,%6,%7}, {%8,%9}, {%0,%1,%2,%3};"
        : "+f"(c0), "+f"(c1), "+f"(c2), "+f"(c3)
        : "r"(a0), "r"(a1), "r"(a2), "r"(a3), "r"(b0), "r"(b1));
}
__device__ __forceinline__ uint32_t h2u(__half a, __half b) {
    return (uint32_t)*(uint16_t*)&a | ((uint32_t)*(uint16_t*)&b << 16);
}

// ---------------------------------------------------------------------------
// convert q,k,v (fp32) -> fp16 single
// ---------------------------------------------------------------------------
__global__ __launch_bounds__(256)
void conv_x(const float4* __restrict__ q, const float4* __restrict__ k,
            const float4* __restrict__ v) {
    const int which = blockIdx.y;
    const float4* src = which == 0 ? q : (which == 1 ? k : v);
    const size_t i = (size_t)blockIdx.x * 256 + threadIdx.x;
    float4 t = src[i];
    __half h[4] = {__float2half_rn(t.x), __float2half_rn(t.y),
                   __float2half_rn(t.z), __float2half_rn(t.w)};
    ((uint2*)(g_pool + OFF_XH + (size_t)which * MD_))[i] = *(uint2*)h;
}

__global__ __launch_bounds__(256)
void conv_w(const float4* __restrict__ wq, const float4* __restrict__ wk,
            const float4* __restrict__ wv, const float4* __restrict__ wo) {
    const int which = blockIdx.y;
    const float4* src = which == 0 ? wq : (which == 1 ? wk : (which == 2 ? wv : wo));
    const size_t i = (size_t)blockIdx.x * 256 + threadIdx.x;
    float4 t = src[i];
    __half h[4] = {__float2half_rn(t.x), __float2half_rn(t.y),
                   __float2half_rn(t.z), __float2half_rn(t.w)};
    ((uint2*)(g_pool + OFF_WH + (size_t)which * MW_))[i] = *(uint2*)h;
}

// ---------------------------------------------------------------------------
// fp16 1-pass HMMA GEMM, 3-stage cp.async, one sync per chunk.
// MODE 0: batched QKV (z): z=0 -> Q fp16 scaled QSCALE; z=1/2 -> K/V fp16.
// MODE 1: out proj from ctx fp16 single -> fp32.
// ---------------------------------------------------------------------------
#define LDS_  40
#define TILEB (128*LDS_*2)        // 10240 B
#define STG2  (2*TILEB)           // 20480 B (A, W)
#define SMEMG (3*STG2)            // 61440 B

template<int MODE>
__global__ __launch_bounds__(256, 2)
void gemm_f16(float* __restrict__ Cout) {
    extern __shared__ char smg[];
    const uint32_t sb = smem_u32(smg);
    const int tid = threadIdx.x, lane = tid & 31, wid = tid >> 5;
    const int wm = wid & 1, wn = wid >> 1;
    const int bm = blockIdx.y * 128, bn = blockIdx.x * 128;
    const int z = blockIdx.z;

    const __half *Ah, *Wh;
    if (MODE == 0) {
        Ah = (const __half*)(g_pool + OFF_XH + (size_t)z * MD_);
        Wh = (const __half*)(g_pool + OFF_WH + (size_t)z * MW_);
    } else {
        Ah = (const __half*)(g_pool + OFF_CH);
        Wh = (const __half*)(g_pool + OFF_WH + (size_t)3 * MW_);
    }

    const int lrow = tid >> 2;
    const int lseg = (tid & 3) * 8;
    const uint32_t sofs = (uint32_t)(lrow * LDS_ + lseg) * 2;

    float acc[4][4][4];
#pragma unroll
    for (int f = 0; f < 4; f++)
#pragma unroll
        for (int g = 0; g < 4; g++)
#pragma unroll
            for (int e = 0; e < 4; e++) acc[f][g][e] = 0.f;

    const int arow = wm * 64 + (lane & 15);
    const int acol = (lane >> 4) * 8;
    const int brow = wn * 32 + (lane & 7) + ((lane >> 4) << 3);
    const int bcol = ((lane >> 3) & 1) * 8;

#define PREFETCH(c, buf) do {                                                 \
    uint32_t dst = sb + (buf) * STG2;                                         \
    const size_t gofs = (size_t)(c) * 32;                                     \
    _Pragma("unroll")                                                         \
    for (int t = 0; t < 2; t++) {                                             \
        uint32_t so = dst + sofs + t * 64 * LDS_ * 2;                         \
        size_t ga = (size_t)(bm + lrow + t * 64) * D_ + gofs + lseg;          \
        size_t gw = (size_t)(bn + lrow + t * 64) * D_ + gofs + lseg;          \
        CP16(so,         Ah + ga);                                            \
        CP16(so + TILEB, Wh + gw);                                            \
    }                                                                         \
    CP_COMMIT();                                                              \
} while (0)

    PREFETCH(0, 0);
    PREFETCH(1, 1);

    for (int c = 0; c < 32; ++c) {
        if (c + 1 < 32) CP_WAIT1(); else CP_WAIT0();
        __syncthreads();
        if (c + 2 < 32) {
            const int nb = (c + 2) % 3;
            PREFETCH(c + 2, nb);
        }

        const uint32_t st = sb + (c % 3) * STG2;
#pragma unroll
        for (int s16 = 0; s16 < 2; ++s16) {
            const uint32_t aoff = (uint32_t)(arow * LDS_ + s16 * 16 + acol) * 2;
            const uint32_t boff = (uint32_t)(brow * LDS_ + s16 * 16 + bcol) * 2;

            uint32_t ra[4][4], rb[2][4];
#pragma unroll
            for (int f = 0; f < 4; f++)
                ldm_x4(ra[f][0], ra[f][1], ra[f][2], ra[f][3],
                       st + aoff + (uint32_t)(f * 16 * LDS_ * 2));
#pragma unroll
            for (int p = 0; p < 2; p++)
                ldm_x4(rb[p][0], rb[p][1], rb[p][2], rb[p][3],
                       st + TILEB + boff + (uint32_t)(p * 16 * LDS_ * 2));
#pragma unroll
            for (int f = 0; f < 4; f++)
#pragma unroll
                for (int p = 0; p < 2; p++) {
                    mma_f16(acc[f][2*p][0],   acc[f][2*p][1],   acc[f][2*p][2],   acc[f][2*p][3],
                            ra[f][0], ra[f][1], ra[f][2], ra[f][3], rb[p][0], rb[p][1]);
                    mma_f16(acc[f][2*p+1][0], acc[f][2*p+1][1], acc[f][2*p+1][2], acc[f][2*p+1][3],
                            ra[f][0], ra[f][1], ra[f][2], ra[f][3], rb[p][2], rb[p][3]);
                }
        }
        // no trailing sync: leading sync of iter c+1 orders reads of buf(c%3)
        // before the prefetch into it at iter c+3.
    }
#undef PREFETCH

    const int crow = bm + wm * 64 + (lane >> 2);
    const int ccol = bn + wn * 32 + 2 * (lane & 3);
    if (MODE == 0) {
        const float sc = (z == 0) ? QSCALE : 1.0f;
        __half* Kv = (__half*)(g_pool + (z == 0 ? OFF_QH : (z == 1 ? OFF_KH : OFF_VH)));
#pragma unroll
        for (int f = 0; f < 4; f++)
#pragma unroll
            for (int g = 0; g < 4; g++) {
                size_t o0 = (size_t)(crow + f * 16)     * D_ + ccol + g * 8;
                size_t o1 = (size_t)(crow + f * 16 + 8) * D_ + ccol + g * 8;
                *(uint32_t*)(Kv + o0) = h2u(__float2half_rn(acc[f][g][0] * sc),
                                            __float2half_rn(acc[f][g][1] * sc));
                *(uint32_t*)(Kv + o1) = h2u(__float2half_rn(acc[f][g][2] * sc),
                                            __float2half_rn(acc[f][g][3] * sc));
            }
    } else {
#pragma unroll
        for (int f = 0; f < 4; f++)
#pragma unroll
            for (int g = 0; g < 4; g++) {
                float* p0 = Cout + (size_t)(crow + f * 16)     * D_ + ccol + g * 8;
                float* p1 = Cout + (size_t)(crow + f * 16 + 8) * D_ + ccol + g * 8;
                *(float2*)p0 = make_float2(acc[f][g][0], acc[f][g][1]);
                *(float2*)p1 = make_float2(acc[f][g][2], acc[f][g][3]);
            }
    }
}

// ---------------------------------------------------------------------------
// fp16 flash attention, causal, exp2 domain. Q,K,V fp16 single.
// QK^T: 1 pass. PV: 1 pass. 64 q-rows/CTA, 4 warps, K-tile 64,
// 2-stage cp.async, 4 CTAs/SM. Ctx fp16 single.
// ---------------------------------------------------------------------------
#define FQT 64
#define NW  4
#define NTH 128
#define FKT 64
#define FSTR 72
#define QTILE1 (FQT*FSTR*2)       // 9216
#define FT_B   (64*FSTR*2)        // 9216
#define STG_B  (2*FT_B)           // Kh, Vh = 18432
#define SMEMF  (QTILE1 + 2*STG_B) // 46080

__global__ __launch_bounds__(NTH, 4)
void flash_hmma() {
    extern __shared__ char smf[];
    const uint32_t sb = smem_u32(smf);
    const int qt = gridDim.x - 1 - blockIdx.x;   // heavy tiles first
    const int h = blockIdx.y, b = blockIdx.z;
    const int tid = threadIdx.x, lane = tid & 31, w = tid >> 5;
    const int g = lane >> 2, tig = lane & 3;
    const int q8 = lane >> 3, r8 = lane & 7;

    const __half* Qh_ = (const __half*)(g_pool + OFF_QH);
    const __half* Kh_ = (const __half*)(g_pool + OFF_KH);
    const __half* Vh_ = (const __half*)(g_pool + OFF_VH);
    __half* Ch_ = (__half*)(g_pool + OFF_CH);

    const size_t rowQ0 = (size_t)b * S_ + (size_t)qt * FQT;
    const size_t colH  = (size_t)h * DK_;
    const size_t rowK0 = (size_t)b * S_;
    const int nkt = qt + 1;

    const uint32_t stg0 = sb + QTILE1;
#define PFETCH(kt_, buf_) do {                                                \
    const size_t kr = rowK0 + (size_t)(kt_) * FKT;                            \
    uint32_t dd = stg0 + (buf_) * STG_B;                                      \
    _Pragma("unroll")                                                         \
    for (int i2 = 0; i2 < 4; i2++) {                                          \
        int idx = tid + i2 * NTH;                                             \
        int r = idx >> 3, c = idx & 7;                                        \
        uint32_t so = dd + (uint32_t)((r * FSTR + c * 8) * 2);                \
        size_t go = (kr + r) * D_ + colH + c * 8;                             \
        CP16(so,        Kh_ + go);                                            \
        CP16(so + FT_B, Vh_ + go);                                            \
    }                                                                         \
    CP_COMMIT();                                                              \
} while (0)

    PFETCH(0, 0);

    // ---- load Q into smem ----
#pragma unroll
    for (int i = 0; i < 4; i++) {
        int idx = tid + i * NTH;
        int r = idx >> 3, c = idx & 7;
        *(uint4*)(smf + (r * FSTR + c * 8) * 2) =
            *(const uint4*)(Qh_ + (rowQ0 + r) * D_ + colH + c * 8);
    }
    __syncthreads();

    const uint32_t qrow = (uint32_t)(w * 16 + 8 * (q8 & 1) + r8);
    uint32_t qoff[4];
#pragma unroll
    for (int kc = 0; kc < 4; kc++)
        qoff[kc] = (qrow * FSTR + 16 * kc + 8 * (q8 >> 1)) * 2;

    float oA[8][4];
#pragma unroll
    for (int j = 0; j < 8; j++)
#pragma unroll
        for (int e = 0; e < 4; e++) oA[j][e] = 0.f;
    float m0 = -1e30f, m1 = -1e30f, l0 = 0.f, l1 = 0.f;

    const int qbase = qt * FQT + w * 16;

    for (int kt = 0; kt < nkt; kt++) {
        const int buf = kt & 1;
        if (kt + 1 < nkt) { PFETCH(kt + 1, buf ^ 1); CP_WAIT1(); }
        else              { CP_WAIT0(); }
        __syncthreads();

        {
            const uint32_t stK = stg0 + buf * STG_B;
            float sA[8][4];
#pragma unroll
            for (int j = 0; j < 8; j++)
#pragma unroll
                for (int e = 0; e < 4; e++) sA[j][e] = 0.f;

            // ---- S = Q K^T (1 pass), exp2 units ----
            const uint32_t krow = (uint32_t)(8 * (q8 >> 1) + r8);
            const uint32_t kcol = (uint32_t)(8 * (q8 & 1));
#pragma unroll
            for (int kc = 0; kc < 4; kc++) {
                uint32_t kb[8][2];
                const uint32_t coff = (uint32_t)(16 * kc + kcol) * 2;
#pragma unroll
                for (int nf2 = 0; nf2 < 4; nf2++)
                    ldm_x4(kb[2*nf2][0], kb[2*nf2][1], kb[2*nf2+1][0], kb[2*nf2+1][1],
                           stK + ((16 * nf2 + krow) * FSTR) * 2 + coff);
                uint32_t qf[4];
                ldm_x4(qf[0], qf[1], qf[2], qf[3], sb + qoff[kc]);
#pragma unroll
                for (int j = 0; j < 8; j++)
                    mma_f16(sA[j][0], sA[j][1], sA[j][2], sA[j][3],
                            qf[0], qf[1], qf[2], qf[3], kb[j][0], kb[j][1]);
            }

            // ---- causal mask (only the diagonal K-tile needs it) ----
            if (kt == nkt - 1) {
                const int grow0 = qbase + g, grow1 = qbase + g + 8;
#pragma unroll
                for (int j = 0; j < 8; j++) {
                    int c0 = kt * FKT + 8 * j + 2 * tig;
                    if (c0     > grow0) sA[j][0] = -1e30f;
                    if (c0 + 1 > grow0) sA[j][1] = -1e30f;
                    if (c0     > grow1) sA[j][2] = -1e30f;
                    if (c0 + 1 > grow1) sA[j][3] = -1e30f;
                }
            }

            // ---- online softmax in exp2 domain ----
            float t0 = -1e30f, t1 = -1e30f;
#pragma unroll
            for (int j = 0; j < 8; j++) {
                t0 = fmaxf(t0, fmaxf(sA[j][0], sA[j][1]));
                t1 = fmaxf(t1, fmaxf(sA[j][2], sA[j][3]));
            }
            t0 = fmaxf(t0, __shfl_xor_sync(0xffffffffu, t0, 1));
            t0 = fmaxf(t0, __shfl_xor_sync(0xffffffffu, t0, 2));
            t1 = fmaxf(t1, __shfl_xor_sync(0xffffffffu, t1, 1));
            t1 = fmaxf(t1, __shfl_xor_sync(0xffffffffu, t1, 2));
            const float mn0 = fmaxf(m0, t0), mn1 = fmaxf(m1, t1);
            const float cr0 = ex2f(m0 - mn0), cr1 = ex2f(m1 - mn1);

            uint32_t ph[4][4];
            float rs0 = 0.f, rs1 = 0.f;
#pragma unroll
            for (int j = 0; j < 8; j++) {
                float p0 = ex2f(sA[j][0] - mn0);
                float p1 = ex2f(sA[j][1] - mn0);
                float p2 = ex2f(sA[j][2] - mn1);
                float p3 = ex2f(sA[j][3] - mn1);
                rs0 += p0 + p1; rs1 += p2 + p3;
                const int kc = j >> 1, o = (j & 1) * 2;
                ph[kc][o]   = h2u(__float2half_rn(p0), __float2half_rn(p1));
                ph[kc][o+1] = h2u(__float2half_rn(p2), __float2half_rn(p3));
            }
            rs0 += __shfl_xor_sync(0xffffffffu, rs0, 1);
            rs0 += __shfl_xor_sync(0xffffffffu, rs0, 2);
            rs1 += __shfl_xor_sync(0xffffffffu, rs1, 1);
            rs1 += __shfl_xor_sync(0xffffffffu, rs1, 2);
            l0 = l0 * cr0 + rs0; l1 = l1 * cr1 + rs1;
            m0 = mn0; m1 = mn1;
#pragma unroll
            for (int j = 0; j < 8; j++) {
                oA[j][0] *= cr0; oA[j][1] *= cr0;
                oA[j][2] *= cr1; oA[j][3] *= cr1;
            }

            // ---- O += P V (1 pass) ----
            const uint32_t vrow = (uint32_t)(8 * (q8 & 1) + r8);
            const uint32_t vcol = (uint32_t)(8 * (q8 >> 1));
#pragma unroll
            for (int kc2 = 0; kc2 < 4; kc2++) {
                uint32_t vb[8][2];
#pragma unroll
                for (int ng2 = 0; ng2 < 4; ng2++)
                    ldm_x4_t(vb[2*ng2][0], vb[2*ng2][1], vb[2*ng2+1][0], vb[2*ng2+1][1],
                             stK + FT_B + ((16*kc2 + vrow) * FSTR + 16*ng2 + vcol) * 2);
#pragma unroll
                for (int j = 0; j < 8; j++)
                    mma_f16(oA[j][0], oA[j][1], oA[j][2], oA[j][3],
                            ph[kc2][0], ph[kc2][1], ph[kc2][2], ph[kc2][3], vb[j][0], vb[j][1]);
            }
        }
        __syncthreads();
    }
#undef PFETCH

    // ---- epilogue: normalize, fp16 single ctx ----
    const float inv0 = 1.f / l0, inv1 = 1.f / l1;
    const size_t r0g = rowQ0 + w * 16 + g;
    const size_t r1g = r0g + 8;
#pragma unroll
    for (int j = 0; j < 8; j++) {
        const size_t col = colH + 8 * j + 2 * tig;
        *(uint32_t*)(Ch_ + r0g * D_ + col) =
            h2u(__float2half_rn(oA[j][0] * inv0), __float2half_rn(oA[j][1] * inv0));
        *(uint32_t*)(Ch_ + r1g * D_ + col) =
            h2u(__float2half_rn(oA[j][2] * inv1), __float2half_rn(oA[j][3] * inv1));
    }
}

// ---------------------------------------------------------------------------
extern "C" void kernel_launch(void* const* d_in, const int* in_sizes, int n_in,
                              void* d_out, int out_size) {
    const float* q   = (const float*)d_in[0];
    const float* k   = (const float*)d_in[1];
    const float* v   = (const float*)d_in[2];
    const float* w_q = (const float*)d_in[4];
    const float* w_k = (const float*)d_in[5];
    const float* w_v = (const float*)d_in[6];
    const float* w_o = (const float*)d_in[7];
    float* out = (float*)d_out;

    cudaFuncSetAttribute(gemm_f16<0>,
                         cudaFuncAttributeMaxDynamicSharedMemorySize, SMEMG);
    cudaFuncSetAttribute(gemm_f16<1>,
                         cudaFuncAttributeMaxDynamicSharedMemorySize, SMEMG);
    cudaFuncSetAttribute(flash_hmma,
                         cudaFuncAttributeMaxDynamicSharedMemorySize, SMEMF);

    conv_x<<<dim3((unsigned)(MD_/4/256), 3), 256>>>(
        (const float4*)q, (const float4*)k, (const float4*)v);
    conv_w<<<dim3(MW_/4/256, 4), 256>>>(
        (const float4*)w_q, (const float4*)w_k, (const float4*)w_v, (const float4*)w_o);

    gemm_f16<0><<<dim3(D_/128, M_/128, 3), 256, SMEMG>>>(nullptr);

    flash_hmma<<<dim3(S_/FQT, H_, B_), NTH, SMEMF>>>();

    gemm_f16<1><<<dim3(D_/128, M_/128, 1), 256, SMEMG>>>(out);
}